// round 6
// baseline (speedup 1.0000x reference)
#include <cuda_runtime.h>
#include <cuda_bf16.h>
#include <cstdint>

#define N_NODES 50000
#define E_EDGES 800000
#define EGT     200000

// ---------------- scratch (static device globals; no allocation) ----------------
__device__ float g_h0[N_NODES * 24];        // [x(16) | agg_trigger(4) | agg_action(4)]
__device__ int   g_degd[N_NODES];
__device__ int   g_degs[N_NODES];
__device__ int   g_curd[N_NODES];
__device__ int   g_curs[N_NODES];
__device__ int   g_off[N_NODES + 1];        // CSR by dst
__device__ int   g_offs[N_NODES + 1];       // CSR by src
__device__ int   g_csrc[E_EDGES];           // per in-edge: src | (action<<20)
__device__ int   g_strig[E_EDGES];          // per out-edge: trigger code
__device__ float g_agg24[N_NODES * 24];
__device__ float g_h1[N_NODES * 256];
__device__ float g_agg256[N_NODES * 256];
__device__ float g_uv[N_NODES * 256];       // [u(128) | v(128)] per node
__device__ __nv_bfloat16 g_wc2h[552 * 128]; // Wc2^T hi, [n][k]
__device__ __nv_bfloat16 g_wc2l[552 * 128];
__device__ __nv_bfloat16 g_w2h[128 * 512];  // [W2l;W2r]^T hi, [n][k]
__device__ __nv_bfloat16 g_w2l[128 * 512];
__device__ __nv_bfloat16 g_wuvh[256 * 128]; // [Wc1_top|Wc1_bot]^T hi, [n][k]
__device__ __nv_bfloat16 g_wuvl[256 * 128];
__device__ __nv_bfloat16 g_w1h[256 * 64];   // [W1l;W1r]^T hi, [n][k], k padded 48->64
__device__ __nv_bfloat16 g_w1l[256 * 64];

// ======================= warp-MMA + async helpers (baseline PTX, sm_80+) =======================
__device__ __forceinline__ uint32_t smem_u32(const void* p) {
    uint32_t a;
    asm("{ .reg .u64 t; cvta.to.shared.u64 t, %1; cvt.u32.u64 %0, t; }" : "=r"(a) : "l"(p));
    return a;
}
__device__ __forceinline__ void ldm_x4(uint32_t* r, uint32_t addr) {
    asm volatile("ldmatrix.sync.aligned.m8n8.x4.shared.b16 {%0,%1,%2,%3}, [%4];"
        : "=r"(r[0]), "=r"(r[1]), "=r"(r[2]), "=r"(r[3]) : "r"(addr));
}
__device__ __forceinline__ void mma_bf16(float* c, const uint32_t* a, const uint32_t* b) {
    asm volatile(
        "mma.sync.aligned.m16n8k16.row.col.f32.bf16.bf16.f32 "
        "{%0,%1,%2,%3}, {%4,%5,%6,%7}, {%8,%9}, {%0,%1,%2,%3};"
        : "+f"(c[0]), "+f"(c[1]), "+f"(c[2]), "+f"(c[3])
        : "r"(a[0]), "r"(a[1]), "r"(a[2]), "r"(a[3]), "r"(b[0]), "r"(b[1]));
}
__device__ __forceinline__ void cp16(uint32_t dst, const void* src) {
    asm volatile("cp.async.cg.shared.global [%0], [%1], 16;" :: "r"(dst), "l"(src));
}
#define CP_COMMIT() asm volatile("cp.async.commit_group;" ::: "memory")
#define CP_WAIT0()  asm volatile("cp.async.wait_group 0;" ::: "memory")
#define CP_WAIT1()  asm volatile("cp.async.wait_group 1;" ::: "memory")
__device__ __forceinline__ float sigf(float x) { return 1.f / (1.f + __expf(-x)); }

__device__ __forceinline__ void split8(const float* z, uint32_t* hw, uint32_t* lw) {
#pragma unroll
    for (int p = 0; p < 4; p++) {
        __nv_bfloat16 h0 = __float2bfloat16(z[2 * p]);
        __nv_bfloat16 h1 = __float2bfloat16(z[2 * p + 1]);
        __nv_bfloat16 l0 = __float2bfloat16(z[2 * p] - __bfloat162float(h0));
        __nv_bfloat16 l1 = __float2bfloat16(z[2 * p + 1] - __bfloat162float(h1));
        __nv_bfloat162 hh = {h0, h1}, ll = {l0, l1};
        hw[p] = *reinterpret_cast<uint32_t*>(&hh);
        lw[p] = *reinterpret_cast<uint32_t*>(&ll);
    }
}
__device__ __forceinline__ void split2(float x, float y, uint32_t& hw, uint32_t& lw) {
    __nv_bfloat16 h0 = __float2bfloat16(x);
    __nv_bfloat16 h1 = __float2bfloat16(y);
    __nv_bfloat16 l0 = __float2bfloat16(x - __bfloat162float(h0));
    __nv_bfloat16 l1 = __float2bfloat16(y - __bfloat162float(h1));
    __nv_bfloat162 hh = {h0, h1}, ll = {l0, l1};
    hw = *reinterpret_cast<uint32_t*>(&hh);
    lw = *reinterpret_cast<uint32_t*>(&ll);
}

// ---------------- init: zero counters ----------------
__global__ void k_init() {
    int i = blockIdx.x * blockDim.x + threadIdx.x;
    if (i < N_NODES) { g_degd[i] = 0; g_degs[i] = 0; g_curd[i] = 0; g_curs[i] = 0; }
}

// ---------------- weight prep kernels ----------------
__global__ void k_wc2_prep(const float* __restrict__ Wc2) {
    int i = blockIdx.x * blockDim.x + threadIdx.x;
    if (i >= 552 * 128) return;
    int n = i >> 7, k = i & 127;
    float w = Wc2[(size_t)k * 552 + n];
    __nv_bfloat16 h = __float2bfloat16(w);
    g_wc2h[i] = h;
    g_wc2l[i] = __float2bfloat16(w - __bfloat162float(h));
}
__global__ void k_w2_prep(const float* __restrict__ W2l, const float* __restrict__ W2r) {
    int i = blockIdx.x * blockDim.x + threadIdx.x;
    if (i >= 128 * 512) return;
    int n = i >> 9, k = i & 511;
    float w = (k < 256) ? W2l[(size_t)k * 128 + n] : W2r[(size_t)(k - 256) * 128 + n];
    __nv_bfloat16 h = __float2bfloat16(w);
    g_w2h[i] = h;
    g_w2l[i] = __float2bfloat16(w - __bfloat162float(h));
}
__global__ void k_wuv_prep(const float* __restrict__ Wc1) {
    int i = blockIdx.x * blockDim.x + threadIdx.x;
    if (i >= 256 * 128) return;
    int n = i >> 7, k = i & 127;
    float w = (n < 128) ? Wc1[(size_t)k * 128 + n] : Wc1[(size_t)(128 + k) * 128 + (n - 128)];
    __nv_bfloat16 h = __float2bfloat16(w);
    g_wuvh[i] = h;
    g_wuvl[i] = __float2bfloat16(w - __bfloat162float(h));
}
__global__ void k_w1_prep(const float* __restrict__ W1l, const float* __restrict__ W1r) {
    int i = blockIdx.x * blockDim.x + threadIdx.x;
    if (i >= 256 * 64) return;
    int n = i >> 6, k = i & 63;
    float w = 0.f;
    if (k < 24) w = W1l[(size_t)k * 256 + n];
    else if (k < 48) w = W1r[(size_t)(k - 24) * 256 + n];
    __nv_bfloat16 h = __float2bfloat16(w);
    g_w1h[i] = h;
    g_w1l[i] = __float2bfloat16(w - __bfloat162float(h));
}

// ---------------- degree count (both directions) ----------------
__global__ void k_count(const int* __restrict__ ei) {
    int e = blockIdx.x * blockDim.x + threadIdx.x;
    if (e >= E_EDGES) return;
    atomicAdd(&g_degs[ei[e]], 1);
    atomicAdd(&g_degd[ei[E_EDGES + e]], 1);
}

// ---------------- scan (selector: 0 = dst-CSR, 1 = src-CSR) ----------------
__global__ void k_scan(int which) {
    const int* deg = which ? g_degs : g_degd;
    int* off = which ? g_offs : g_off;
    const int CH = (N_NODES + 1023) / 1024;
    int tid = threadIdx.x, lane = tid & 31, wid = tid >> 5;
    int beg = tid * CH, end = min(beg + CH, N_NODES);
    int sum = 0;
    for (int i = beg; i < end; i++) sum += deg[i];
    int v = sum;
#pragma unroll
    for (int o = 1; o < 32; o <<= 1) {
        int t = __shfl_up_sync(0xFFFFFFFFu, v, o);
        if (lane >= o) v += t;
    }
    __shared__ int wsum[32];
    if (lane == 31) wsum[wid] = v;
    __syncthreads();
    if (wid == 0) {
        int w = wsum[lane];
#pragma unroll
        for (int o = 1; o < 32; o <<= 1) {
            int t = __shfl_up_sync(0xFFFFFFFFu, w, o);
            if (lane >= o) w += t;
        }
        wsum[lane] = w;
    }
    __syncthreads();
    int base = v - sum + (wid ? wsum[wid - 1] : 0);
    for (int i = beg; i < end; i++) { off[i] = base; base += deg[i]; }
    if (tid == 1023) off[N_NODES] = base;
}

// ---------------- scatter both CSRs (action packed into csrc high bits) ----------------
__global__ void k_scatter2(const int* __restrict__ ei, const int* __restrict__ ef) {
    int e = blockIdx.x * blockDim.x + threadIdx.x;
    if (e >= E_EDGES) return;
    int s = ei[e], d = ei[E_EDGES + e];
    int t = ef[2 * e], a = ef[2 * e + 1];
    int posd = g_off[d] + atomicAdd(&g_curd[d], 1);
    g_csrc[posd] = s | (a << 20);
    int poss = g_offs[s] + atomicAdd(&g_curs[s], 1);
    g_strig[poss] = t;
}

// ---------------- h0 build: x copy + trigger/action gather-reduce (no atomics) ----------------
__global__ void k_h0build(const float* __restrict__ x,
                          const float* __restrict__ embT, const float* __restrict__ embA) {
    int n = blockIdx.x * blockDim.x + threadIdx.x;
    if (n >= N_NODES) return;
    float* h0 = g_h0 + (size_t)n * 24;
    const float4* xp = (const float4*)(x + (size_t)n * 16);
#pragma unroll
    for (int j = 0; j < 4; j++) ((float4*)h0)[j] = xp[j];
    float4 trig = make_float4(0, 0, 0, 0);
    int b0 = g_offs[n], e0 = g_offs[n + 1];
    for (int e = b0; e < e0; e++) {
        int t = g_strig[e];
        float4 v = *(const float4*)(embT + (size_t)t * 4);
        trig.x += v.x; trig.y += v.y; trig.z += v.z; trig.w += v.w;
    }
    float4 act = make_float4(0, 0, 0, 0);
    int b1 = g_off[n], e1 = g_off[n + 1];
    for (int e = b1; e < e1; e++) {
        int a = g_csrc[e] >> 20;
        float4 v = *(const float4*)(embA + (size_t)a * 4);
        act.x += v.x; act.y += v.y; act.z += v.z; act.w += v.w;
    }
    ((float4*)h0)[4] = trig;
    ((float4*)h0)[5] = act;
}

// ---------------- layer-1 aggregation in 24-dim space (warp per node) ----------------
__global__ void k_agg24() {
    int w = (blockIdx.x * blockDim.x + threadIdx.x) >> 5;
    int lane = threadIdx.x & 31;
    if (w >= N_NODES) return;
    int beg = g_off[w], end = g_off[w + 1];
    float acc = 0.f;
    if (lane < 24) {
        for (int e = beg; e < end; e++) {
            int s = g_csrc[e] & 0xFFFFF;
            acc += g_h0[s * 24 + lane];
        }
        float inv = 1.f / fmaxf((float)(end - beg), 1.f);
        g_agg24[w * 24 + lane] = acc * inv;
    }
}

// =====================================================================================
// k_gemm1_mma: h1 = relu([agg24|h0] @ [W1l;W1r] + b1) via bf16x3 mma.sync
// =====================================================================================
#define G1_SA_H 0
#define G1_SA_L 16384
#define G1_SB_H 32768
#define G1_SB_L 65536
#define G1_SMEM 98304

__global__ __launch_bounds__(256, 1)
void k_gemm1_mma(const float* __restrict__ b1) {
    extern __shared__ char smem[];
    uint32_t sb = smem_u32(smem);
    int tid = threadIdx.x, wid = tid >> 5, lane = tid & 31;
    int r0 = blockIdx.x * 128;

    {
        int m = tid >> 1, h = tid & 1;
        int node = min(r0 + m, N_NODES - 1);
        const float* a24 = g_agg24 + (size_t)node * 24;
        const float* h0p = g_h0 + (size_t)node * 24;
#pragma unroll
        for (int kk = 0; kk < 32; kk += 8) {
            float z[8];
#pragma unroll
            for (int j = 0; j < 8; j++) {
                int k = h * 32 + kk + j;
                z[j] = (k < 24) ? a24[k] : ((k < 48) ? h0p[k - 24] : 0.f);
            }
            uint32_t hw[4], lw[4];
            split8(z, hw, lw);
            int c = h * 4 + (kk >> 3);
            uint32_t off = (uint32_t)m * 128 + (uint32_t)((c ^ (m & 7)) << 4);
            *(uint4*)(smem + G1_SA_H + off) = make_uint4(hw[0], hw[1], hw[2], hw[3]);
            *(uint4*)(smem + G1_SA_L + off) = make_uint4(lw[0], lw[1], lw[2], lw[3]);
        }
    }
    {
        int n = tid;
        const __nv_bfloat16* srcH = g_w1h + (size_t)n * 64;
        const __nv_bfloat16* srcL = g_w1l + (size_t)n * 64;
#pragma unroll
        for (int c = 0; c < 8; c++) {
            uint32_t off = (uint32_t)n * 128 + (uint32_t)((c ^ (n & 7)) << 4);
            *(uint4*)(smem + G1_SB_H + off) = *(const uint4*)(srcH + c * 8);
            *(uint4*)(smem + G1_SB_L + off) = *(const uint4*)(srcL + c * 8);
        }
    }
    __syncthreads();

    uint32_t Ah[16], Al[16];
    {
        int rowA = wid * 16 + (lane & 15);
        uint32_t rbase = (uint32_t)rowA * 128;
        int rx = rowA & 7;
        int csel = lane >> 4;
#pragma unroll
        for (int ks = 0; ks < 4; ks++) {
            int c = ks * 2 + csel;
            uint32_t addr = sb + rbase + (uint32_t)((c ^ rx) << 4);
            ldm_x4(&Ah[ks * 4], addr + G1_SA_H);
            ldm_x4(&Al[ks * 4], addr + G1_SA_L);
        }
    }

    int row0 = r0 + wid * 16 + (lane >> 2);
    int row1 = row0 + 8;
#pragma unroll
    for (int nt = 0; nt < 32; nt++) {
        uint32_t Bh[8], Bl[8];
        {
            int nrow = nt * 8 + (lane & 7);
            uint32_t rbase = (uint32_t)nrow * 128;
            int rx = nrow & 7;
            int csel = lane >> 3;
#pragma unroll
            for (int kp = 0; kp < 2; kp++) {
                int c = kp * 4 + csel;
                uint32_t addr = sb + rbase + (uint32_t)((c ^ rx) << 4);
                ldm_x4(&Bh[kp * 4], addr + G1_SB_H);
                ldm_x4(&Bl[kp * 4], addr + G1_SB_L);
            }
        }
        float accE[4] = {0, 0, 0, 0}, accO[4] = {0, 0, 0, 0};
#pragma unroll
        for (int ks = 0; ks < 4; ks++)
            mma_bf16((ks & 1) ? accO : accE, &Ah[ks * 4], &Bh[ks * 2]);
#pragma unroll
        for (int ks = 0; ks < 4; ks++)
            mma_bf16((ks & 1) ? accO : accE, &Ah[ks * 4], &Bl[ks * 2]);
#pragma unroll
        for (int ks = 0; ks < 4; ks++)
            mma_bf16((ks & 1) ? accO : accE, &Al[ks * 4], &Bh[ks * 2]);

        int col = nt * 8 + ((lane & 3) << 1);
        float bx = b1[col], by = b1[col + 1];
        if (row0 < N_NODES) {
            float2 o = {fmaxf(accE[0] + accO[0] + bx, 0.f), fmaxf(accE[1] + accO[1] + by, 0.f)};
            *(float2*)(g_h1 + (size_t)row0 * 256 + col) = o;
        }
        if (row1 < N_NODES) {
            float2 o = {fmaxf(accE[2] + accO[2] + bx, 0.f), fmaxf(accE[3] + accO[3] + by, 0.f)};
            *(float2*)(g_h1 + (size_t)row1 * 256 + col) = o;
        }
    }
}

// ---------------- layer-2 aggregation: 256-dim gather-reduce (warp per node) ----------------
__global__ void k_agg256() {
    int w = (blockIdx.x * blockDim.x + threadIdx.x) >> 5;
    int lane = threadIdx.x & 31;
    if (w >= N_NODES) return;
    int beg = g_off[w], end = g_off[w + 1];
    float4 a0 = make_float4(0, 0, 0, 0), a1 = a0;
    for (int e = beg; e < end; e++) {
        int s = g_csrc[e] & 0xFFFFF;
        const float4* p = (const float4*)(g_h1 + (size_t)s * 256 + lane * 8);
        float4 x0 = p[0], x1 = p[1];
        a0.x += x0.x; a0.y += x0.y; a0.z += x0.z; a0.w += x0.w;
        a1.x += x1.x; a1.y += x1.y; a1.z += x1.z; a1.w += x1.w;
    }
    float inv = 1.f / fmaxf((float)(end - beg), 1.f);
    a0.x *= inv; a0.y *= inv; a0.z *= inv; a0.w *= inv;
    a1.x *= inv; a1.y *= inv; a1.z *= inv; a1.w *= inv;
    float4* q = (float4*)(g_agg256 + (size_t)w * 256 + lane * 8);
    q[0] = a0; q[1] = a1;
}

// =====================================================================================
// k_gemm2uv_mma: FUSED  h2 = relu([agg256|h1]@[W2l;W2r]+b2);  uv = h2 @ Wuv
// =====================================================================================
#define F_SA_H   0
#define F_SA_L   32768
#define F_SB_H   65536
#define F_SB_L   98304
#define F_A2_H   0
#define F_A2_L   32768
#define F_BUV_H  65536
#define F_BUV_L  131072
#define F_SMEM   196608

__global__ __launch_bounds__(256, 1)
void k_gemm2uv_mma(const float* __restrict__ b2) {
    extern __shared__ char smem[];
    uint32_t sb = smem_u32(smem);
    int tid = threadIdx.x, wid = tid >> 5, lane = tid & 31;
    int r0 = blockIdx.x * 128;

    float acc[16][4];
#pragma unroll
    for (int nt = 0; nt < 16; nt++)
#pragma unroll
        for (int j = 0; j < 4; j++) acc[nt][j] = 0.f;

    for (int kc = 0; kc < 4; kc++) {
        if (kc) __syncthreads();
        {
            int m = tid >> 1, h = tid & 1;
            int node = min(r0 + m, N_NODES - 1);
            const float* src = ((kc < 2) ? (g_agg256 + (size_t)node * 256 + kc * 128)
                                         : (g_h1 + (size_t)node * 256 + (kc - 2) * 128)) + h * 64;
#pragma unroll
            for (int kk = 0; kk < 64; kk += 8) {
                float z[8];
                *(float4*)(z) = *(const float4*)(src + kk);
                *(float4*)(z + 4) = *(const float4*)(src + kk + 4);
                uint32_t hw[4], lw[4];
                split8(z, hw, lw);
                int chunk = h * 8 + (kk >> 3);
                uint32_t off = (uint32_t)m * 256 + (uint32_t)((chunk ^ (m & 7)) << 4);
                *(uint4*)(smem + F_SA_H + off) = make_uint4(hw[0], hw[1], hw[2], hw[3]);
                *(uint4*)(smem + F_SA_L + off) = make_uint4(lw[0], lw[1], lw[2], lw[3]);
            }
        }
        {
            int n = tid >> 1, h = tid & 1;
            const __nv_bfloat16* srcH = g_w2h + (size_t)n * 512 + kc * 128 + h * 64;
            const __nv_bfloat16* srcL = g_w2l + (size_t)n * 512 + kc * 128 + h * 64;
#pragma unroll
            for (int c = 0; c < 8; c++) {
                int chunk = h * 8 + c;
                uint32_t off = (uint32_t)n * 256 + (uint32_t)((chunk ^ (n & 7)) << 4);
                *(uint4*)(smem + F_SB_H + off) = *(const uint4*)(srcH + c * 8);
                *(uint4*)(smem + F_SB_L + off) = *(const uint4*)(srcL + c * 8);
            }
        }
        __syncthreads();

        uint32_t Ah[32], Al[32];
        {
            int rowA = wid * 16 + (lane & 15);
            uint32_t rbase = (uint32_t)rowA * 256;
            int rx = rowA & 7;
            int csel = lane >> 4;
#pragma unroll
            for (int ks = 0; ks < 8; ks++) {
                int chunk = ks * 2 + csel;
                uint32_t addr = sb + rbase + (uint32_t)((chunk ^ rx) << 4);
                ldm_x4(&Ah[ks * 4], addr + F_SA_H);
                ldm_x4(&Al[ks * 4], addr + F_SA_L);
            }
        }
#pragma unroll
        for (int nt = 0; nt < 16; nt++) {
            uint32_t Bh[16], Bl[16];
            {
                int nrow = nt * 8 + (lane & 7);
                uint32_t rbase = (uint32_t)nrow * 256;
                int rx = nrow & 7;
                int csel = lane >> 3;
#pragma unroll
                for (int kp = 0; kp < 4; kp++) {
                    int chunk = kp * 4 + csel;
                    uint32_t addr = sb + rbase + (uint32_t)((chunk ^ rx) << 4);
                    ldm_x4(&Bh[kp * 4], addr + F_SB_H);
                    ldm_x4(&Bl[kp * 4], addr + F_SB_L);
                }
            }
            float accE[4] = {0, 0, 0, 0}, accO[4] = {0, 0, 0, 0};
#pragma unroll
            for (int ks = 0; ks < 8; ks++)
                mma_bf16((ks & 1) ? accO : accE, &Ah[ks * 4], &Bh[ks * 2]);
#pragma unroll
            for (int ks = 0; ks < 8; ks++)
                mma_bf16((ks & 1) ? accO : accE, &Ah[ks * 4], &Bl[ks * 2]);
#pragma unroll
            for (int ks = 0; ks < 8; ks++)
                mma_bf16((ks & 1) ? accO : accE, &Al[ks * 4], &Bh[ks * 2]);
#pragma unroll
            for (int j = 0; j < 4; j++) acc[nt][j] += accE[j] + accO[j];
        }
    }
    __syncthreads();

    {
        int n = tid;
        const __nv_bfloat16* srcH = g_wuvh + (size_t)n * 128;
        const __nv_bfloat16* srcL = g_wuvl + (size_t)n * 128;
#pragma unroll
        for (int c = 0; c < 16; c++) {
            uint32_t off = (uint32_t)n * 256 + (uint32_t)((c ^ (n & 7)) << 4);
            *(uint4*)(smem + F_BUV_H + off) = *(const uint4*)(srcH + c * 8);
            *(uint4*)(smem + F_BUV_L + off) = *(const uint4*)(srcL + c * 8);
        }
    }
    {
        int rloc0 = wid * 16 + (lane >> 2);
        int rloc1 = rloc0 + 8;
        int rx0 = rloc0 & 7, rx1 = rloc1 & 7;
#pragma unroll
        for (int nt = 0; nt < 16; nt++) {
            int c = nt * 8 + ((lane & 3) << 1);
            float bx = b2[c], by = b2[c + 1];
            float v0x = fmaxf(acc[nt][0] + bx, 0.f), v0y = fmaxf(acc[nt][1] + by, 0.f);
            float v1x = fmaxf(acc[nt][2] + bx, 0.f), v1y = fmaxf(acc[nt][3] + by, 0.f);
            uint32_t hw, lw;
            uint32_t base0 = (uint32_t)rloc0 * 256 + (uint32_t)((((c >> 3) ^ rx0)) << 4) + (uint32_t)(c & 7) * 2;
            split2(v0x, v0y, hw, lw);
            *(uint32_t*)(smem + F_A2_H + base0) = hw;
            *(uint32_t*)(smem + F_A2_L + base0) = lw;
            uint32_t base1 = (uint32_t)rloc1 * 256 + (uint32_t)((((c >> 3) ^ rx1)) << 4) + (uint32_t)(c & 7) * 2;
            split2(v1x, v1y, hw, lw);
            *(uint32_t*)(smem + F_A2_H + base1) = hw;
            *(uint32_t*)(smem + F_A2_L + base1) = lw;
        }
    }
    __syncthreads();

    uint32_t Ah[32], Al[32];
    {
        int rowA = wid * 16 + (lane & 15);
        uint32_t rbase = (uint32_t)rowA * 256;
        int rx = rowA & 7;
        int csel = lane >> 4;
#pragma unroll
        for (int ks = 0; ks < 8; ks++) {
            int chunk = ks * 2 + csel;
            uint32_t addr = sb + rbase + (uint32_t)((chunk ^ rx) << 4);
            ldm_x4(&Ah[ks * 4], addr + F_A2_H);
            ldm_x4(&Al[ks * 4], addr + F_A2_L);
        }
    }
    int row0 = r0 + wid * 16 + (lane >> 2);
    int row1 = row0 + 8;
#pragma unroll
    for (int nt = 0; nt < 32; nt++) {
        uint32_t Bh[16], Bl[16];
        {
            int nrow = nt * 8 + (lane & 7);
            uint32_t rbase = (uint32_t)nrow * 256;
            int rx = nrow & 7;
            int csel = lane >> 3;
#pragma unroll
            for (int kp = 0; kp < 4; kp++) {
                int chunk = kp * 4 + csel;
                uint32_t addr = sb + rbase + (uint32_t)((chunk ^ rx) << 4);
                ldm_x4(&Bh[kp * 4], addr + F_BUV_H);
                ldm_x4(&Bl[kp * 4], addr + F_BUV_L);
            }
        }
        float accE[4] = {0, 0, 0, 0}, accO[4] = {0, 0, 0, 0};
#pragma unroll
        for (int ks = 0; ks < 8; ks++)
            mma_bf16((ks & 1) ? accO : accE, &Ah[ks * 4], &Bh[ks * 2]);
#pragma unroll
        for (int ks = 0; ks < 8; ks++)
            mma_bf16((ks & 1) ? accO : accE, &Ah[ks * 4], &Bl[ks * 2]);
#pragma unroll
        for (int ks = 0; ks < 8; ks++)
            mma_bf16((ks & 1) ? accO : accE, &Al[ks * 4], &Bh[ks * 2]);

        int col = nt * 8 + ((lane & 3) << 1);
        if (row0 < N_NODES) {
            float2 o = {accE[0] + accO[0], accE[1] + accO[1]};
            *(float2*)(g_uv + (size_t)row0 * 256 + col) = o;
        }
        if (row1 < N_NODES) {
            float2 o = {accE[2] + accO[2], accE[3] + accO[3]};
            *(float2*)(g_uv + (size_t)row1 * 256 + col) = o;
        }
    }
}

// =====================================================================================
// k_edge_mma: edge classifier, bf16x3 mma.sync, cp.async double-buffered B (6 chunks)
// chunks: 5 x 12 tiles (96 rows) + 1 x 9 tiles (72 rows); buffers at 65536 + buf*49152
// =====================================================================================
#define EM_M     128
#define EM_BUF0  65536
#define EM_BUFSZ 49152
#define EM_LO    24576
#define SM_AH    0
#define SM_AL    32768
#define SM_EDGE_TOTAL 163840

__device__ __forceinline__ void em_load_chunk(uint32_t sb, int buf, int ch, int tid) {
    int rows = (ch == 5) ? 72 : 96;
    int nbase = ch * 96;
    uint32_t bufbase = sb + EM_BUF0 + (uint32_t)buf * EM_BUFSZ;
    for (int id = tid; id < rows * 16; id += 256) {
        int n = id >> 4, c = id & 15;
        uint32_t dst = bufbase + (uint32_t)n * 256 + (uint32_t)((c ^ (n & 7)) << 4);
        cp16(dst, g_wc2h + (size_t)(nbase + n) * 128 + c * 8);
        cp16(dst + EM_LO, g_wc2l + (size_t)(nbase + n) * 128 + c * 8);
    }
}

__global__ __launch_bounds__(256, 1)
void k_edge_mma(const int* __restrict__ egt, const float* __restrict__ bc1,
                const float* __restrict__ bc2, float* __restrict__ out) {
    extern __shared__ char smem[];
    uint32_t sb = smem_u32(smem);
    int tid = threadIdx.x, wid = tid >> 5, lane = tid & 31;
    int e0 = blockIdx.x * EM_M;

    // prefetch chunks 0 and 1 (two groups) while doing A prep + A ldmatrix
    em_load_chunk(sb, 0, 0, tid);
    CP_COMMIT();
    em_load_chunk(sb, 1, 1, tid);
    CP_COMMIT();

    // A prep: z = relu(u[s]+v[d]+bc1) -> hi/lo bf16
    {
        int m = tid >> 1, h = tid & 1;
        int er = e0 + m;
        int s = 0, d = 0;
        if (er < EGT) { s = egt[er]; d = egt[EGT + er]; }
        const float* up = g_uv + (size_t)s * 256 + h * 64;
        const float* vp = g_uv + (size_t)d * 256 + 128 + h * 64;
        const float* bp = bc1 + h * 64;
#pragma unroll
        for (int kk = 0; kk < 64; kk += 8) {
            float z[8];
#pragma unroll
            for (int j = 0; j < 8; j += 4) {
                float4 u4 = *(const float4*)(up + kk + j);
                float4 v4 = *(const float4*)(vp + kk + j);
                float4 b4 = *(const float4*)(bp + kk + j);
                z[j + 0] = fmaxf(u4.x + v4.x + b4.x, 0.f);
                z[j + 1] = fmaxf(u4.y + v4.y + b4.y, 0.f);
                z[j + 2] = fmaxf(u4.z + v4.z + b4.z, 0.f);
                z[j + 3] = fmaxf(u4.w + v4.w + b4.w, 0.f);
            }
            uint32_t hw[4], lw[4];
            split8(z, hw, lw);
            int chunk = h * 8 + (kk >> 3);
            uint32_t off = (uint32_t)m * 256 + (uint32_t)((chunk ^ (m & 7)) << 4);
            *(uint4*)(smem + SM_AH + off) = make_uint4(hw[0], hw[1], hw[2], hw[3]);
            *(uint4*)(smem + SM_AL + off) = make_uint4(lw[0], lw[1], lw[2], lw[3]);
        }
    }
    __syncthreads();   // A smem visible

    uint32_t Ah[32], Al[32];
    {
        int rowA = wid * 16 + (lane & 15);
        uint32_t rbase = (uint32_t)rowA * 256;
        int rx = rowA & 7;
        int csel = lane >> 4;
#pragma unroll
        for (int ks = 0; ks < 8; ks++) {
            int chunk = ks * 2 + csel;
            uint32_t addr = sb + rbase + (uint32_t)((chunk ^ rx) << 4);
            ldm_x4(&Ah[ks * 4], addr + SM_AH);
            ldm_x4(&Al[ks * 4], addr + SM_AL);
        }
    }

    int r0g = e0 + wid * 16 + (lane >> 2);
    bool v0 = r0g < EGT, v1 = (r0g + 8) < EGT;
    float* orow0 = out + (size_t)r0g * 552;
    float* orow1 = orow0 + 8 * 552;

    for (int ch = 0; ch < 6; ch++) {
        // wait for chunk ch (keep at most the following chunk's group pending)
        if (ch < 5) CP_WAIT1(); else CP_WAIT0();
        __syncthreads();    // chunk ch visible to all; also: all warps done with buf[ch&1]'s previous contents
        uint32_t bufbase = sb + EM_BUF0 + (uint32_t)(ch & 1) * EM_BUFSZ;
        int ntiles = (ch == 5) ? 9 : 12;
        for (int jt = 0; jt < ntiles; jt++) {
            uint32_t Bh[16], Bl[16];
            {
                int nrow = jt * 8 + (lane & 7);
                uint32_t rbase = bufbase + (uint32_t)nrow * 256;
                int rx = nrow & 7;
                int csel = lane >> 3;
#pragma unroll
                for (int kp = 0; kp < 4; kp++) {
                    int chunk = kp * 4 + csel;
                    uint32_t addr = rbase + (uint32_t)((chunk ^ rx) << 4);
                    ldm_x4(&Bh[kp * 4], addr);
                    ldm_x4(&Bl[kp * 4], addr + EM_LO);
                }
            }
            float accE[4] = {0, 0, 0, 0}, accO[4] = {0, 0, 0, 0};
#pragma unroll
            for (int ks = 0; ks < 8; ks++)
                mma_bf16((ks & 1) ? accO : accE, &Ah[ks * 4], &Bh[ks * 2]);
#pragma unroll
            for (int ks = 0; ks < 8; ks++)
                mma_bf16((ks & 1) ? accO : accE, &Ah[ks * 4], &Bl[ks * 2]);
#pragma unroll
            for (int ks = 0; ks < 8; ks++)
                mma_bf16((ks & 1) ? accO : accE, &Al[ks * 4], &Bh[ks * 2]);

            int col = (ch * 12 + jt) * 8 + ((lane & 3) << 1);
            float bx = bc2[col], by = bc2[col + 1];
            if (v0) {
                float2 o0 = {sigf(accE[0] + accO[0] + bx), sigf(accE[1] + accO[1] + by)};
                *(float2*)(orow0 + col) = o0;
            }
            if (v1) {
                float2 o1 = {sigf(accE[2] + accO[2] + bx), sigf(accE[3] + accO[3] + by)};
                *(float2*)(orow1 + col) = o1;
            }
        }
        // prefetch chunk ch+2 into the buffer we just finished reading
        if (ch + 2 <= 5) {
            __syncthreads();   // all warps done computing chunk ch
            em_load_chunk(sb, ch & 1, ch + 2, tid);
            CP_COMMIT();
        }
    }
}

// ---------------- launch ----------------
extern "C" void kernel_launch(void* const* d_in, const int* in_sizes, int n_in,
                              void* d_out, int out_size) {
    const float* x    = (const float*)d_in[0];
    const int*   ei   = (const int*)  d_in[1];
    const int*   egt  = (const int*)  d_in[2];
    const int*   ef   = (const int*)  d_in[3];
    const float* embT = (const float*)d_in[4];
    const float* embA = (const float*)d_in[5];
    const float* W1l  = (const float*)d_in[6];
    const float* W1r  = (const float*)d_in[7];
    const float* b1   = (const float*)d_in[8];
    const float* W2l  = (const float*)d_in[9];
    const float* W2r  = (const float*)d_in[10];
    const float* b2   = (const float*)d_in[11];
    const float* Wc1  = (const float*)d_in[12];
    const float* bc1  = (const float*)d_in[13];
    const float* Wc2  = (const float*)d_in[14];
    const float* bc2  = (const float*)d_in[15];
    float* out = (float*)d_out;

    cudaFuncSetAttribute(k_gemm1_mma, cudaFuncAttributeMaxDynamicSharedMemorySize, G1_SMEM);
    cudaFuncSetAttribute(k_gemm2uv_mma, cudaFuncAttributeMaxDynamicSharedMemorySize, F_SMEM);
    cudaFuncSetAttribute(k_edge_mma, cudaFuncAttributeMaxDynamicSharedMemorySize, SM_EDGE_TOTAL);

    k_init<<<(N_NODES + 255) / 256, 256>>>();
    k_wc2_prep<<<(552 * 128 + 255) / 256, 256>>>(Wc2);
    k_w2_prep<<<(128 * 512 + 255) / 256, 256>>>(W2l, W2r);
    k_count<<<(E_EDGES + 255) / 256, 256>>>(ei);
    k_wuv_prep<<<(256 * 128 + 255) / 256, 256>>>(Wc1);
    k_w1_prep<<<(256 * 64 + 255) / 256, 256>>>(W1l, W1r);
    k_scan<<<1, 1024>>>(0);
    k_scan<<<1, 1024>>>(1);
    k_scatter2<<<(E_EDGES + 255) / 256, 256>>>(ei, ef);
    k_h0build<<<(N_NODES + 255) / 256, 256>>>(x, embT, embA);
    k_agg24<<<(N_NODES * 32 + 255) / 256, 256>>>();
    k_gemm1_mma<<<(N_NODES + 127) / 128, 256, G1_SMEM>>>(b1);
    k_agg256<<<(N_NODES * 32 + 255) / 256, 256>>>();
    k_gemm2uv_mma<<<(N_NODES + 127) / 128, 256, F_SMEM>>>(b2);
    k_edge_mma<<<(EGT + EM_M - 1) / EM_M, 256, SM_EDGE_TOTAL>>>(egt, bc1, bc2, out);
}

// round 7
// speedup vs baseline: 1.0867x; 1.0867x over previous
#include <cuda_runtime.h>
#include <cuda_fp16.h>
#include <cstdint>

#define N_NODES 50000
#define E_EDGES 800000
#define EGT     200000

// ---------------- scratch (static device globals; no allocation) ----------------
__device__ float g_h0[N_NODES * 24];        // [x(16) | agg_trigger(4) | agg_action(4)]
__device__ int   g_degd[N_NODES];
__device__ int   g_degs[N_NODES];
__device__ int   g_curd[N_NODES];
__device__ int   g_curs[N_NODES];
__device__ int   g_off[N_NODES + 1];        // CSR by dst
__device__ int   g_offs[N_NODES + 1];       // CSR by src
__device__ int   g_csrc[E_EDGES];           // per in-edge: src | (action<<20)
__device__ int   g_strig[E_EDGES];          // per out-edge: trigger code
__device__ float g_agg24[N_NODES * 24];
__device__ float g_h1[N_NODES * 256];
__device__ float g_agg256[N_NODES * 256];
__device__ float g_uv[N_NODES * 256];       // [u(128) | v(128)] per node
__device__ __half g_wc2[552 * 128];         // Wc2^T fp16, [n][k]
__device__ __half g_w2[128 * 512];          // [W2l;W2r]^T fp16, [n][k]
__device__ __half g_wuv[256 * 128];         // [Wc1_top|Wc1_bot]^T fp16, [n][k]
__device__ __half g_w1[256 * 64];           // [W1l;W1r]^T fp16, [n][k] (k padded 48->64)

// ======================= warp-MMA + async helpers (baseline PTX, sm_80+) =======================
__device__ __forceinline__ uint32_t smem_u32(const void* p) {
    uint32_t a;
    asm("{ .reg .u64 t; cvta.to.shared.u64 t, %1; cvt.u32.u64 %0, t; }" : "=r"(a) : "l"(p));
    return a;
}
__device__ __forceinline__ void ldm_x4(uint32_t* r, uint32_t addr) {
    asm volatile("ldmatrix.sync.aligned.m8n8.x4.shared.b16 {%0,%1,%2,%3}, [%4];"
        : "=r"(r[0]), "=r"(r[1]), "=r"(r[2]), "=r"(r[3]) : "r"(addr));
}
__device__ __forceinline__ void mma_f16(float* c, const uint32_t* a, const uint32_t* b) {
    asm volatile(
        "mma.sync.aligned.m16n8k16.row.col.f32.f16.f16.f32 "
        "{%0,%1,%2,%3}, {%4,%5,%6,%7}, {%8,%9}, {%0,%1,%2,%3};"
        : "+f"(c[0]), "+f"(c[1]), "+f"(c[2]), "+f"(c[3])
        : "r"(a[0]), "r"(a[1]), "r"(a[2]), "r"(a[3]), "r"(b[0]), "r"(b[1]));
}
__device__ __forceinline__ void cp16(uint32_t dst, const void* src) {
    asm volatile("cp.async.cg.shared.global [%0], [%1], 16;" :: "r"(dst), "l"(src));
}
#define CP_COMMIT() asm volatile("cp.async.commit_group;" ::: "memory")
#define CP_WAIT0()  asm volatile("cp.async.wait_group 0;" ::: "memory")
__device__ __forceinline__ float sigf(float x) { return 1.f / (1.f + __expf(-x)); }

// split fp32 -> (hi, lo) fp16 pair words from 8 consecutive floats
__device__ __forceinline__ void split8h(const float* z, uint32_t* hw, uint32_t* lw) {
#pragma unroll
    for (int p = 0; p < 4; p++) {
        __half h0 = __float2half(z[2 * p]);
        __half h1 = __float2half(z[2 * p + 1]);
        __half l0 = __float2half(z[2 * p] - __half2float(h0));
        __half l1 = __float2half(z[2 * p + 1] - __half2float(h1));
        __half2 hh = __halves2half2(h0, h1), ll = __halves2half2(l0, l1);
        hw[p] = *reinterpret_cast<uint32_t*>(&hh);
        lw[p] = *reinterpret_cast<uint32_t*>(&ll);
    }
}
__device__ __forceinline__ void split2h(float x, float y, uint32_t& hw, uint32_t& lw) {
    __half h0 = __float2half(x);
    __half h1 = __float2half(y);
    __half l0 = __float2half(x - __half2float(h0));
    __half l1 = __float2half(y - __half2float(h1));
    __half2 hh = __halves2half2(h0, h1), ll = __halves2half2(l0, l1);
    hw = *reinterpret_cast<uint32_t*>(&hh);
    lw = *reinterpret_cast<uint32_t*>(&ll);
}

// ---------------- fused prep: zero counters + all weight transposes (fp16) ----------------
__global__ void k_prep(const float* __restrict__ Wc2, const float* __restrict__ W2l,
                       const float* __restrict__ W2r, const float* __restrict__ Wc1,
                       const float* __restrict__ W1l, const float* __restrict__ W1r) {
    int i = blockIdx.x * blockDim.x + threadIdx.x;
    if (i < N_NODES) { g_degd[i] = 0; g_degs[i] = 0; g_curd[i] = 0; g_curs[i] = 0; }
    if (i < 552 * 128) {
        int n = i >> 7, k = i & 127;
        g_wc2[i] = __float2half(Wc2[(size_t)k * 552 + n]);
    }
    if (i < 128 * 512) {
        int n = i >> 9, k = i & 511;
        float w = (k < 256) ? W2l[(size_t)k * 128 + n] : W2r[(size_t)(k - 256) * 128 + n];
        g_w2[i] = __float2half(w);
    }
    if (i < 256 * 128) {
        int n = i >> 7, k = i & 127;
        float w = (n < 128) ? Wc1[(size_t)k * 128 + n] : Wc1[(size_t)(128 + k) * 128 + (n - 128)];
        g_wuv[i] = __float2half(w);
    }
    if (i < 256 * 64) {
        int n = i >> 6, k = i & 63;
        float w = 0.f;
        if (k < 24) w = W1l[(size_t)k * 256 + n];
        else if (k < 48) w = W1r[(size_t)(k - 24) * 256 + n];
        g_w1[i] = __float2half(w);
    }
}

// ---------------- degree count (both directions) ----------------
__global__ void k_count(const int* __restrict__ ei) {
    int e = blockIdx.x * blockDim.x + threadIdx.x;
    if (e >= E_EDGES) return;
    atomicAdd(&g_degs[ei[e]], 1);
    atomicAdd(&g_degd[ei[E_EDGES + e]], 1);
}

// ---------------- scan (selector: 0 = dst-CSR, 1 = src-CSR) ----------------
__global__ void k_scan(int which) {
    const int* deg = which ? g_degs : g_degd;
    int* off = which ? g_offs : g_off;
    const int CH = (N_NODES + 1023) / 1024;
    int tid = threadIdx.x, lane = tid & 31, wid = tid >> 5;
    int beg = tid * CH, end = min(beg + CH, N_NODES);
    int sum = 0;
    for (int i = beg; i < end; i++) sum += deg[i];
    int v = sum;
#pragma unroll
    for (int o = 1; o < 32; o <<= 1) {
        int t = __shfl_up_sync(0xFFFFFFFFu, v, o);
        if (lane >= o) v += t;
    }
    __shared__ int wsum[32];
    if (lane == 31) wsum[wid] = v;
    __syncthreads();
    if (wid == 0) {
        int w = wsum[lane];
#pragma unroll
        for (int o = 1; o < 32; o <<= 1) {
            int t = __shfl_up_sync(0xFFFFFFFFu, w, o);
            if (lane >= o) w += t;
        }
        wsum[lane] = w;
    }
    __syncthreads();
    int base = v - sum + (wid ? wsum[wid - 1] : 0);
    for (int i = beg; i < end; i++) { off[i] = base; base += deg[i]; }
    if (tid == 1023) off[N_NODES] = base;
}

// ---------------- scatter both CSRs (action packed into csrc high bits) ----------------
__global__ void k_scatter2(const int* __restrict__ ei, const int* __restrict__ ef) {
    int e = blockIdx.x * blockDim.x + threadIdx.x;
    if (e >= E_EDGES) return;
    int s = ei[e], d = ei[E_EDGES + e];
    int t = ef[2 * e], a = ef[2 * e + 1];
    int posd = g_off[d] + atomicAdd(&g_curd[d], 1);
    g_csrc[posd] = s | (a << 20);
    int poss = g_offs[s] + atomicAdd(&g_curs[s], 1);
    g_strig[poss] = t;
}

// ---------------- h0 build: x copy + trigger/action gather-reduce (no atomics) ----------------
__global__ void k_h0build(const float* __restrict__ x,
                          const float* __restrict__ embT, const float* __restrict__ embA) {
    int n = blockIdx.x * blockDim.x + threadIdx.x;
    if (n >= N_NODES) return;
    float* h0 = g_h0 + (size_t)n * 24;
    const float4* xp = (const float4*)(x + (size_t)n * 16);
#pragma unroll
    for (int j = 0; j < 4; j++) ((float4*)h0)[j] = xp[j];
    float4 trig = make_float4(0, 0, 0, 0);
    int b0 = g_offs[n], e0 = g_offs[n + 1];
    for (int e = b0; e < e0; e++) {
        int t = g_strig[e];
        float4 v = *(const float4*)(embT + (size_t)t * 4);
        trig.x += v.x; trig.y += v.y; trig.z += v.z; trig.w += v.w;
    }
    float4 act = make_float4(0, 0, 0, 0);
    int b1 = g_off[n], e1 = g_off[n + 1];
    for (int e = b1; e < e1; e++) {
        int a = g_csrc[e] >> 20;
        float4 v = *(const float4*)(embA + (size_t)a * 4);
        act.x += v.x; act.y += v.y; act.z += v.z; act.w += v.w;
    }
    ((float4*)h0)[4] = trig;
    ((float4*)h0)[5] = act;
}

// ---------------- layer-1 aggregation in 24-dim space (warp per node) ----------------
__global__ void k_agg24() {
    int w = (blockIdx.x * blockDim.x + threadIdx.x) >> 5;
    int lane = threadIdx.x & 31;
    if (w >= N_NODES) return;
    int beg = g_off[w], end = g_off[w + 1];
    float acc = 0.f;
    if (lane < 24) {
        for (int e = beg; e < end; e++) {
            int s = g_csrc[e] & 0xFFFFF;
            acc += g_h0[s * 24 + lane];
        }
        float inv = 1.f / fmaxf((float)(end - beg), 1.f);
        g_agg24[w * 24 + lane] = acc * inv;
    }
}

// =====================================================================================
// k_gemm1_mma: h1 = relu([agg24|h0] @ [W1l;W1r] + b1) via fp16x2 mma.sync
// CTA: 128 nodes x 256 outs, K=64 (48 padded). 256 threads.
// =====================================================================================
#define G1_SA_H 0
#define G1_SA_L 16384
#define G1_SB   32768
#define G1_SMEM 65536

__global__ __launch_bounds__(256, 1)
void k_gemm1_mma(const float* __restrict__ b1) {
    extern __shared__ char smem[];
    uint32_t sb = smem_u32(smem);
    int tid = threadIdx.x, wid = tid >> 5, lane = tid & 31;
    int r0 = blockIdx.x * 128;

    // A: 128 rows x 64 k (thread = row tid/2, 32-k half tid&1), row stride 128B
    {
        int m = tid >> 1, h = tid & 1;
        int node = min(r0 + m, N_NODES - 1);
        const float* a24 = g_agg24 + (size_t)node * 24;
        const float* h0p = g_h0 + (size_t)node * 24;
#pragma unroll
        for (int kk = 0; kk < 32; kk += 8) {
            float z[8];
#pragma unroll
            for (int j = 0; j < 8; j++) {
                int k = h * 32 + kk + j;
                z[j] = (k < 24) ? a24[k] : ((k < 48) ? h0p[k - 24] : 0.f);
            }
            uint32_t hw[4], lw[4];
            split8h(z, hw, lw);
            int c = h * 4 + (kk >> 3);
            uint32_t off = (uint32_t)m * 128 + (uint32_t)((c ^ (m & 7)) << 4);
            *(uint4*)(smem + G1_SA_H + off) = make_uint4(hw[0], hw[1], hw[2], hw[3]);
            *(uint4*)(smem + G1_SA_L + off) = make_uint4(lw[0], lw[1], lw[2], lw[3]);
        }
    }
    // B: 256 n-rows x 64 k, row stride 128B (thread = n row)
    {
        int n = tid;
        const __half* src = g_w1 + (size_t)n * 64;
#pragma unroll
        for (int c = 0; c < 8; c++) {
            uint32_t off = (uint32_t)n * 128 + (uint32_t)((c ^ (n & 7)) << 4);
            *(uint4*)(smem + G1_SB + off) = *(const uint4*)(src + c * 8);
        }
    }
    __syncthreads();

    uint32_t Ah[16], Al[16];
    {
        int rowA = wid * 16 + (lane & 15);
        uint32_t rbase = (uint32_t)rowA * 128;
        int rx = rowA & 7;
        int csel = lane >> 4;
#pragma unroll
        for (int ks = 0; ks < 4; ks++) {
            int c = ks * 2 + csel;
            uint32_t addr = sb + rbase + (uint32_t)((c ^ rx) << 4);
            ldm_x4(&Ah[ks * 4], addr + G1_SA_H);
            ldm_x4(&Al[ks * 4], addr + G1_SA_L);
        }
    }

    int row0 = r0 + wid * 16 + (lane >> 2);
    int row1 = row0 + 8;
#pragma unroll
    for (int nt = 0; nt < 32; nt++) {
        uint32_t B[8];
        {
            int nrow = nt * 8 + (lane & 7);
            uint32_t rbase = (uint32_t)nrow * 128;
            int rx = nrow & 7;
            int csel = lane >> 3;
#pragma unroll
            for (int kp = 0; kp < 2; kp++) {
                int c = kp * 4 + csel;
                ldm_x4(&B[kp * 4], sb + G1_SB + rbase + (uint32_t)((c ^ rx) << 4));
            }
        }
        float accE[4] = {0, 0, 0, 0}, accO[4] = {0, 0, 0, 0};
#pragma unroll
        for (int ks = 0; ks < 4; ks++) {
            mma_f16((ks & 1) ? accO : accE, &Ah[ks * 4], &B[ks * 2]);
            mma_f16((ks & 1) ? accO : accE, &Al[ks * 4], &B[ks * 2]);
        }
        int col = nt * 8 + ((lane & 3) << 1);
        float bx = b1[col], by = b1[col + 1];
        if (row0 < N_NODES) {
            float2 o = {fmaxf(accE[0] + accO[0] + bx, 0.f), fmaxf(accE[1] + accO[1] + by, 0.f)};
            *(float2*)(g_h1 + (size_t)row0 * 256 + col) = o;
        }
        if (row1 < N_NODES) {
            float2 o = {fmaxf(accE[2] + accO[2] + bx, 0.f), fmaxf(accE[3] + accO[3] + by, 0.f)};
            *(float2*)(g_h1 + (size_t)row1 * 256 + col) = o;
        }
    }
}

// ---------------- layer-2 aggregation: 256-dim gather-reduce (warp per node) ----------------
__global__ void k_agg256() {
    int w = (blockIdx.x * blockDim.x + threadIdx.x) >> 5;
    int lane = threadIdx.x & 31;
    if (w >= N_NODES) return;
    int beg = g_off[w], end = g_off[w + 1];
    float4 a0 = make_float4(0, 0, 0, 0), a1 = a0;
    for (int e = beg; e < end; e++) {
        int s = g_csrc[e] & 0xFFFFF;
        const float4* p = (const float4*)(g_h1 + (size_t)s * 256 + lane * 8);
        float4 x0 = p[0], x1 = p[1];
        a0.x += x0.x; a0.y += x0.y; a0.z += x0.z; a0.w += x0.w;
        a1.x += x1.x; a1.y += x1.y; a1.z += x1.z; a1.w += x1.w;
    }
    float inv = 1.f / fmaxf((float)(end - beg), 1.f);
    a0.x *= inv; a0.y *= inv; a0.z *= inv; a0.w *= inv;
    a1.x *= inv; a1.y *= inv; a1.z *= inv; a1.w *= inv;
    float4* q = (float4*)(g_agg256 + (size_t)w * 256 + lane * 8);
    q[0] = a0; q[1] = a1;
}

// =====================================================================================
// k_gemm2uv_mma: FUSED  h2 = relu([agg256|h1]@[W2l;W2r]+b2);  uv = h2 @ Wuv  (fp16x2)
// =====================================================================================
#define F_SA_H   0
#define F_SA_L   32768
#define F_SB     65536
#define F_A2_H   0
#define F_A2_L   32768
#define F_BUV    65536
#define F_SMEM   131072

__global__ __launch_bounds__(256, 1)
void k_gemm2uv_mma(const float* __restrict__ b2) {
    extern __shared__ char smem[];
    uint32_t sb = smem_u32(smem);
    int tid = threadIdx.x, wid = tid >> 5, lane = tid & 31;
    int r0 = blockIdx.x * 128;

    float acc[16][4];
#pragma unroll
    for (int nt = 0; nt < 16; nt++)
#pragma unroll
        for (int j = 0; j < 4; j++) acc[nt][j] = 0.f;

    // ---------------- phase 1: h2 accumulation over K=512 ----------------
    for (int kc = 0; kc < 4; kc++) {
        if (kc) __syncthreads();
        {
            int m = tid >> 1, h = tid & 1;
            int node = min(r0 + m, N_NODES - 1);
            const float* src = ((kc < 2) ? (g_agg256 + (size_t)node * 256 + kc * 128)
                                         : (g_h1 + (size_t)node * 256 + (kc - 2) * 128)) + h * 64;
#pragma unroll
            for (int kk = 0; kk < 64; kk += 8) {
                float z[8];
                *(float4*)(z) = *(const float4*)(src + kk);
                *(float4*)(z + 4) = *(const float4*)(src + kk + 4);
                uint32_t hw[4], lw[4];
                split8h(z, hw, lw);
                int chunk = h * 8 + (kk >> 3);
                uint32_t off = (uint32_t)m * 256 + (uint32_t)((chunk ^ (m & 7)) << 4);
                *(uint4*)(smem + F_SA_H + off) = make_uint4(hw[0], hw[1], hw[2], hw[3]);
                *(uint4*)(smem + F_SA_L + off) = make_uint4(lw[0], lw[1], lw[2], lw[3]);
            }
        }
        {
            int n = tid >> 1, h = tid & 1;
            const __half* src = g_w2 + (size_t)n * 512 + kc * 128 + h * 64;
#pragma unroll
            for (int c = 0; c < 8; c++) {
                int chunk = h * 8 + c;
                uint32_t off = (uint32_t)n * 256 + (uint32_t)((chunk ^ (n & 7)) << 4);
                *(uint4*)(smem + F_SB + off) = *(const uint4*)(src + c * 8);
            }
        }
        __syncthreads();

        uint32_t Ah[32], Al[32];
        {
            int rowA = wid * 16 + (lane & 15);
            uint32_t rbase = (uint32_t)rowA * 256;
            int rx = rowA & 7;
            int csel = lane >> 4;
#pragma unroll
            for (int ks = 0; ks < 8; ks++) {
                int chunk = ks * 2 + csel;
                uint32_t addr = sb + rbase + (uint32_t)((chunk ^ rx) << 4);
                ldm_x4(&Ah[ks * 4], addr + F_SA_H);
                ldm_x4(&Al[ks * 4], addr + F_SA_L);
            }
        }
#pragma unroll
        for (int nt = 0; nt < 16; nt++) {
            uint32_t B[16];
            {
                int nrow = nt * 8 + (lane & 7);
                uint32_t rbase = (uint32_t)nrow * 256;
                int rx = nrow & 7;
                int csel = lane >> 3;
#pragma unroll
                for (int kp = 0; kp < 4; kp++) {
                    int chunk = kp * 4 + csel;
                    ldm_x4(&B[kp * 4], sb + F_SB + rbase + (uint32_t)((chunk ^ rx) << 4));
                }
            }
            float accE[4] = {0, 0, 0, 0}, accO[4] = {0, 0, 0, 0};
#pragma unroll
            for (int ks = 0; ks < 8; ks++) {
                mma_f16((ks & 1) ? accO : accE, &Ah[ks * 4], &B[ks * 2]);
                mma_f16((ks & 1) ? accO : accE, &Al[ks * 4], &B[ks * 2]);
            }
#pragma unroll
            for (int j = 0; j < 4; j++) acc[nt][j] += accE[j] + accO[j];
        }
    }
    __syncthreads();

    // ---------------- phase 2: h2 -> A2 smem (fp16 hi/lo), Buv load, GEMM -> g_uv ----------------
    {
        int n = tid;
        const __half* src = g_wuv + (size_t)n * 128;
#pragma unroll
        for (int c = 0; c < 16; c++) {
            uint32_t off = (uint32_t)n * 256 + (uint32_t)((c ^ (n & 7)) << 4);
            *(uint4*)(smem + F_BUV + off) = *(const uint4*)(src + c * 8);
        }
    }
    {
        int rloc0 = wid * 16 + (lane >> 2);
        int rloc1 = rloc0 + 8;
        int rx0 = rloc0 & 7, rx1 = rloc1 & 7;
#pragma unroll
        for (int nt = 0; nt < 16; nt++) {
            int c = nt * 8 + ((lane & 3) << 1);
            float bx = b2[c], by = b2[c + 1];
            float v0x = fmaxf(acc[nt][0] + bx, 0.f), v0y = fmaxf(acc[nt][1] + by, 0.f);
            float v1x = fmaxf(acc[nt][2] + bx, 0.f), v1y = fmaxf(acc[nt][3] + by, 0.f);
            uint32_t hw, lw;
            uint32_t base0 = (uint32_t)rloc0 * 256 + (uint32_t)((((c >> 3) ^ rx0)) << 4) + (uint32_t)(c & 7) * 2;
            split2h(v0x, v0y, hw, lw);
            *(uint32_t*)(smem + F_A2_H + base0) = hw;
            *(uint32_t*)(smem + F_A2_L + base0) = lw;
            uint32_t base1 = (uint32_t)rloc1 * 256 + (uint32_t)((((c >> 3) ^ rx1)) << 4) + (uint32_t)(c & 7) * 2;
            split2h(v1x, v1y, hw, lw);
            *(uint32_t*)(smem + F_A2_H + base1) = hw;
            *(uint32_t*)(smem + F_A2_L + base1) = lw;
        }
    }
    __syncthreads();

    uint32_t Ah[32], Al[32];
    {
        int rowA = wid * 16 + (lane & 15);
        uint32_t rbase = (uint32_t)rowA * 256;
        int rx = rowA & 7;
        int csel = lane >> 4;
#pragma unroll
        for (int ks = 0; ks < 8; ks++) {
            int chunk = ks * 2 + csel;
            uint32_t addr = sb + rbase + (uint32_t)((chunk ^ rx) << 4);
            ldm_x4(&Ah[ks * 4], addr + F_A2_H);
            ldm_x4(&Al[ks * 4], addr + F_A2_L);
        }
    }
    int row0 = r0 + wid * 16 + (lane >> 2);
    int row1 = row0 + 8;
#pragma unroll
    for (int nt = 0; nt < 32; nt++) {
        uint32_t B[16];
        {
            int nrow = nt * 8 + (lane & 7);
            uint32_t rbase = (uint32_t)nrow * 256;
            int rx = nrow & 7;
            int csel = lane >> 3;
#pragma unroll
            for (int kp = 0; kp < 4; kp++) {
                int chunk = kp * 4 + csel;
                ldm_x4(&B[kp * 4], sb + F_BUV + rbase + (uint32_t)((chunk ^ rx) << 4));
            }
        }
        float accE[4] = {0, 0, 0, 0}, accO[4] = {0, 0, 0, 0};
#pragma unroll
        for (int ks = 0; ks < 8; ks++) {
            mma_f16((ks & 1) ? accO : accE, &Ah[ks * 4], &B[ks * 2]);
            mma_f16((ks & 1) ? accO : accE, &Al[ks * 4], &B[ks * 2]);
        }
        int col = nt * 8 + ((lane & 3) << 1);
        if (row0 < N_NODES) {
            float2 o = {accE[0] + accO[0], accE[1] + accO[1]};
            *(float2*)(g_uv + (size_t)row0 * 256 + col) = o;
        }
        if (row1 < N_NODES) {
            float2 o = {accE[2] + accO[2], accE[3] + accO[3]};
            *(float2*)(g_uv + (size_t)row1 * 256 + col) = o;
        }
    }
}

// =====================================================================================
// k_edge_mma: edge classifier, fp16x2 mma.sync; FULL B (552x128 fp16 = 141KB) in SMEM
// =====================================================================================
#define EM_M     128
#define SM_AH    0
#define SM_AL    32768
#define SM_B     65536
#define SM_EDGE_TOTAL (65536 + 552 * 256)   // 206848

__global__ __launch_bounds__(256, 1)
void k_edge_mma(const int* __restrict__ egt, const float* __restrict__ bc1,
                const float* __restrict__ bc2, float* __restrict__ out) {
    extern __shared__ char smem[];
    uint32_t sb = smem_u32(smem);
    int tid = threadIdx.x, wid = tid >> 5, lane = tid & 31;
    int e0 = blockIdx.x * EM_M;

    // async-load the full B (552 rows x 128 k fp16), overlapped with A prep
    for (int id = tid; id < 552 * 16; id += 256) {
        int n = id >> 4, c = id & 15;
        uint32_t dst = sb + SM_B + (uint32_t)n * 256 + (uint32_t)((c ^ (n & 7)) << 4);
        cp16(dst, g_wc2 + (size_t)n * 128 + c * 8);
    }
    CP_COMMIT();

    // A prep: z = relu(u[s]+v[d]+bc1) -> fp16 hi/lo
    {
        int m = tid >> 1, h = tid & 1;
        int er = e0 + m;
        int s = 0, d = 0;
        if (er < EGT) { s = egt[er]; d = egt[EGT + er]; }
        const float* up = g_uv + (size_t)s * 256 + h * 64;
        const float* vp = g_uv + (size_t)d * 256 + 128 + h * 64;
        const float* bp = bc1 + h * 64;
#pragma unroll
        for (int kk = 0; kk < 64; kk += 8) {
            float z[8];
#pragma unroll
            for (int j = 0; j < 8; j += 4) {
                float4 u4 = *(const float4*)(up + kk + j);
                float4 v4 = *(const float4*)(vp + kk + j);
                float4 b4 = *(const float4*)(bp + kk + j);
                z[j + 0] = fmaxf(u4.x + v4.x + b4.x, 0.f);
                z[j + 1] = fmaxf(u4.y + v4.y + b4.y, 0.f);
                z[j + 2] = fmaxf(u4.z + v4.z + b4.z, 0.f);
                z[j + 3] = fmaxf(u4.w + v4.w + b4.w, 0.f);
            }
            uint32_t hw[4], lw[4];
            split8h(z, hw, lw);
            int chunk = h * 8 + (kk >> 3);
            uint32_t off = (uint32_t)m * 256 + (uint32_t)((chunk ^ (m & 7)) << 4);
            *(uint4*)(smem + SM_AH + off) = make_uint4(hw[0], hw[1], hw[2], hw[3]);
            *(uint4*)(smem + SM_AL + off) = make_uint4(lw[0], lw[1], lw[2], lw[3]);
        }
    }
    CP_WAIT0();
    __syncthreads();   // A + B smem visible

    uint32_t Ah[32], Al[32];
    {
        int rowA = wid * 16 + (lane & 15);
        uint32_t rbase = (uint32_t)rowA * 256;
        int rx = rowA & 7;
        int csel = lane >> 4;
#pragma unroll
        for (int ks = 0; ks < 8; ks++) {
            int chunk = ks * 2 + csel;
            uint32_t addr = sb + rbase + (uint32_t)((chunk ^ rx) << 4);
            ldm_x4(&Ah[ks * 4], addr + SM_AH);
            ldm_x4(&Al[ks * 4], addr + SM_AL);
        }
    }

    int r0g = e0 + wid * 16 + (lane >> 2);
    bool v0 = r0g < EGT, v1 = (r0g + 8) < EGT;
    float* orow0 = out + (size_t)r0g * 552;
    float* orow1 = orow0 + 8 * 552;

    for (int jt = 0; jt < 69; jt++) {
        uint32_t B[16];
        {
            int nrow = jt * 8 + (lane & 7);
            uint32_t rbase = sb + SM_B + (uint32_t)nrow * 256;
            int rx = nrow & 7;
            int csel = lane >> 3;
#pragma unroll
            for (int kp = 0; kp < 4; kp++) {
                int chunk = kp * 4 + csel;
                ldm_x4(&B[kp * 4], rbase + (uint32_t)((chunk ^ rx) << 4));
            }
        }
        float accE[4] = {0, 0, 0, 0}, accO[4] = {0, 0, 0, 0};
#pragma unroll
        for (int ks = 0; ks < 8; ks++) {
            mma_f16((ks & 1) ? accO : accE, &Ah[ks * 4], &B[ks * 2]);
            mma_f16((ks & 1) ? accO : accE, &Al[ks * 4], &B[ks * 2]);
        }
        int col = jt * 8 + ((lane & 3) << 1);
        float bx = bc2[col], by = bc2[col + 1];
        if (v0) {
            float2 o0 = {sigf(accE[0] + accO[0] + bx), sigf(accE[1] + accO[1] + by)};
            *(float2*)(orow0 + col) = o0;
        }
        if (v1) {
            float2 o1 = {sigf(accE[2] + accO[2] + bx), sigf(accE[3] + accO[3] + by)};
            *(float2*)(orow1 + col) = o1;
        }
    }
}

// ---------------- launch ----------------
extern "C" void kernel_launch(void* const* d_in, const int* in_sizes, int n_in,
                              void* d_out, int out_size) {
    const float* x    = (const float*)d_in[0];
    const int*   ei   = (const int*)  d_in[1];
    const int*   egt  = (const int*)  d_in[2];
    const int*   ef   = (const int*)  d_in[3];
    const float* embT = (const float*)d_in[4];
    const float* embA = (const float*)d_in[5];
    const float* W1l  = (const float*)d_in[6];
    const float* W1r  = (const float*)d_in[7];
    const float* b1   = (const float*)d_in[8];
    const float* W2l  = (const float*)d_in[9];
    const float* W2r  = (const float*)d_in[10];
    const float* b2   = (const float*)d_in[11];
    const float* Wc1  = (const float*)d_in[12];
    const float* bc1  = (const float*)d_in[13];
    const float* Wc2  = (const float*)d_in[14];
    const float* bc2  = (const float*)d_in[15];
    float* out = (float*)d_out;

    cudaFuncSetAttribute(k_gemm1_mma, cudaFuncAttributeMaxDynamicSharedMemorySize, G1_SMEM);
    cudaFuncSetAttribute(k_gemm2uv_mma, cudaFuncAttributeMaxDynamicSharedMemorySize, F_SMEM);
    cudaFuncSetAttribute(k_edge_mma, cudaFuncAttributeMaxDynamicSharedMemorySize, SM_EDGE_TOTAL);

    k_prep<<<(552 * 128 + 255) / 256, 256>>>(Wc2, W2l, W2r, Wc1, W1l, W1r);
    k_count<<<(E_EDGES + 255) / 256, 256>>>(ei);
    k_scan<<<1, 1024>>>(0);
    k_scan<<<1, 1024>>>(1);
    k_scatter2<<<(E_EDGES + 255) / 256, 256>>>(ei, ef);
    k_h0build<<<(N_NODES + 255) / 256, 256>>>(x, embT, embA);
    k_agg24<<<(N_NODES * 32 + 255) / 256, 256>>>();
    k_gemm1_mma<<<(N_NODES + 127) / 128, 256, G1_SMEM>>>(b1);
    k_agg256<<<(N_NODES * 32 + 255) / 256, 256>>>();
    k_gemm2uv_mma<<<(N_NODES + 127) / 128, 256, F_SMEM>>>(b2);
    k_edge_mma<<<(EGT + EM_M - 1) / EM_M, 256, SM_EDGE_TOTAL>>>(egt, bc1, bc2, out);
}

// round 8
// speedup vs baseline: 1.1782x; 1.0842x over previous
#include <cuda_runtime.h>
#include <cuda_fp16.h>
#include <cstdint>

#define N_NODES 50000
#define E_EDGES 800000
#define EGT     200000
#define NPAD    53248      // 1024 threads * 52 (CH), multiple of 4

// ---------------- scratch (static device globals; no allocation) ----------------
__device__ float g_h0[N_NODES * 24];        // [x(16) | agg_trigger(4) | agg_action(4)]
__device__ int   g_degd[NPAD];
__device__ int   g_degs[NPAD];
__device__ int   g_curd[N_NODES];
__device__ int   g_curs[N_NODES];
__device__ int   g_off[NPAD + 4];           // CSR by dst
__device__ int   g_offs[NPAD + 4];          // CSR by src
__device__ int   g_csrc[E_EDGES];           // per in-edge: src | (action<<20)
__device__ int   g_strig[E_EDGES];          // per out-edge: trigger code
__device__ float g_agg24[N_NODES * 24];
__device__ float g_h1[N_NODES * 256];
__device__ float g_agg256[N_NODES * 256];
__device__ float g_uv[N_NODES * 256];       // [u(128) | v(128)] per node
__device__ __half g_wc2[552 * 128];         // Wc2^T fp16, [n][k]
__device__ __half g_w2[128 * 512];          // [W2l;W2r]^T fp16, [n][k]
__device__ __half g_wuv[256 * 128];         // [Wc1_top|Wc1_bot]^T fp16, [n][k]
__device__ __half g_w1[256 * 64];           // [W1l;W1r]^T fp16, [n][k] (k padded 48->64)

// ======================= warp-MMA + async helpers (baseline PTX, sm_80+) =======================
__device__ __forceinline__ uint32_t smem_u32(const void* p) {
    uint32_t a;
    asm("{ .reg .u64 t; cvta.to.shared.u64 t, %1; cvt.u32.u64 %0, t; }" : "=r"(a) : "l"(p));
    return a;
}
__device__ __forceinline__ void ldm_x4(uint32_t* r, uint32_t addr) {
    asm volatile("ldmatrix.sync.aligned.m8n8.x4.shared.b16 {%0,%1,%2,%3}, [%4];"
        : "=r"(r[0]), "=r"(r[1]), "=r"(r[2]), "=r"(r[3]) : "r"(addr));
}
__device__ __forceinline__ void mma_f16(float* c, const uint32_t* a, const uint32_t* b) {
    asm volatile(
        "mma.sync.aligned.m16n8k16.row.col.f32.f16.f16.f32 "
        "{%0,%1,%2,%3}, {%4,%5,%6,%7}, {%8,%9}, {%0,%1,%2,%3};"
        : "+f"(c[0]), "+f"(c[1]), "+f"(c[2]), "+f"(c[3])
        : "r"(a[0]), "r"(a[1]), "r"(a[2]), "r"(a[3]), "r"(b[0]), "r"(b[1]));
}
__device__ __forceinline__ void cp16(uint32_t dst, const void* src) {
    asm volatile("cp.async.cg.shared.global [%0], [%1], 16;" :: "r"(dst), "l"(src));
}
#define CP_COMMIT() asm volatile("cp.async.commit_group;" ::: "memory")
#define CP_WAIT0()  asm volatile("cp.async.wait_group 0;" ::: "memory")
__device__ __forceinline__ float sigf(float x) { return 1.f / (1.f + __expf(-x)); }

// split fp32 -> (hi, lo) fp16 pair words from 8 consecutive floats
__device__ __forceinline__ void split8h(const float* z, uint32_t* hw, uint32_t* lw) {
#pragma unroll
    for (int p = 0; p < 4; p++) {
        __half h0 = __float2half(z[2 * p]);
        __half h1 = __float2half(z[2 * p + 1]);
        __half l0 = __float2half(z[2 * p] - __half2float(h0));
        __half l1 = __float2half(z[2 * p + 1] - __half2float(h1));
        __half2 hh = __halves2half2(h0, h1), ll = __halves2half2(l0, l1);
        hw[p] = *reinterpret_cast<uint32_t*>(&hh);
        lw[p] = *reinterpret_cast<uint32_t*>(&ll);
    }
}
__device__ __forceinline__ void split2h(float x, float y, uint32_t& hw, uint32_t& lw) {
    __half h0 = __float2half(x);
    __half h1 = __float2half(y);
    __half l0 = __float2half(x - __half2float(h0));
    __half l1 = __float2half(y - __half2float(h1));
    __half2 hh = __halves2half2(h0, h1), ll = __halves2half2(l0, l1);
    hw = *reinterpret_cast<uint32_t*>(&hh);
    lw = *reinterpret_cast<uint32_t*>(&ll);
}

// ---------------- fused prep: zero counters (incl. padding) + weight transposes (fp16) ----------------
__global__ void k_prep(const float* __restrict__ Wc2, const float* __restrict__ W2l,
                       const float* __restrict__ W2r, const float* __restrict__ Wc1,
                       const float* __restrict__ W1l, const float* __restrict__ W1r) {
    int i = blockIdx.x * blockDim.x + threadIdx.x;
    if (i < NPAD) { g_degd[i] = 0; g_degs[i] = 0; }
    if (i < N_NODES) { g_curd[i] = 0; g_curs[i] = 0; }
    if (i < 552 * 128) {
        int n = i >> 7, k = i & 127;
        g_wc2[i] = __float2half(Wc2[(size_t)k * 552 + n]);
    }
    if (i < 128 * 512) {
        int n = i >> 9, k = i & 511;
        float w = (k < 256) ? W2l[(size_t)k * 128 + n] : W2r[(size_t)(k - 256) * 128 + n];
        g_w2[i] = __float2half(w);
    }
    if (i < 256 * 128) {
        int n = i >> 7, k = i & 127;
        float w = (n < 128) ? Wc1[(size_t)k * 128 + n] : Wc1[(size_t)(128 + k) * 128 + (n - 128)];
        g_wuv[i] = __float2half(w);
    }
    if (i < 256 * 64) {
        int n = i >> 6, k = i & 63;
        float w = 0.f;
        if (k < 24) w = W1l[(size_t)k * 256 + n];
        else if (k < 48) w = W1r[(size_t)(k - 24) * 256 + n];
        g_w1[i] = __float2half(w);
    }
}

// ---------------- degree count (both directions) ----------------
__global__ void k_count(const int* __restrict__ ei) {
    int e = blockIdx.x * blockDim.x + threadIdx.x;
    if (e >= E_EDGES) return;
    atomicAdd(&g_degs[ei[e]], 1);
    atomicAdd(&g_degd[ei[E_EDGES + e]], 1);
}

// ---------------- dual scan: blockIdx.x = 0 (dst-CSR) / 1 (src-CSR), int4 vectorized ----------------
__global__ void k_scan2() {
    int which = blockIdx.x;
    const int* deg = which ? g_degs : g_degd;
    int* off = which ? g_offs : g_off;
    const int CH = 52;      // 1024 * 52 = 53248 = NPAD, 16B-aligned chunks
    int tid = threadIdx.x, lane = tid & 31, wid = tid >> 5;
    int beg = tid * CH;
    int sum = 0;
#pragma unroll
    for (int i = 0; i < CH; i += 4) {
        int4 v = *(const int4*)(deg + beg + i);
        sum += v.x + v.y + v.z + v.w;
    }
    int v = sum;
#pragma unroll
    for (int o = 1; o < 32; o <<= 1) {
        int t = __shfl_up_sync(0xFFFFFFFFu, v, o);
        if (lane >= o) v += t;
    }
    __shared__ int wsum[32];
    if (lane == 31) wsum[wid] = v;
    __syncthreads();
    if (wid == 0) {
        int w = wsum[lane];
#pragma unroll
        for (int o = 1; o < 32; o <<= 1) {
            int t = __shfl_up_sync(0xFFFFFFFFu, w, o);
            if (lane >= o) w += t;
        }
        wsum[lane] = w;
    }
    __syncthreads();
    int base = v - sum + (wid ? wsum[wid - 1] : 0);
#pragma unroll
    for (int i = 0; i < CH; i += 4) {
        int4 d = *(const int4*)(deg + beg + i);
        int4 o;
        o.x = base;
        o.y = o.x + d.x;
        o.z = o.y + d.y;
        o.w = o.z + d.z;
        base = o.w + d.w;
        *(int4*)(off + beg + i) = o;
    }
    // padding degrees are zero, so off[N_NODES] (== total) was already written correctly
}

// ---------------- scatter both CSRs (action packed into csrc high bits) ----------------
__global__ void k_scatter2(const int* __restrict__ ei, const int* __restrict__ ef) {
    int e = blockIdx.x * blockDim.x + threadIdx.x;
    if (e >= E_EDGES) return;
    int s = ei[e], d = ei[E_EDGES + e];
    int t = ef[2 * e], a = ef[2 * e + 1];
    int posd = g_off[d] + atomicAdd(&g_curd[d], 1);
    g_csrc[posd] = s | (a << 20);
    int poss = g_offs[s] + atomicAdd(&g_curs[s], 1);
    g_strig[poss] = t;
}

// ---------------- h0 build: x copy + trigger/action gather-reduce (no atomics) ----------------
__global__ void k_h0build(const float* __restrict__ x,
                          const float* __restrict__ embT, const float* __restrict__ embA) {
    int n = blockIdx.x * blockDim.x + threadIdx.x;
    if (n >= N_NODES) return;
    float* h0 = g_h0 + (size_t)n * 24;
    const float4* xp = (const float4*)(x + (size_t)n * 16);
#pragma unroll
    for (int j = 0; j < 4; j++) ((float4*)h0)[j] = xp[j];
    float4 trig = make_float4(0, 0, 0, 0);
    int b0 = g_offs[n], e0 = g_offs[n + 1];
    for (int e = b0; e < e0; e++) {
        int t = g_strig[e];
        float4 v = *(const float4*)(embT + (size_t)t * 4);
        trig.x += v.x; trig.y += v.y; trig.z += v.z; trig.w += v.w;
    }
    float4 act = make_float4(0, 0, 0, 0);
    int b1 = g_off[n], e1 = g_off[n + 1];
    for (int e = b1; e < e1; e++) {
        int a = g_csrc[e] >> 20;
        float4 v = *(const float4*)(embA + (size_t)a * 4);
        act.x += v.x; act.y += v.y; act.z += v.z; act.w += v.w;
    }
    ((float4*)h0)[4] = trig;
    ((float4*)h0)[5] = act;
}

// ---------------- layer-1 aggregation in 24-dim space (warp per node, 2-way unroll) ----------------
__global__ void k_agg24() {
    int w = (blockIdx.x * blockDim.x + threadIdx.x) >> 5;
    int lane = threadIdx.x & 31;
    if (w >= N_NODES) return;
    int beg = g_off[w], end = g_off[w + 1];
    if (lane < 24) {
        float acc0 = 0.f, acc1 = 0.f;
        int e = beg;
        for (; e + 1 < end; e += 2) {
            int s0 = g_csrc[e] & 0xFFFFF;
            int s1 = g_csrc[e + 1] & 0xFFFFF;
            acc0 += g_h0[s0 * 24 + lane];
            acc1 += g_h0[s1 * 24 + lane];
        }
        if (e < end) acc0 += g_h0[(g_csrc[e] & 0xFFFFF) * 24 + lane];
        float inv = 1.f / fmaxf((float)(end - beg), 1.f);
        g_agg24[w * 24 + lane] = (acc0 + acc1) * inv;
    }
}

// =====================================================================================
// k_gemm1_mma: h1 = relu([agg24|h0] @ [W1l;W1r] + b1) via fp16x2 mma.sync
// =====================================================================================
#define G1_SA_H 0
#define G1_SA_L 16384
#define G1_SB   32768
#define G1_SMEM 65536

__global__ __launch_bounds__(256, 1)
void k_gemm1_mma(const float* __restrict__ b1) {
    extern __shared__ char smem[];
    uint32_t sb = smem_u32(smem);
    int tid = threadIdx.x, wid = tid >> 5, lane = tid & 31;
    int r0 = blockIdx.x * 128;

    {
        int m = tid >> 1, h = tid & 1;
        int node = min(r0 + m, N_NODES - 1);
        const float* a24 = g_agg24 + (size_t)node * 24;
        const float* h0p = g_h0 + (size_t)node * 24;
#pragma unroll
        for (int kk = 0; kk < 32; kk += 8) {
            float z[8];
#pragma unroll
            for (int j = 0; j < 8; j++) {
                int k = h * 32 + kk + j;
                z[j] = (k < 24) ? a24[k] : ((k < 48) ? h0p[k - 24] : 0.f);
            }
            uint32_t hw[4], lw[4];
            split8h(z, hw, lw);
            int c = h * 4 + (kk >> 3);
            uint32_t off = (uint32_t)m * 128 + (uint32_t)((c ^ (m & 7)) << 4);
            *(uint4*)(smem + G1_SA_H + off) = make_uint4(hw[0], hw[1], hw[2], hw[3]);
            *(uint4*)(smem + G1_SA_L + off) = make_uint4(lw[0], lw[1], lw[2], lw[3]);
        }
    }
    {
        int n = tid;
        const __half* src = g_w1 + (size_t)n * 64;
#pragma unroll
        for (int c = 0; c < 8; c++) {
            uint32_t off = (uint32_t)n * 128 + (uint32_t)((c ^ (n & 7)) << 4);
            *(uint4*)(smem + G1_SB + off) = *(const uint4*)(src + c * 8);
        }
    }
    __syncthreads();

    uint32_t Ah[16], Al[16];
    {
        int rowA = wid * 16 + (lane & 15);
        uint32_t rbase = (uint32_t)rowA * 128;
        int rx = rowA & 7;
        int csel = lane >> 4;
#pragma unroll
        for (int ks = 0; ks < 4; ks++) {
            int c = ks * 2 + csel;
            uint32_t addr = sb + rbase + (uint32_t)((c ^ rx) << 4);
            ldm_x4(&Ah[ks * 4], addr + G1_SA_H);
            ldm_x4(&Al[ks * 4], addr + G1_SA_L);
        }
    }

    int row0 = r0 + wid * 16 + (lane >> 2);
    int row1 = row0 + 8;
#pragma unroll
    for (int nt = 0; nt < 32; nt++) {
        uint32_t B[8];
        {
            int nrow = nt * 8 + (lane & 7);
            uint32_t rbase = (uint32_t)nrow * 128;
            int rx = nrow & 7;
            int csel = lane >> 3;
#pragma unroll
            for (int kp = 0; kp < 2; kp++) {
                int c = kp * 4 + csel;
                ldm_x4(&B[kp * 4], sb + G1_SB + rbase + (uint32_t)((c ^ rx) << 4));
            }
        }
        float accE[4] = {0, 0, 0, 0}, accO[4] = {0, 0, 0, 0};
#pragma unroll
        for (int ks = 0; ks < 4; ks++) {
            mma_f16((ks & 1) ? accO : accE, &Ah[ks * 4], &B[ks * 2]);
            mma_f16((ks & 1) ? accO : accE, &Al[ks * 4], &B[ks * 2]);
        }
        int col = nt * 8 + ((lane & 3) << 1);
        float bx = b1[col], by = b1[col + 1];
        if (row0 < N_NODES) {
            float2 o = {fmaxf(accE[0] + accO[0] + bx, 0.f), fmaxf(accE[1] + accO[1] + by, 0.f)};
            *(float2*)(g_h1 + (size_t)row0 * 256 + col) = o;
        }
        if (row1 < N_NODES) {
            float2 o = {fmaxf(accE[2] + accO[2] + bx, 0.f), fmaxf(accE[3] + accO[3] + by, 0.f)};
            *(float2*)(g_h1 + (size_t)row1 * 256 + col) = o;
        }
    }
}

// ---------------- layer-2 aggregation: 256-dim gather-reduce (warp per node, 2-way unroll) ----------------
__global__ void k_agg256() {
    int w = (blockIdx.x * blockDim.x + threadIdx.x) >> 5;
    int lane = threadIdx.x & 31;
    if (w >= N_NODES) return;
    int beg = g_off[w], end = g_off[w + 1];
    float4 a0 = make_float4(0, 0, 0, 0), a1 = a0;
    float4 b0 = make_float4(0, 0, 0, 0), b1 = b0;
    int e = beg;
    for (; e + 1 < end; e += 2) {
        int s0 = g_csrc[e] & 0xFFFFF;
        int s1 = g_csrc[e + 1] & 0xFFFFF;
        const float4* p0 = (const float4*)(g_h1 + (size_t)s0 * 256 + lane * 8);
        const float4* p1 = (const float4*)(g_h1 + (size_t)s1 * 256 + lane * 8);
        float4 x0 = p0[0], x1 = p0[1], y0 = p1[0], y1 = p1[1];
        a0.x += x0.x; a0.y += x0.y; a0.z += x0.z; a0.w += x0.w;
        a1.x += x1.x; a1.y += x1.y; a1.z += x1.z; a1.w += x1.w;
        b0.x += y0.x; b0.y += y0.y; b0.z += y0.z; b0.w += y0.w;
        b1.x += y1.x; b1.y += y1.y; b1.z += y1.z; b1.w += y1.w;
    }
    if (e < end) {
        int s0 = g_csrc[e] & 0xFFFFF;
        const float4* p0 = (const float4*)(g_h1 + (size_t)s0 * 256 + lane * 8);
        float4 x0 = p0[0], x1 = p0[1];
        a0.x += x0.x; a0.y += x0.y; a0.z += x0.z; a0.w += x0.w;
        a1.x += x1.x; a1.y += x1.y; a1.z += x1.z; a1.w += x1.w;
    }
    a0.x += b0.x; a0.y += b0.y; a0.z += b0.z; a0.w += b0.w;
    a1.x += b1.x; a1.y += b1.y; a1.z += b1.z; a1.w += b1.w;
    float inv = 1.f / fmaxf((float)(end - beg), 1.f);
    a0.x *= inv; a0.y *= inv; a0.z *= inv; a0.w *= inv;
    a1.x *= inv; a1.y *= inv; a1.z *= inv; a1.w *= inv;
    float4* q = (float4*)(g_agg256 + (size_t)w * 256 + lane * 8);
    q[0] = a0; q[1] = a1;
}

// =====================================================================================
// k_gemm2uv_mma: FUSED  h2 = relu([agg256|h1]@[W2l;W2r]+b2);  uv = h2 @ Wuv  (fp16x2)
// =====================================================================================
#define F_SA_H   0
#define F_SA_L   32768
#define F_SB     65536
#define F_A2_H   0
#define F_A2_L   32768
#define F_BUV    65536
#define F_SMEM   131072

__global__ __launch_bounds__(256, 1)
void k_gemm2uv_mma(const float* __restrict__ b2) {
    extern __shared__ char smem[];
    uint32_t sb = smem_u32(smem);
    int tid = threadIdx.x, wid = tid >> 5, lane = tid & 31;
    int r0 = blockIdx.x * 128;

    float acc[16][4];
#pragma unroll
    for (int nt = 0; nt < 16; nt++)
#pragma unroll
        for (int j = 0; j < 4; j++) acc[nt][j] = 0.f;

    for (int kc = 0; kc < 4; kc++) {
        if (kc) __syncthreads();
        {
            int m = tid >> 1, h = tid & 1;
            int node = min(r0 + m, N_NODES - 1);
            const float* src = ((kc < 2) ? (g_agg256 + (size_t)node * 256 + kc * 128)
                                         : (g_h1 + (size_t)node * 256 + (kc - 2) * 128)) + h * 64;
#pragma unroll
            for (int kk = 0; kk < 64; kk += 8) {
                float z[8];
                *(float4*)(z) = *(const float4*)(src + kk);
                *(float4*)(z + 4) = *(const float4*)(src + kk + 4);
                uint32_t hw[4], lw[4];
                split8h(z, hw, lw);
                int chunk = h * 8 + (kk >> 3);
                uint32_t off = (uint32_t)m * 256 + (uint32_t)((chunk ^ (m & 7)) << 4);
                *(uint4*)(smem + F_SA_H + off) = make_uint4(hw[0], hw[1], hw[2], hw[3]);
                *(uint4*)(smem + F_SA_L + off) = make_uint4(lw[0], lw[1], lw[2], lw[3]);
            }
        }
        {
            int n = tid >> 1, h = tid & 1;
            const __half* src = g_w2 + (size_t)n * 512 + kc * 128 + h * 64;
#pragma unroll
            for (int c = 0; c < 8; c++) {
                int chunk = h * 8 + c;
                uint32_t off = (uint32_t)n * 256 + (uint32_t)((chunk ^ (n & 7)) << 4);
                *(uint4*)(smem + F_SB + off) = *(const uint4*)(src + c * 8);
            }
        }
        __syncthreads();

        uint32_t Ah[32], Al[32];
        {
            int rowA = wid * 16 + (lane & 15);
            uint32_t rbase = (uint32_t)rowA * 256;
            int rx = rowA & 7;
            int csel = lane >> 4;
#pragma unroll
            for (int ks = 0; ks < 8; ks++) {
                int chunk = ks * 2 + csel;
                uint32_t addr = sb + rbase + (uint32_t)((chunk ^ rx) << 4);
                ldm_x4(&Ah[ks * 4], addr + F_SA_H);
                ldm_x4(&Al[ks * 4], addr + F_SA_L);
            }
        }
#pragma unroll
        for (int nt = 0; nt < 16; nt++) {
            uint32_t B[16];
            {
                int nrow = nt * 8 + (lane & 7);
                uint32_t rbase = (uint32_t)nrow * 256;
                int rx = nrow & 7;
                int csel = lane >> 3;
#pragma unroll
                for (int kp = 0; kp < 4; kp++) {
                    int chunk = kp * 4 + csel;
                    ldm_x4(&B[kp * 4], sb + F_SB + rbase + (uint32_t)((chunk ^ rx) << 4));
                }
            }
            float accE[4] = {0, 0, 0, 0}, accO[4] = {0, 0, 0, 0};
#pragma unroll
            for (int ks = 0; ks < 8; ks++) {
                mma_f16((ks & 1) ? accO : accE, &Ah[ks * 4], &B[ks * 2]);
                mma_f16((ks & 1) ? accO : accE, &Al[ks * 4], &B[ks * 2]);
            }
#pragma unroll
            for (int j = 0; j < 4; j++) acc[nt][j] += accE[j] + accO[j];
        }
    }
    __syncthreads();

    {
        int n = tid;
        const __half* src = g_wuv + (size_t)n * 128;
#pragma unroll
        for (int c = 0; c < 16; c++) {
            uint32_t off = (uint32_t)n * 256 + (uint32_t)((c ^ (n & 7)) << 4);
            *(uint4*)(smem + F_BUV + off) = *(const uint4*)(src + c * 8);
        }
    }
    {
        int rloc0 = wid * 16 + (lane >> 2);
        int rloc1 = rloc0 + 8;
        int rx0 = rloc0 & 7, rx1 = rloc1 & 7;
#pragma unroll
        for (int nt = 0; nt < 16; nt++) {
            int c = nt * 8 + ((lane & 3) << 1);
            float bx = b2[c], by = b2[c + 1];
            float v0x = fmaxf(acc[nt][0] + bx, 0.f), v0y = fmaxf(acc[nt][1] + by, 0.f);
            float v1x = fmaxf(acc[nt][2] + bx, 0.f), v1y = fmaxf(acc[nt][3] + by, 0.f);
            uint32_t hw, lw;
            uint32_t base0 = (uint32_t)rloc0 * 256 + (uint32_t)((((c >> 3) ^ rx0)) << 4) + (uint32_t)(c & 7) * 2;
            split2h(v0x, v0y, hw, lw);
            *(uint32_t*)(smem + F_A2_H + base0) = hw;
            *(uint32_t*)(smem + F_A2_L + base0) = lw;
            uint32_t base1 = (uint32_t)rloc1 * 256 + (uint32_t)((((c >> 3) ^ rx1)) << 4) + (uint32_t)(c & 7) * 2;
            split2h(v1x, v1y, hw, lw);
            *(uint32_t*)(smem + F_A2_H + base1) = hw;
            *(uint32_t*)(smem + F_A2_L + base1) = lw;
        }
    }
    __syncthreads();

    uint32_t Ah[32], Al[32];
    {
        int rowA = wid * 16 + (lane & 15);
        uint32_t rbase = (uint32_t)rowA * 256;
        int rx = rowA & 7;
        int csel = lane >> 4;
#pragma unroll
        for (int ks = 0; ks < 8; ks++) {
            int chunk = ks * 2 + csel;
            uint32_t addr = sb + rbase + (uint32_t)((chunk ^ rx) << 4);
            ldm_x4(&Ah[ks * 4], addr + F_A2_H);
            ldm_x4(&Al[ks * 4], addr + F_A2_L);
        }
    }
    int row0 = r0 + wid * 16 + (lane >> 2);
    int row1 = row0 + 8;
#pragma unroll
    for (int nt = 0; nt < 32; nt++) {
        uint32_t B[16];
        {
            int nrow = nt * 8 + (lane & 7);
            uint32_t rbase = (uint32_t)nrow * 256;
            int rx = nrow & 7;
            int csel = lane >> 3;
#pragma unroll
            for (int kp = 0; kp < 4; kp++) {
                int chunk = kp * 4 + csel;
                ldm_x4(&B[kp * 4], sb + F_BUV + rbase + (uint32_t)((chunk ^ rx) << 4));
            }
        }
        float accE[4] = {0, 0, 0, 0}, accO[4] = {0, 0, 0, 0};
#pragma unroll
        for (int ks = 0; ks < 8; ks++) {
            mma_f16((ks & 1) ? accO : accE, &Ah[ks * 4], &B[ks * 2]);
            mma_f16((ks & 1) ? accO : accE, &Al[ks * 4], &B[ks * 2]);
        }
        int col = nt * 8 + ((lane & 3) << 1);
        if (row0 < N_NODES) {
            float2 o = {accE[0] + accO[0], accE[1] + accO[1]};
            *(float2*)(g_uv + (size_t)row0 * 256 + col) = o;
        }
        if (row1 < N_NODES) {
            float2 o = {accE[2] + accO[2], accE[3] + accO[3]};
            *(float2*)(g_uv + (size_t)row1 * 256 + col) = o;
        }
    }
}

// =====================================================================================
// k_edge_mma: edge classifier, fp16x2 mma.sync; FULL B (552x128 fp16 = 141KB) in SMEM
// =====================================================================================
#define EM_M     128
#define SM_AH    0
#define SM_AL    32768
#define SM_B     65536
#define SM_EDGE_TOTAL (65536 + 552 * 256)   // 206848

__global__ __launch_bounds__(256, 1)
void k_edge_mma(const int* __restrict__ egt, const float* __restrict__ bc1,
                const float* __restrict__ bc2, float* __restrict__ out) {
    extern __shared__ char smem[];
    uint32_t sb = smem_u32(smem);
    int tid = threadIdx.x, wid = tid >> 5, lane = tid & 31;
    int e0 = blockIdx.x * EM_M;

    // async-load the full B (552 rows x 128 k fp16), overlapped with A prep
    for (int id = tid; id < 552 * 16; id += 256) {
        int n = id >> 4, c = id & 15;
        uint32_t dst = sb + SM_B + (uint32_t)n * 256 + (uint32_t)((c ^ (n & 7)) << 4);
        cp16(dst, g_wc2 + (size_t)n * 128 + c * 8);
    }
    CP_COMMIT();

    // A prep: z = relu(u[s]+v[d]+bc1) -> fp16 hi/lo
    {
        int m = tid >> 1, h = tid & 1;
        int er = e0 + m;
        int s = 0, d = 0;
        if (er < EGT) { s = egt[er]; d = egt[EGT + er]; }
        const float* up = g_uv + (size_t)s * 256 + h * 64;
        const float* vp = g_uv + (size_t)d * 256 + 128 + h * 64;
        const float* bp = bc1 + h * 64;
#pragma unroll
        for (int kk = 0; kk < 64; kk += 8) {
            float z[8];
#pragma unroll
            for (int j = 0; j < 8; j += 4) {
                float4 u4 = *(const float4*)(up + kk + j);
                float4 v4 = *(const float4*)(vp + kk + j);
                float4 b4 = *(const float4*)(bp + kk + j);
                z[j + 0] = fmaxf(u4.x + v4.x + b4.x, 0.f);
                z[j + 1] = fmaxf(u4.y + v4.y + b4.y, 0.f);
                z[j + 2] = fmaxf(u4.z + v4.z + b4.z, 0.f);
                z[j + 3] = fmaxf(u4.w + v4.w + b4.w, 0.f);
            }
            uint32_t hw[4], lw[4];
            split8h(z, hw, lw);
            int chunk = h * 8 + (kk >> 3);
            uint32_t off = (uint32_t)m * 256 + (uint32_t)((chunk ^ (m & 7)) << 4);
            *(uint4*)(smem + SM_AH + off) = make_uint4(hw[0], hw[1], hw[2], hw[3]);
            *(uint4*)(smem + SM_AL + off) = make_uint4(lw[0], lw[1], lw[2], lw[3]);
        }
    }
    CP_WAIT0();
    __syncthreads();   // A + B smem visible

    uint32_t Ah[32], Al[32];
    {
        int rowA = wid * 16 + (lane & 15);
        uint32_t rbase = (uint32_t)rowA * 256;
        int rx = rowA & 7;
        int csel = lane >> 4;
#pragma unroll
        for (int ks = 0; ks < 8; ks++) {
            int chunk = ks * 2 + csel;
            uint32_t addr = sb + rbase + (uint32_t)((chunk ^ rx) << 4);
            ldm_x4(&Ah[ks * 4], addr + SM_AH);
            ldm_x4(&Al[ks * 4], addr + SM_AL);
        }
    }

    int r0g = e0 + wid * 16 + (lane >> 2);
    bool v0 = r0g < EGT, v1 = (r0g + 8) < EGT;
    float* orow0 = out + (size_t)r0g * 552;
    float* orow1 = orow0 + 8 * 552;

    for (int jt = 0; jt < 69; jt++) {
        uint32_t B[16];
        {
            int nrow = jt * 8 + (lane & 7);
            uint32_t rbase = sb + SM_B + (uint32_t)nrow * 256;
            int rx = nrow & 7;
            int csel = lane >> 3;
#pragma unroll
            for (int kp = 0; kp < 4; kp++) {
                int chunk = kp * 4 + csel;
                ldm_x4(&B[kp * 4], rbase + (uint32_t)((chunk ^ rx) << 4));
            }
        }
        float accE[4] = {0, 0, 0, 0}, accO[4] = {0, 0, 0, 0};
#pragma unroll
        for (int ks = 0; ks < 8; ks++) {
            mma_f16((ks & 1) ? accO : accE, &Ah[ks * 4], &B[ks * 2]);
            mma_f16((ks & 1) ? accO : accE, &Al[ks * 4], &B[ks * 2]);
        }
        int col = jt * 8 + ((lane & 3) << 1);
        float bx = bc2[col], by = bc2[col + 1];
        if (v0) {
            float2 o0 = {sigf(accE[0] + accO[0] + bx), sigf(accE[1] + accO[1] + by)};
            *(float2*)(orow0 + col) = o0;
        }
        if (v1) {
            float2 o1 = {sigf(accE[2] + accO[2] + bx), sigf(accE[3] + accO[3] + by)};
            *(float2*)(orow1 + col) = o1;
        }
    }
}

// ---------------- launch ----------------
extern "C" void kernel_launch(void* const* d_in, const int* in_sizes, int n_in,
                              void* d_out, int out_size) {
    const float* x    = (const float*)d_in[0];
    const int*   ei   = (const int*)  d_in[1];
    const int*   egt  = (const int*)  d_in[2];
    const int*   ef   = (const int*)  d_in[3];
    const float* embT = (const float*)d_in[4];
    const float* embA = (const float*)d_in[5];
    const float* W1l  = (const float*)d_in[6];
    const float* W1r  = (const float*)d_in[7];
    const float* b1   = (const float*)d_in[8];
    const float* W2l  = (const float*)d_in[9];
    const float* W2r  = (const float*)d_in[10];
    const float* b2   = (const float*)d_in[11];
    const float* Wc1  = (const float*)d_in[12];
    const float* bc1  = (const float*)d_in[13];
    const float* Wc2  = (const float*)d_in[14];
    const float* bc2  = (const float*)d_in[15];
    float* out = (float*)d_out;

    cudaFuncSetAttribute(k_gemm1_mma, cudaFuncAttributeMaxDynamicSharedMemorySize, G1_SMEM);
    cudaFuncSetAttribute(k_gemm2uv_mma, cudaFuncAttributeMaxDynamicSharedMemorySize, F_SMEM);
    cudaFuncSetAttribute(k_edge_mma, cudaFuncAttributeMaxDynamicSharedMemorySize, SM_EDGE_TOTAL);

    k_prep<<<(552 * 128 + 255) / 256, 256>>>(Wc2, W2l, W2r, Wc1, W1l, W1r);
    k_count<<<(E_EDGES + 255) / 256, 256>>>(ei);
    k_scan2<<<2, 1024>>>();
    k_scatter2<<<(E_EDGES + 255) / 256, 256>>>(ei, ef);
    k_h0build<<<(N_NODES + 255) / 256, 256>>>(x, embT, embA);
    k_agg24<<<(N_NODES * 32 + 255) / 256, 256>>>();
    k_gemm1_mma<<<(N_NODES + 127) / 128, 256, G1_SMEM>>>(b1);
    k_agg256<<<(N_NODES * 32 + 255) / 256, 256>>>();
    k_gemm2uv_mma<<<(N_NODES + 127) / 128, 256, F_SMEM>>>(b2);
    k_edge_mma<<<(EGT + EM_M - 1) / EM_M, 256, SM_EDGE_TOTAL>>>(egt, bc1, bc2, out);
}

// round 9
// speedup vs baseline: 1.6112x; 1.3675x over previous
#include <cuda_runtime.h>
#include <cuda_fp16.h>
#include <cstdint>

#define N_NODES 50000
#define E_EDGES 800000
#define EGT     200000
#define NPAD    53248      // 1024 threads * 52 (CH), multiple of 4

// ---------------- scratch (static device globals; no allocation) ----------------
__device__ float g_h0[N_NODES * 24];        // [x(16) | agg_trigger(4) | agg_action(4)]
__device__ int   g_degd[NPAD];
__device__ int   g_degs[NPAD];
__device__ int   g_curd[N_NODES];
__device__ int   g_curs[N_NODES];
__device__ int   g_off[NPAD + 4];           // CSR by dst
__device__ int   g_offs[NPAD + 4];          // CSR by src
__device__ int   g_csrc[E_EDGES];           // per in-edge: src | (action<<20)
__device__ int   g_strig[E_EDGES];          // per out-edge: trigger code
__device__ float g_agg24[N_NODES * 24];
__device__ float g_h1[N_NODES * 256];
__device__ float g_agg256[N_NODES * 256];
__device__ float g_uv[N_NODES * 256];       // [u(128) | v(128)] per node
__device__ __half g_wc2[552 * 128];         // Wc2^T fp16, [n][k]
__device__ __half g_w2[128 * 512];          // [W2l;W2r]^T fp16, [n][k]
__device__ __half g_wuv[256 * 128];         // [Wc1_top|Wc1_bot]^T fp16, [n][k]
__device__ __half g_w1[256 * 64];           // [W1l;W1r]^T fp16, [n][k] (k padded 48->64)

// ======================= warp-MMA + async helpers (baseline PTX, sm_80+) =======================
__device__ __forceinline__ uint32_t smem_u32(const void* p) {
    uint32_t a;
    asm("{ .reg .u64 t; cvta.to.shared.u64 t, %1; cvt.u32.u64 %0, t; }" : "=r"(a) : "l"(p));
    return a;
}
__device__ __forceinline__ void ldm_x4(uint32_t* r, uint32_t addr) {
    asm volatile("ldmatrix.sync.aligned.m8n8.x4.shared.b16 {%0,%1,%2,%3}, [%4];"
        : "=r"(r[0]), "=r"(r[1]), "=r"(r[2]), "=r"(r[3]) : "r"(addr));
}
__device__ __forceinline__ void mma_f16(float* c, const uint32_t* a, const uint32_t* b) {
    asm volatile(
        "mma.sync.aligned.m16n8k16.row.col.f32.f16.f16.f32 "
        "{%0,%1,%2,%3}, {%4,%5,%6,%7}, {%8,%9}, {%0,%1,%2,%3};"
        : "+f"(c[0]), "+f"(c[1]), "+f"(c[2]), "+f"(c[3])
        : "r"(a[0]), "r"(a[1]), "r"(a[2]), "r"(a[3]), "r"(b[0]), "r"(b[1]));
}
__device__ __forceinline__ void cp16(uint32_t dst, const void* src) {
    asm volatile("cp.async.cg.shared.global [%0], [%1], 16;" :: "r"(dst), "l"(src));
}
#define CP_COMMIT() asm volatile("cp.async.commit_group;" ::: "memory")
#define CP_WAIT0()  asm volatile("cp.async.wait_group 0;" ::: "memory")
__device__ __forceinline__ float sigf(float x) { return __fdividef(1.f, 1.f + __expf(-x)); }

// split fp32 -> (hi, lo) fp16 pair words from 8 consecutive floats
__device__ __forceinline__ void split8h(const float* z, uint32_t* hw, uint32_t* lw) {
#pragma unroll
    for (int p = 0; p < 4; p++) {
        __half h0 = __float2half(z[2 * p]);
        __half h1 = __float2half(z[2 * p + 1]);
        __half l0 = __float2half(z[2 * p] - __half2float(h0));
        __half l1 = __float2half(z[2 * p + 1] - __half2float(h1));
        __half2 hh = __halves2half2(h0, h1), ll = __halves2half2(l0, l1);
        hw[p] = *reinterpret_cast<uint32_t*>(&hh);
        lw[p] = *reinterpret_cast<uint32_t*>(&ll);
    }
}
// pack 8 floats to fp16 (no split)
__device__ __forceinline__ void pack8h(const float* z, uint32_t* hw) {
#pragma unroll
    for (int p = 0; p < 4; p++) {
        __half2 hh = __halves2half2(__float2half(z[2 * p]), __float2half(z[2 * p + 1]));
        hw[p] = *reinterpret_cast<uint32_t*>(&hh);
    }
}
__device__ __forceinline__ void split2h(float x, float y, uint32_t& hw, uint32_t& lw) {
    __half h0 = __float2half(x);
    __half h1 = __float2half(y);
    __half l0 = __float2half(x - __half2float(h0));
    __half l1 = __float2half(y - __half2float(h1));
    __half2 hh = __halves2half2(h0, h1), ll = __halves2half2(l0, l1);
    hw = *reinterpret_cast<uint32_t*>(&hh);
    lw = *reinterpret_cast<uint32_t*>(&ll);
}

// ---------------- fused prep: zero counters (incl. padding) + weight transposes (fp16) ----------------
__global__ void k_prep(const float* __restrict__ Wc2, const float* __restrict__ W2l,
                       const float* __restrict__ W2r, const float* __restrict__ Wc1,
                       const float* __restrict__ W1l, const float* __restrict__ W1r) {
    int i = blockIdx.x * blockDim.x + threadIdx.x;
    if (i < NPAD) { g_degd[i] = 0; g_degs[i] = 0; }
    if (i < N_NODES) { g_curd[i] = 0; g_curs[i] = 0; }
    if (i < 552 * 128) {
        int n = i >> 7, k = i & 127;
        g_wc2[i] = __float2half(Wc2[(size_t)k * 552 + n]);
    }
    if (i < 128 * 512) {
        int n = i >> 9, k = i & 511;
        float w = (k < 256) ? W2l[(size_t)k * 128 + n] : W2r[(size_t)(k - 256) * 128 + n];
        g_w2[i] = __float2half(w);
    }
    if (i < 256 * 128) {
        int n = i >> 7, k = i & 127;
        float w = (n < 128) ? Wc1[(size_t)k * 128 + n] : Wc1[(size_t)(128 + k) * 128 + (n - 128)];
        g_wuv[i] = __float2half(w);
    }
    if (i < 256 * 64) {
        int n = i >> 6, k = i & 63;
        float w = 0.f;
        if (k < 24) w = W1l[(size_t)k * 256 + n];
        else if (k < 48) w = W1r[(size_t)(k - 24) * 256 + n];
        g_w1[i] = __float2half(w);
    }
}

// ---------------- degree count (both directions) ----------------
__global__ void k_count(const int* __restrict__ ei) {
    int e = blockIdx.x * blockDim.x + threadIdx.x;
    if (e >= E_EDGES) return;
    atomicAdd(&g_degs[ei[e]], 1);
    atomicAdd(&g_degd[ei[E_EDGES + e]], 1);
}

// ---------------- dual scan: blockIdx.x = 0 (dst-CSR) / 1 (src-CSR), int4 vectorized ----------------
__global__ void k_scan2() {
    int which = blockIdx.x;
    const int* deg = which ? g_degs : g_degd;
    int* off = which ? g_offs : g_off;
    const int CH = 52;
    int tid = threadIdx.x, lane = tid & 31, wid = tid >> 5;
    int beg = tid * CH;
    int sum = 0;
#pragma unroll
    for (int i = 0; i < CH; i += 4) {
        int4 v = *(const int4*)(deg + beg + i);
        sum += v.x + v.y + v.z + v.w;
    }
    int v = sum;
#pragma unroll
    for (int o = 1; o < 32; o <<= 1) {
        int t = __shfl_up_sync(0xFFFFFFFFu, v, o);
        if (lane >= o) v += t;
    }
    __shared__ int wsum[32];
    if (lane == 31) wsum[wid] = v;
    __syncthreads();
    if (wid == 0) {
        int w = wsum[lane];
#pragma unroll
        for (int o = 1; o < 32; o <<= 1) {
            int t = __shfl_up_sync(0xFFFFFFFFu, w, o);
            if (lane >= o) w += t;
        }
        wsum[lane] = w;
    }
    __syncthreads();
    int base = v - sum + (wid ? wsum[wid - 1] : 0);
#pragma unroll
    for (int i = 0; i < CH; i += 4) {
        int4 d = *(const int4*)(deg + beg + i);
        int4 o;
        o.x = base;
        o.y = o.x + d.x;
        o.z = o.y + d.y;
        o.w = o.z + d.z;
        base = o.w + d.w;
        *(int4*)(off + beg + i) = o;
    }
}

// ---------------- scatter both CSRs (action packed into csrc high bits) ----------------
__global__ void k_scatter2(const int* __restrict__ ei, const int* __restrict__ ef) {
    int e = blockIdx.x * blockDim.x + threadIdx.x;
    if (e >= E_EDGES) return;
    int s = ei[e], d = ei[E_EDGES + e];
    int t = ef[2 * e], a = ef[2 * e + 1];
    int posd = g_off[d] + atomicAdd(&g_curd[d], 1);
    g_csrc[posd] = s | (a << 20);
    int poss = g_offs[s] + atomicAdd(&g_curs[s], 1);
    g_strig[poss] = t;
}

// ---------------- h0 build: x copy + trigger/action gather-reduce (no atomics) ----------------
__global__ void k_h0build(const float* __restrict__ x,
                          const float* __restrict__ embT, const float* __restrict__ embA) {
    int n = blockIdx.x * blockDim.x + threadIdx.x;
    if (n >= N_NODES) return;
    float* h0 = g_h0 + (size_t)n * 24;
    const float4* xp = (const float4*)(x + (size_t)n * 16);
#pragma unroll
    for (int j = 0; j < 4; j++) ((float4*)h0)[j] = xp[j];
    float4 trig = make_float4(0, 0, 0, 0);
    int b0 = g_offs[n], e0 = g_offs[n + 1];
    for (int e = b0; e < e0; e++) {
        int t = g_strig[e];
        float4 v = *(const float4*)(embT + (size_t)t * 4);
        trig.x += v.x; trig.y += v.y; trig.z += v.z; trig.w += v.w;
    }
    float4 act = make_float4(0, 0, 0, 0);
    int b1 = g_off[n], e1 = g_off[n + 1];
    for (int e = b1; e < e1; e++) {
        int a = g_csrc[e] >> 20;
        float4 v = *(const float4*)(embA + (size_t)a * 4);
        act.x += v.x; act.y += v.y; act.z += v.z; act.w += v.w;
    }
    ((float4*)h0)[4] = trig;
    ((float4*)h0)[5] = act;
}

// ---------------- layer-1 aggregation in 24-dim space (warp per node, 2-way unroll) ----------------
__global__ void k_agg24() {
    int w = (blockIdx.x * blockDim.x + threadIdx.x) >> 5;
    int lane = threadIdx.x & 31;
    if (w >= N_NODES) return;
    int beg = g_off[w], end = g_off[w + 1];
    if (lane < 24) {
        float acc0 = 0.f, acc1 = 0.f;
        int e = beg;
        for (; e + 1 < end; e += 2) {
            int s0 = g_csrc[e] & 0xFFFFF;
            int s1 = g_csrc[e + 1] & 0xFFFFF;
            acc0 += g_h0[s0 * 24 + lane];
            acc1 += g_h0[s1 * 24 + lane];
        }
        if (e < end) acc0 += g_h0[(g_csrc[e] & 0xFFFFF) * 24 + lane];
        float inv = 1.f / fmaxf((float)(end - beg), 1.f);
        g_agg24[w * 24 + lane] = (acc0 + acc1) * inv;
    }
}

// =====================================================================================
// k_gemm1_mma: h1 = relu([agg24|h0] @ [W1l;W1r] + b1) via fp16x2 mma.sync
// =====================================================================================
#define G1_SA_H 0
#define G1_SA_L 16384
#define G1_SB   32768
#define G1_SMEM 65536

__global__ __launch_bounds__(256, 1)
void k_gemm1_mma(const float* __restrict__ b1) {
    extern __shared__ char smem[];
    uint32_t sb = smem_u32(smem);
    int tid = threadIdx.x, wid = tid >> 5, lane = tid & 31;
    int r0 = blockIdx.x * 128;

    {
        int m = tid >> 1, h = tid & 1;
        int node = min(r0 + m, N_NODES - 1);
        const float* a24 = g_agg24 + (size_t)node * 24;
        const float* h0p = g_h0 + (size_t)node * 24;
#pragma unroll
        for (int kk = 0; kk < 32; kk += 8) {
            float z[8];
#pragma unroll
            for (int j = 0; j < 8; j++) {
                int k = h * 32 + kk + j;
                z[j] = (k < 24) ? a24[k] : ((k < 48) ? h0p[k - 24] : 0.f);
            }
            uint32_t hw[4], lw[4];
            split8h(z, hw, lw);
            int c = h * 4 + (kk >> 3);
            uint32_t off = (uint32_t)m * 128 + (uint32_t)((c ^ (m & 7)) << 4);
            *(uint4*)(smem + G1_SA_H + off) = make_uint4(hw[0], hw[1], hw[2], hw[3]);
            *(uint4*)(smem + G1_SA_L + off) = make_uint4(lw[0], lw[1], lw[2], lw[3]);
        }
    }
    {
        int n = tid;
        const __half* src = g_w1 + (size_t)n * 64;
#pragma unroll
        for (int c = 0; c < 8; c++) {
            uint32_t off = (uint32_t)n * 128 + (uint32_t)((c ^ (n & 7)) << 4);
            *(uint4*)(smem + G1_SB + off) = *(const uint4*)(src + c * 8);
        }
    }
    __syncthreads();

    uint32_t Ah[16], Al[16];
    {
        int rowA = wid * 16 + (lane & 15);
        uint32_t rbase = (uint32_t)rowA * 128;
        int rx = rowA & 7;
        int csel = lane >> 4;
#pragma unroll
        for (int ks = 0; ks < 4; ks++) {
            int c = ks * 2 + csel;
            uint32_t addr = sb + rbase + (uint32_t)((c ^ rx) << 4);
            ldm_x4(&Ah[ks * 4], addr + G1_SA_H);
            ldm_x4(&Al[ks * 4], addr + G1_SA_L);
        }
    }

    int row0 = r0 + wid * 16 + (lane >> 2);
    int row1 = row0 + 8;
#pragma unroll
    for (int nt = 0; nt < 32; nt++) {
        uint32_t B[8];
        {
            int nrow = nt * 8 + (lane & 7);
            uint32_t rbase = (uint32_t)nrow * 128;
            int rx = nrow & 7;
            int csel = lane >> 3;
#pragma unroll
            for (int kp = 0; kp < 2; kp++) {
                int c = kp * 4 + csel;
                ldm_x4(&B[kp * 4], sb + G1_SB + rbase + (uint32_t)((c ^ rx) << 4));
            }
        }
        float accE[4] = {0, 0, 0, 0}, accO[4] = {0, 0, 0, 0};
#pragma unroll
        for (int ks = 0; ks < 4; ks++) {
            mma_f16((ks & 1) ? accO : accE, &Ah[ks * 4], &B[ks * 2]);
            mma_f16((ks & 1) ? accO : accE, &Al[ks * 4], &B[ks * 2]);
        }
        int col = nt * 8 + ((lane & 3) << 1);
        float bx = b1[col], by = b1[col + 1];
        if (row0 < N_NODES) {
            float2 o = {fmaxf(accE[0] + accO[0] + bx, 0.f), fmaxf(accE[1] + accO[1] + by, 0.f)};
            *(float2*)(g_h1 + (size_t)row0 * 256 + col) = o;
        }
        if (row1 < N_NODES) {
            float2 o = {fmaxf(accE[2] + accO[2] + bx, 0.f), fmaxf(accE[3] + accO[3] + by, 0.f)};
            *(float2*)(g_h1 + (size_t)row1 * 256 + col) = o;
        }
    }
}

// ---------------- layer-2 aggregation: 256-dim gather-reduce (warp per node, 2-way unroll) ----------------
__global__ void k_agg256() {
    int w = (blockIdx.x * blockDim.x + threadIdx.x) >> 5;
    int lane = threadIdx.x & 31;
    if (w >= N_NODES) return;
    int beg = g_off[w], end = g_off[w + 1];
    float4 a0 = make_float4(0, 0, 0, 0), a1 = a0;
    float4 b0 = make_float4(0, 0, 0, 0), b1 = b0;
    int e = beg;
    for (; e + 1 < end; e += 2) {
        int s0 = g_csrc[e] & 0xFFFFF;
        int s1 = g_csrc[e + 1] & 0xFFFFF;
        const float4* p0 = (const float4*)(g_h1 + (size_t)s0 * 256 + lane * 8);
        const float4* p1 = (const float4*)(g_h1 + (size_t)s1 * 256 + lane * 8);
        float4 x0 = p0[0], x1 = p0[1], y0 = p1[0], y1 = p1[1];
        a0.x += x0.x; a0.y += x0.y; a0.z += x0.z; a0.w += x0.w;
        a1.x += x1.x; a1.y += x1.y; a1.z += x1.z; a1.w += x1.w;
        b0.x += y0.x; b0.y += y0.y; b0.z += y0.z; b0.w += y0.w;
        b1.x += y1.x; b1.y += y1.y; b1.z += y1.z; b1.w += y1.w;
    }
    if (e < end) {
        int s0 = g_csrc[e] & 0xFFFFF;
        const float4* p0 = (const float4*)(g_h1 + (size_t)s0 * 256 + lane * 8);
        float4 x0 = p0[0], x1 = p0[1];
        a0.x += x0.x; a0.y += x0.y; a0.z += x0.z; a0.w += x0.w;
        a1.x += x1.x; a1.y += x1.y; a1.z += x1.z; a1.w += x1.w;
    }
    a0.x += b0.x; a0.y += b0.y; a0.z += b0.z; a0.w += b0.w;
    a1.x += b1.x; a1.y += b1.y; a1.z += b1.z; a1.w += b1.w;
    float inv = 1.f / fmaxf((float)(end - beg), 1.f);
    a0.x *= inv; a0.y *= inv; a0.z *= inv; a0.w *= inv;
    a1.x *= inv; a1.y *= inv; a1.z *= inv; a1.w *= inv;
    float4* q = (float4*)(g_agg256 + (size_t)w * 256 + lane * 8);
    q[0] = a0; q[1] = a1;
}

// =====================================================================================
// k_gemm2uv_mma: FUSED  h2 = relu([agg256|h1]@[W2l;W2r]+b2);  uv = h2 @ Wuv  (fp16x2)
// =====================================================================================
#define F_SA_H   0
#define F_SA_L   32768
#define F_SB     65536
#define F_A2_H   0
#define F_A2_L   32768
#define F_BUV    65536
#define F_SMEM   131072

__global__ __launch_bounds__(256, 1)
void k_gemm2uv_mma(const float* __restrict__ b2) {
    extern __shared__ char smem[];
    uint32_t sb = smem_u32(smem);
    int tid = threadIdx.x, wid = tid >> 5, lane = tid & 31;
    int r0 = blockIdx.x * 128;

    float acc[16][4];
#pragma unroll
    for (int nt = 0; nt < 16; nt++)
#pragma unroll
        for (int j = 0; j < 4; j++) acc[nt][j] = 0.f;

    for (int kc = 0; kc < 4; kc++) {
        if (kc) __syncthreads();
        {
            int m = tid >> 1, h = tid & 1;
            int node = min(r0 + m, N_NODES - 1);
            const float* src = ((kc < 2) ? (g_agg256 + (size_t)node * 256 + kc * 128)
                                         : (g_h1 + (size_t)node * 256 + (kc - 2) * 128)) + h * 64;
#pragma unroll
            for (int kk = 0; kk < 64; kk += 8) {
                float z[8];
                *(float4*)(z) = *(const float4*)(src + kk);
                *(float4*)(z + 4) = *(const float4*)(src + kk + 4);
                uint32_t hw[4], lw[4];
                split8h(z, hw, lw);
                int chunk = h * 8 + (kk >> 3);
                uint32_t off = (uint32_t)m * 256 + (uint32_t)((chunk ^ (m & 7)) << 4);
                *(uint4*)(smem + F_SA_H + off) = make_uint4(hw[0], hw[1], hw[2], hw[3]);
                *(uint4*)(smem + F_SA_L + off) = make_uint4(lw[0], lw[1], lw[2], lw[3]);
            }
        }
        {
            int n = tid >> 1, h = tid & 1;
            const __half* src = g_w2 + (size_t)n * 512 + kc * 128 + h * 64;
#pragma unroll
            for (int c = 0; c < 8; c++) {
                int chunk = h * 8 + c;
                uint32_t off = (uint32_t)n * 256 + (uint32_t)((chunk ^ (n & 7)) << 4);
                *(uint4*)(smem + F_SB + off) = *(const uint4*)(src + c * 8);
            }
        }
        __syncthreads();

        uint32_t Ah[32], Al[32];
        {
            int rowA = wid * 16 + (lane & 15);
            uint32_t rbase = (uint32_t)rowA * 256;
            int rx = rowA & 7;
            int csel = lane >> 4;
#pragma unroll
            for (int ks = 0; ks < 8; ks++) {
                int chunk = ks * 2 + csel;
                uint32_t addr = sb + rbase + (uint32_t)((chunk ^ rx) << 4);
                ldm_x4(&Ah[ks * 4], addr + F_SA_H);
                ldm_x4(&Al[ks * 4], addr + F_SA_L);
            }
        }
#pragma unroll
        for (int nt = 0; nt < 16; nt++) {
            uint32_t B[16];
            {
                int nrow = nt * 8 + (lane & 7);
                uint32_t rbase = (uint32_t)nrow * 256;
                int rx = nrow & 7;
                int csel = lane >> 3;
#pragma unroll
                for (int kp = 0; kp < 4; kp++) {
                    int chunk = kp * 4 + csel;
                    ldm_x4(&B[kp * 4], sb + F_SB + rbase + (uint32_t)((chunk ^ rx) << 4));
                }
            }
            float accE[4] = {0, 0, 0, 0}, accO[4] = {0, 0, 0, 0};
#pragma unroll
            for (int ks = 0; ks < 8; ks++) {
                mma_f16((ks & 1) ? accO : accE, &Ah[ks * 4], &B[ks * 2]);
                mma_f16((ks & 1) ? accO : accE, &Al[ks * 4], &B[ks * 2]);
            }
#pragma unroll
            for (int j = 0; j < 4; j++) acc[nt][j] += accE[j] + accO[j];
        }
    }
    __syncthreads();

    {
        int n = tid;
        const __half* src = g_wuv + (size_t)n * 128;
#pragma unroll
        for (int c = 0; c < 16; c++) {
            uint32_t off = (uint32_t)n * 256 + (uint32_t)((c ^ (n & 7)) << 4);
            *(uint4*)(smem + F_BUV + off) = *(const uint4*)(src + c * 8);
        }
    }
    {
        int rloc0 = wid * 16 + (lane >> 2);
        int rloc1 = rloc0 + 8;
        int rx0 = rloc0 & 7, rx1 = rloc1 & 7;
#pragma unroll
        for (int nt = 0; nt < 16; nt++) {
            int c = nt * 8 + ((lane & 3) << 1);
            float bx = b2[c], by = b2[c + 1];
            float v0x = fmaxf(acc[nt][0] + bx, 0.f), v0y = fmaxf(acc[nt][1] + by, 0.f);
            float v1x = fmaxf(acc[nt][2] + bx, 0.f), v1y = fmaxf(acc[nt][3] + by, 0.f);
            uint32_t hw, lw;
            uint32_t base0 = (uint32_t)rloc0 * 256 + (uint32_t)((((c >> 3) ^ rx0)) << 4) + (uint32_t)(c & 7) * 2;
            split2h(v0x, v0y, hw, lw);
            *(uint32_t*)(smem + F_A2_H + base0) = hw;
            *(uint32_t*)(smem + F_A2_L + base0) = lw;
            uint32_t base1 = (uint32_t)rloc1 * 256 + (uint32_t)((((c >> 3) ^ rx1)) << 4) + (uint32_t)(c & 7) * 2;
            split2h(v1x, v1y, hw, lw);
            *(uint32_t*)(smem + F_A2_H + base1) = hw;
            *(uint32_t*)(smem + F_A2_L + base1) = lw;
        }
    }
    __syncthreads();

    uint32_t Ah[32], Al[32];
    {
        int rowA = wid * 16 + (lane & 15);
        uint32_t rbase = (uint32_t)rowA * 256;
        int rx = rowA & 7;
        int csel = lane >> 4;
#pragma unroll
        for (int ks = 0; ks < 8; ks++) {
            int chunk = ks * 2 + csel;
            uint32_t addr = sb + rbase + (uint32_t)((chunk ^ rx) << 4);
            ldm_x4(&Ah[ks * 4], addr + F_A2_H);
            ldm_x4(&Al[ks * 4], addr + F_A2_L);
        }
    }
    int row0 = r0 + wid * 16 + (lane >> 2);
    int row1 = row0 + 8;
#pragma unroll
    for (int nt = 0; nt < 32; nt++) {
        uint32_t B[16];
        {
            int nrow = nt * 8 + (lane & 7);
            uint32_t rbase = (uint32_t)nrow * 256;
            int rx = nrow & 7;
            int csel = lane >> 3;
#pragma unroll
            for (int kp = 0; kp < 4; kp++) {
                int chunk = kp * 4 + csel;
                ldm_x4(&B[kp * 4], sb + F_BUV + rbase + (uint32_t)((chunk ^ rx) << 4));
            }
        }
        float accE[4] = {0, 0, 0, 0}, accO[4] = {0, 0, 0, 0};
#pragma unroll
        for (int ks = 0; ks < 8; ks++) {
            mma_f16((ks & 1) ? accO : accE, &Ah[ks * 4], &B[ks * 2]);
            mma_f16((ks & 1) ? accO : accE, &Al[ks * 4], &B[ks * 2]);
        }
        int col = nt * 8 + ((lane & 3) << 1);
        if (row0 < N_NODES) {
            float2 o = {accE[0] + accO[0], accE[1] + accO[1]};
            *(float2*)(g_uv + (size_t)row0 * 256 + col) = o;
        }
        if (row1 < N_NODES) {
            float2 o = {accE[2] + accO[2], accE[3] + accO[3]};
            *(float2*)(g_uv + (size_t)row1 * 256 + col) = o;
        }
    }
}

// =====================================================================================
// k_edge_mma: edge classifier, SINGLE-fp16 A x fp16 B (8 MMAs/tile); full B in SMEM
// =====================================================================================
#define EM_M     128
#define SM_A     0
#define SM_B     32768
#define SM_EDGE_TOTAL (32768 + 552 * 256)   // 174080

__global__ __launch_bounds__(256, 1)
void k_edge_mma(const int* __restrict__ egt, const float* __restrict__ bc1,
                const float* __restrict__ bc2, float* __restrict__ out) {
    extern __shared__ char smem[];
    uint32_t sb = smem_u32(smem);
    int tid = threadIdx.x, wid = tid >> 5, lane = tid & 31;
    int e0 = blockIdx.x * EM_M;

    // async-load the full B (552 rows x 128 k fp16), overlapped with A prep
    for (int id = tid; id < 552 * 16; id += 256) {
        int n = id >> 4, c = id & 15;
        uint32_t dst = sb + SM_B + (uint32_t)n * 256 + (uint32_t)((c ^ (n & 7)) << 4);
        cp16(dst, g_wc2 + (size_t)n * 128 + c * 8);
    }
    CP_COMMIT();

    // A prep: z = relu(u[s]+v[d]+bc1) -> single fp16
    {
        int m = tid >> 1, h = tid & 1;
        int er = e0 + m;
        int s = 0, d = 0;
        if (er < EGT) { s = egt[er]; d = egt[EGT + er]; }
        const float* up = g_uv + (size_t)s * 256 + h * 64;
        const float* vp = g_uv + (size_t)d * 256 + 128 + h * 64;
        const float* bp = bc1 + h * 64;
#pragma unroll
        for (int kk = 0; kk < 64; kk += 8) {
            float z[8];
#pragma unroll
            for (int j = 0; j < 8; j += 4) {
                float4 u4 = *(const float4*)(up + kk + j);
                float4 v4 = *(const float4*)(vp + kk + j);
                float4 b4 = *(const float4*)(bp + kk + j);
                z[j + 0] = fmaxf(u4.x + v4.x + b4.x, 0.f);
                z[j + 1] = fmaxf(u4.y + v4.y + b4.y, 0.f);
                z[j + 2] = fmaxf(u4.z + v4.z + b4.z, 0.f);
                z[j + 3] = fmaxf(u4.w + v4.w + b4.w, 0.f);
            }
            uint32_t hw[4];
            pack8h(z, hw);
            int chunk = h * 8 + (kk >> 3);
            uint32_t off = (uint32_t)m * 256 + (uint32_t)((chunk ^ (m & 7)) << 4);
            *(uint4*)(smem + SM_A + off) = make_uint4(hw[0], hw[1], hw[2], hw[3]);
        }
    }
    CP_WAIT0();
    __syncthreads();   // A + B smem visible

    uint32_t Ah[32];
    {
        int rowA = wid * 16 + (lane & 15);
        uint32_t rbase = (uint32_t)rowA * 256;
        int rx = rowA & 7;
        int csel = lane >> 4;
#pragma unroll
        for (int ks = 0; ks < 8; ks++) {
            int chunk = ks * 2 + csel;
            ldm_x4(&Ah[ks * 4], sb + SM_A + rbase + (uint32_t)((chunk ^ rx) << 4));
        }
    }

    int r0g = e0 + wid * 16 + (lane >> 2);
    bool v0 = r0g < EGT, v1 = (r0g + 8) < EGT;
    float* orow0 = out + (size_t)r0g * 552;
    float* orow1 = orow0 + 8 * 552;

    for (int jt = 0; jt < 69; jt++) {
        uint32_t B[16];
        {
            int nrow = jt * 8 + (lane & 7);
            uint32_t rbase = sb + SM_B + (uint32_t)nrow * 256;
            int rx = nrow & 7;
            int csel = lane >> 3;
#pragma unroll
            for (int kp = 0; kp < 4; kp++) {
                int chunk = kp * 4 + csel;
                ldm_x4(&B[kp * 4], rbase + (uint32_t)((chunk ^ rx) << 4));
            }
        }
        float accE[4] = {0, 0, 0, 0}, accO[4] = {0, 0, 0, 0};
#pragma unroll
        for (int ks = 0; ks < 8; ks++)
            mma_f16((ks & 1) ? accO : accE, &Ah[ks * 4], &B[ks * 2]);

        int col = jt * 8 + ((lane & 3) << 1);
        float bx = bc2[col], by = bc2[col + 1];
        if (v0) {
            float2 o0 = {sigf(accE[0] + accO[0] + bx), sigf(accE[1] + accO[1] + by)};
            *(float2*)(orow0 + col) = o0;
        }
        if (v1) {
            float2 o1 = {sigf(accE[2] + accO[2] + bx), sigf(accE[3] + accO[3] + by)};
            *(float2*)(orow1 + col) = o1;
        }
    }
}

// ---------------- launch ----------------
extern "C" void kernel_launch(void* const* d_in, const int* in_sizes, int n_in,
                              void* d_out, int out_size) {
    const float* x    = (const float*)d_in[0];
    const int*   ei   = (const int*)  d_in[1];
    const int*   egt  = (const int*)  d_in[2];
    const int*   ef   = (const int*)  d_in[3];
    const float* embT = (const float*)d_in[4];
    const float* embA = (const float*)d_in[5];
    const float* W1l  = (const float*)d_in[6];
    const float* W1r  = (const float*)d_in[7];
    const float* b1   = (const float*)d_in[8];
    const float* W2l  = (const float*)d_in[9];
    const float* W2r  = (const float*)d_in[10];
    const float* b2   = (const float*)d_in[11];
    const float* Wc1  = (const float*)d_in[12];
    const float* bc1  = (const float*)d_in[13];
    const float* Wc2  = (const float*)d_in[14];
    const float* bc2  = (const float*)d_in[15];
    float* out = (float*)d_out;

    cudaFuncSetAttribute(k_gemm1_mma, cudaFuncAttributeMaxDynamicSharedMemorySize, G1_SMEM);
    cudaFuncSetAttribute(k_gemm2uv_mma, cudaFuncAttributeMaxDynamicSharedMemorySize, F_SMEM);
    cudaFuncSetAttribute(k_edge_mma, cudaFuncAttributeMaxDynamicSharedMemorySize, SM_EDGE_TOTAL);

    k_prep<<<(552 * 128 + 255) / 256, 256>>>(Wc2, W2l, W2r, Wc1, W1l, W1r);
    k_count<<<(E_EDGES + 255) / 256, 256>>>(ei);
    k_scan2<<<2, 1024>>>();
    k_scatter2<<<(E_EDGES + 255) / 256, 256>>>(ei, ef);
    k_h0build<<<(N_NODES + 255) / 256, 256>>>(x, embT, embA);
    k_agg24<<<(N_NODES * 32 + 255) / 256, 256>>>();
    k_gemm1_mma<<<(N_NODES + 127) / 128, 256, G1_SMEM>>>(b1);
    k_agg256<<<(N_NODES * 32 + 255) / 256, 256>>>();
    k_gemm2uv_mma<<<(N_NODES + 127) / 128, 256, F_SMEM>>>(b2);
    k_edge_mma<<<(EGT + EM_M - 1) / EM_M, 256, SM_EDGE_TOTAL>>>(egt, bc1, bc2, out);
}

// round 10
// speedup vs baseline: 1.6918x; 1.0500x over previous
#include <cuda_runtime.h>
#include <cuda_fp16.h>
#include <cstdint>

#define N_NODES 50000
#define E_EDGES 800000
#define EGT     200000
#define NPAD    53248      // 1024 threads * 52 (CH), multiple of 4

// ---------------- scratch (static device globals; no allocation) ----------------
__device__ float g_h0[N_NODES * 24];        // [x(16) | agg_trigger(4) | agg_action(4)]
__device__ int   g_degd[NPAD];
__device__ int   g_degs[NPAD];
__device__ int   g_curd[N_NODES];
__device__ int   g_curs[N_NODES];
__device__ int   g_off[NPAD + 4];           // CSR by dst
__device__ int   g_offs[NPAD + 4];          // CSR by src
__device__ int   g_csrc[E_EDGES];           // per in-edge: src | (action<<20)
__device__ int   g_strig[E_EDGES];          // per out-edge: trigger code
__device__ float g_agg24[N_NODES * 24];
__device__ float g_h1[N_NODES * 256];
__device__ float g_agg256[N_NODES * 256];
__device__ float g_uv[N_NODES * 256];       // [u(128) | v(128)] per node
__device__ __half g_wc2[552 * 128];         // Wc2^T fp16, [n][k]
__device__ __half g_w2[128 * 512];          // [W2l;W2r]^T fp16, [n][k]
__device__ __half g_wuv[256 * 128];         // [Wc1_top|Wc1_bot]^T fp16, [n][k]
__device__ __half g_w1[256 * 64];           // [W1l;W1r]^T fp16, [n][k] (k padded 48->64)

// ======================= warp-MMA + async helpers (baseline PTX, sm_80+) =======================
__device__ __forceinline__ uint32_t smem_u32(const void* p) {
    uint32_t a;
    asm("{ .reg .u64 t; cvta.to.shared.u64 t, %1; cvt.u32.u64 %0, t; }" : "=r"(a) : "l"(p));
    return a;
}
__device__ __forceinline__ void ldm_x4(uint32_t* r, uint32_t addr) {
    asm volatile("ldmatrix.sync.aligned.m8n8.x4.shared.b16 {%0,%1,%2,%3}, [%4];"
        : "=r"(r[0]), "=r"(r[1]), "=r"(r[2]), "=r"(r[3]) : "r"(addr));
}
__device__ __forceinline__ void mma_f16(float* c, const uint32_t* a, const uint32_t* b) {
    asm volatile(
        "mma.sync.aligned.m16n8k16.row.col.f32.f16.f16.f32 "
        "{%0,%1,%2,%3}, {%4,%5,%6,%7}, {%8,%9}, {%0,%1,%2,%3};"
        : "+f"(c[0]), "+f"(c[1]), "+f"(c[2]), "+f"(c[3])
        : "r"(a[0]), "r"(a[1]), "r"(a[2]), "r"(a[3]), "r"(b[0]), "r"(b[1]));
}
__device__ __forceinline__ void cp16(uint32_t dst, const void* src) {
    asm volatile("cp.async.cg.shared.global [%0], [%1], 16;" :: "r"(dst), "l"(src));
}
#define CP_COMMIT() asm volatile("cp.async.commit_group;" ::: "memory")
#define CP_WAIT0()  asm volatile("cp.async.wait_group 0;" ::: "memory")
__device__ __forceinline__ float sigf(float x) { return __fdividef(1.f, 1.f + __expf(-x)); }

// pack 8 floats to fp16 (no split)
__device__ __forceinline__ void pack8h(const float* z, uint32_t* hw) {
#pragma unroll
    for (int p = 0; p < 4; p++) {
        __half2 hh = __halves2half2(__float2half(z[2 * p]), __float2half(z[2 * p + 1]));
        hw[p] = *reinterpret_cast<uint32_t*>(&hh);
    }
}
__device__ __forceinline__ uint32_t pack2h(float x, float y) {
    __half2 hh = __halves2half2(__float2half(x), __float2half(y));
    return *reinterpret_cast<uint32_t*>(&hh);
}

// ---------------- fused prep: zero counters (incl. padding) + weight transposes (fp16) ----------------
__global__ void k_prep(const float* __restrict__ Wc2, const float* __restrict__ W2l,
                       const float* __restrict__ W2r, const float* __restrict__ Wc1,
                       const float* __restrict__ W1l, const float* __restrict__ W1r) {
    int i = blockIdx.x * blockDim.x + threadIdx.x;
    if (i < NPAD) { g_degd[i] = 0; g_degs[i] = 0; }
    if (i < N_NODES) { g_curd[i] = 0; g_curs[i] = 0; }
    if (i < 552 * 128) {
        int n = i >> 7, k = i & 127;
        g_wc2[i] = __float2half(Wc2[(size_t)k * 552 + n]);
    }
    if (i < 128 * 512) {
        int n = i >> 9, k = i & 511;
        float w = (k < 256) ? W2l[(size_t)k * 128 + n] : W2r[(size_t)(k - 256) * 128 + n];
        g_w2[i] = __float2half(w);
    }
    if (i < 256 * 128) {
        int n = i >> 7, k = i & 127;
        float w = (n < 128) ? Wc1[(size_t)k * 128 + n] : Wc1[(size_t)(128 + k) * 128 + (n - 128)];
        g_wuv[i] = __float2half(w);
    }
    if (i < 256 * 64) {
        int n = i >> 6, k = i & 63;
        float w = 0.f;
        if (k < 24) w = W1l[(size_t)k * 256 + n];
        else if (k < 48) w = W1r[(size_t)(k - 24) * 256 + n];
        g_w1[i] = __float2half(w);
    }
}

// ---------------- degree count (both directions) ----------------
__global__ void k_count(const int* __restrict__ ei) {
    int e = blockIdx.x * blockDim.x + threadIdx.x;
    if (e >= E_EDGES) return;
    atomicAdd(&g_degs[ei[e]], 1);
    atomicAdd(&g_degd[ei[E_EDGES + e]], 1);
}

// ---------------- dual scan: blockIdx.x = 0 (dst-CSR) / 1 (src-CSR), int4 vectorized ----------------
__global__ void k_scan2() {
    int which = blockIdx.x;
    const int* deg = which ? g_degs : g_degd;
    int* off = which ? g_offs : g_off;
    const int CH = 52;
    int tid = threadIdx.x, lane = tid & 31, wid = tid >> 5;
    int beg = tid * CH;
    int sum = 0;
#pragma unroll
    for (int i = 0; i < CH; i += 4) {
        int4 v = *(const int4*)(deg + beg + i);
        sum += v.x + v.y + v.z + v.w;
    }
    int v = sum;
#pragma unroll
    for (int o = 1; o < 32; o <<= 1) {
        int t = __shfl_up_sync(0xFFFFFFFFu, v, o);
        if (lane >= o) v += t;
    }
    __shared__ int wsum[32];
    if (lane == 31) wsum[wid] = v;
    __syncthreads();
    if (wid == 0) {
        int w = wsum[lane];
#pragma unroll
        for (int o = 1; o < 32; o <<= 1) {
            int t = __shfl_up_sync(0xFFFFFFFFu, w, o);
            if (lane >= o) w += t;
        }
        wsum[lane] = w;
    }
    __syncthreads();
    int base = v - sum + (wid ? wsum[wid - 1] : 0);
#pragma unroll
    for (int i = 0; i < CH; i += 4) {
        int4 d = *(const int4*)(deg + beg + i);
        int4 o;
        o.x = base;
        o.y = o.x + d.x;
        o.z = o.y + d.y;
        o.w = o.z + d.z;
        base = o.w + d.w;
        *(int4*)(off + beg + i) = o;
    }
}

// ---------------- scatter both CSRs (action packed into csrc high bits) ----------------
__global__ void k_scatter2(const int* __restrict__ ei, const int* __restrict__ ef) {
    int e = blockIdx.x * blockDim.x + threadIdx.x;
    if (e >= E_EDGES) return;
    int s = ei[e], d = ei[E_EDGES + e];
    int t = ef[2 * e], a = ef[2 * e + 1];
    int posd = g_off[d] + atomicAdd(&g_curd[d], 1);
    g_csrc[posd] = s | (a << 20);
    int poss = g_offs[s] + atomicAdd(&g_curs[s], 1);
    g_strig[poss] = t;
}

// ---------------- h0 build: x copy + trigger/action gather-reduce (no atomics) ----------------
__global__ void k_h0build(const float* __restrict__ x,
                          const float* __restrict__ embT, const float* __restrict__ embA) {
    int n = blockIdx.x * blockDim.x + threadIdx.x;
    if (n >= N_NODES) return;
    float* h0 = g_h0 + (size_t)n * 24;
    const float4* xp = (const float4*)(x + (size_t)n * 16);
#pragma unroll
    for (int j = 0; j < 4; j++) ((float4*)h0)[j] = xp[j];
    float4 trig = make_float4(0, 0, 0, 0);
    int b0 = g_offs[n], e0 = g_offs[n + 1];
    for (int e = b0; e < e0; e++) {
        int t = g_strig[e];
        float4 v = *(const float4*)(embT + (size_t)t * 4);
        trig.x += v.x; trig.y += v.y; trig.z += v.z; trig.w += v.w;
    }
    float4 act = make_float4(0, 0, 0, 0);
    int b1 = g_off[n], e1 = g_off[n + 1];
    for (int e = b1; e < e1; e++) {
        int a = g_csrc[e] >> 20;
        float4 v = *(const float4*)(embA + (size_t)a * 4);
        act.x += v.x; act.y += v.y; act.z += v.z; act.w += v.w;
    }
    ((float4*)h0)[4] = trig;
    ((float4*)h0)[5] = act;
}

// ---------------- layer-1 aggregation in 24-dim space (warp per node, 2-way unroll) ----------------
__global__ void k_agg24() {
    int w = (blockIdx.x * blockDim.x + threadIdx.x) >> 5;
    int lane = threadIdx.x & 31;
    if (w >= N_NODES) return;
    int beg = g_off[w], end = g_off[w + 1];
    if (lane < 24) {
        float acc0 = 0.f, acc1 = 0.f;
        int e = beg;
        for (; e + 1 < end; e += 2) {
            int s0 = g_csrc[e] & 0xFFFFF;
            int s1 = g_csrc[e + 1] & 0xFFFFF;
            acc0 += g_h0[s0 * 24 + lane];
            acc1 += g_h0[s1 * 24 + lane];
        }
        if (e < end) acc0 += g_h0[(g_csrc[e] & 0xFFFFF) * 24 + lane];
        float inv = 1.f / fmaxf((float)(end - beg), 1.f);
        g_agg24[w * 24 + lane] = (acc0 + acc1) * inv;
    }
}

// =====================================================================================
// k_gemm1_mma: h1 = relu([agg24|h0] @ [W1l;W1r] + b1), single-fp16 A x fp16 B
// =====================================================================================
#define G1_SA   0
#define G1_SB   16384
#define G1_SMEM 49152

__global__ __launch_bounds__(256, 1)
void k_gemm1_mma(const float* __restrict__ b1) {
    extern __shared__ char smem[];
    uint32_t sb = smem_u32(smem);
    int tid = threadIdx.x, wid = tid >> 5, lane = tid & 31;
    int r0 = blockIdx.x * 128;

    {
        int m = tid >> 1, h = tid & 1;
        int node = min(r0 + m, N_NODES - 1);
        const float* a24 = g_agg24 + (size_t)node * 24;
        const float* h0p = g_h0 + (size_t)node * 24;
#pragma unroll
        for (int kk = 0; kk < 32; kk += 8) {
            float z[8];
#pragma unroll
            for (int j = 0; j < 8; j++) {
                int k = h * 32 + kk + j;
                z[j] = (k < 24) ? a24[k] : ((k < 48) ? h0p[k - 24] : 0.f);
            }
            uint32_t hw[4];
            pack8h(z, hw);
            int c = h * 4 + (kk >> 3);
            uint32_t off = (uint32_t)m * 128 + (uint32_t)((c ^ (m & 7)) << 4);
            *(uint4*)(smem + G1_SA + off) = make_uint4(hw[0], hw[1], hw[2], hw[3]);
        }
    }
    {
        int n = tid;
        const __half* src = g_w1 + (size_t)n * 64;
#pragma unroll
        for (int c = 0; c < 8; c++) {
            uint32_t off = (uint32_t)n * 128 + (uint32_t)((c ^ (n & 7)) << 4);
            *(uint4*)(smem + G1_SB + off) = *(const uint4*)(src + c * 8);
        }
    }
    __syncthreads();

    uint32_t Ah[16];
    {
        int rowA = wid * 16 + (lane & 15);
        uint32_t rbase = (uint32_t)rowA * 128;
        int rx = rowA & 7;
        int csel = lane >> 4;
#pragma unroll
        for (int ks = 0; ks < 4; ks++) {
            int c = ks * 2 + csel;
            ldm_x4(&Ah[ks * 4], sb + G1_SA + rbase + (uint32_t)((c ^ rx) << 4));
        }
    }

    int row0 = r0 + wid * 16 + (lane >> 2);
    int row1 = row0 + 8;
#pragma unroll
    for (int nt = 0; nt < 32; nt++) {
        uint32_t B[8];
        {
            int nrow = nt * 8 + (lane & 7);
            uint32_t rbase = (uint32_t)nrow * 128;
            int rx = nrow & 7;
            int csel = lane >> 3;
#pragma unroll
            for (int kp = 0; kp < 2; kp++) {
                int c = kp * 4 + csel;
                ldm_x4(&B[kp * 4], sb + G1_SB + rbase + (uint32_t)((c ^ rx) << 4));
            }
        }
        float accE[4] = {0, 0, 0, 0}, accO[4] = {0, 0, 0, 0};
#pragma unroll
        for (int ks = 0; ks < 4; ks++)
            mma_f16((ks & 1) ? accO : accE, &Ah[ks * 4], &B[ks * 2]);
        int col = nt * 8 + ((lane & 3) << 1);
        float bx = b1[col], by = b1[col + 1];
        if (row0 < N_NODES) {
            float2 o = {fmaxf(accE[0] + accO[0] + bx, 0.f), fmaxf(accE[1] + accO[1] + by, 0.f)};
            *(float2*)(g_h1 + (size_t)row0 * 256 + col) = o;
        }
        if (row1 < N_NODES) {
            float2 o = {fmaxf(accE[2] + accO[2] + bx, 0.f), fmaxf(accE[3] + accO[3] + by, 0.f)};
            *(float2*)(g_h1 + (size_t)row1 * 256 + col) = o;
        }
    }
}

// ---------------- layer-2 aggregation: 256-dim gather-reduce (warp per node, 2-way unroll) ----------------
__global__ void k_agg256() {
    int w = (blockIdx.x * blockDim.x + threadIdx.x) >> 5;
    int lane = threadIdx.x & 31;
    if (w >= N_NODES) return;
    int beg = g_off[w], end = g_off[w + 1];
    float4 a0 = make_float4(0, 0, 0, 0), a1 = a0;
    float4 b0 = make_float4(0, 0, 0, 0), b1 = b0;
    int e = beg;
    for (; e + 1 < end; e += 2) {
        int s0 = g_csrc[e] & 0xFFFFF;
        int s1 = g_csrc[e + 1] & 0xFFFFF;
        const float4* p0 = (const float4*)(g_h1 + (size_t)s0 * 256 + lane * 8);
        const float4* p1 = (const float4*)(g_h1 + (size_t)s1 * 256 + lane * 8);
        float4 x0 = p0[0], x1 = p0[1], y0 = p1[0], y1 = p1[1];
        a0.x += x0.x; a0.y += x0.y; a0.z += x0.z; a0.w += x0.w;
        a1.x += x1.x; a1.y += x1.y; a1.z += x1.z; a1.w += x1.w;
        b0.x += y0.x; b0.y += y0.y; b0.z += y0.z; b0.w += y0.w;
        b1.x += y1.x; b1.y += y1.y; b1.z += y1.z; b1.w += y1.w;
    }
    if (e < end) {
        int s0 = g_csrc[e] & 0xFFFFF;
        const float4* p0 = (const float4*)(g_h1 + (size_t)s0 * 256 + lane * 8);
        float4 x0 = p0[0], x1 = p0[1];
        a0.x += x0.x; a0.y += x0.y; a0.z += x0.z; a0.w += x0.w;
        a1.x += x1.x; a1.y += x1.y; a1.z += x1.z; a1.w += x1.w;
    }
    a0.x += b0.x; a0.y += b0.y; a0.z += b0.z; a0.w += b0.w;
    a1.x += b1.x; a1.y += b1.y; a1.z += b1.z; a1.w += b1.w;
    float inv = 1.f / fmaxf((float)(end - beg), 1.f);
    a0.x *= inv; a0.y *= inv; a0.z *= inv; a0.w *= inv;
    a1.x *= inv; a1.y *= inv; a1.z *= inv; a1.w *= inv;
    float4* q = (float4*)(g_agg256 + (size_t)w * 256 + lane * 8);
    q[0] = a0; q[1] = a1;
}

// =====================================================================================
// k_gemm2uv_mma: FUSED  h2 = relu([agg256|h1]@[W2l;W2r]+b2);  uv = h2 @ Wuv
// single-fp16 A x fp16 B throughout.
// =====================================================================================
#define F_SA     0
#define F_SB     32768
#define F_A2     0
#define F_BUV    32768
#define F_SMEM   98304

__global__ __launch_bounds__(256, 1)
void k_gemm2uv_mma(const float* __restrict__ b2) {
    extern __shared__ char smem[];
    uint32_t sb = smem_u32(smem);
    int tid = threadIdx.x, wid = tid >> 5, lane = tid & 31;
    int r0 = blockIdx.x * 128;

    float acc[16][4];
#pragma unroll
    for (int nt = 0; nt < 16; nt++)
#pragma unroll
        for (int j = 0; j < 4; j++) acc[nt][j] = 0.f;

    for (int kc = 0; kc < 4; kc++) {
        if (kc) __syncthreads();
        {
            int m = tid >> 1, h = tid & 1;
            int node = min(r0 + m, N_NODES - 1);
            const float* src = ((kc < 2) ? (g_agg256 + (size_t)node * 256 + kc * 128)
                                         : (g_h1 + (size_t)node * 256 + (kc - 2) * 128)) + h * 64;
#pragma unroll
            for (int kk = 0; kk < 64; kk += 8) {
                float z[8];
                *(float4*)(z) = *(const float4*)(src + kk);
                *(float4*)(z + 4) = *(const float4*)(src + kk + 4);
                uint32_t hw[4];
                pack8h(z, hw);
                int chunk = h * 8 + (kk >> 3);
                uint32_t off = (uint32_t)m * 256 + (uint32_t)((chunk ^ (m & 7)) << 4);
                *(uint4*)(smem + F_SA + off) = make_uint4(hw[0], hw[1], hw[2], hw[3]);
            }
        }
        {
            int n = tid >> 1, h = tid & 1;
            const __half* src = g_w2 + (size_t)n * 512 + kc * 128 + h * 64;
#pragma unroll
            for (int c = 0; c < 8; c++) {
                int chunk = h * 8 + c;
                uint32_t off = (uint32_t)n * 256 + (uint32_t)((chunk ^ (n & 7)) << 4);
                *(uint4*)(smem + F_SB + off) = *(const uint4*)(src + c * 8);
            }
        }
        __syncthreads();

        uint32_t Ah[32];
        {
            int rowA = wid * 16 + (lane & 15);
            uint32_t rbase = (uint32_t)rowA * 256;
            int rx = rowA & 7;
            int csel = lane >> 4;
#pragma unroll
            for (int ks = 0; ks < 8; ks++) {
                int chunk = ks * 2 + csel;
                ldm_x4(&Ah[ks * 4], sb + F_SA + rbase + (uint32_t)((chunk ^ rx) << 4));
            }
        }
#pragma unroll
        for (int nt = 0; nt < 16; nt++) {
            uint32_t B[16];
            {
                int nrow = nt * 8 + (lane & 7);
                uint32_t rbase = (uint32_t)nrow * 256;
                int rx = nrow & 7;
                int csel = lane >> 3;
#pragma unroll
                for (int kp = 0; kp < 4; kp++) {
                    int chunk = kp * 4 + csel;
                    ldm_x4(&B[kp * 4], sb + F_SB + rbase + (uint32_t)((chunk ^ rx) << 4));
                }
            }
            float accE[4] = {0, 0, 0, 0}, accO[4] = {0, 0, 0, 0};
#pragma unroll
            for (int ks = 0; ks < 8; ks++)
                mma_f16((ks & 1) ? accO : accE, &Ah[ks * 4], &B[ks * 2]);
#pragma unroll
            for (int j = 0; j < 4; j++) acc[nt][j] += accE[j] + accO[j];
        }
    }
    __syncthreads();

    // ---------------- phase 2: h2 -> A2 smem (single fp16), Buv load, GEMM -> g_uv ----------------
    {
        int n = tid;
        const __half* src = g_wuv + (size_t)n * 128;
#pragma unroll
        for (int c = 0; c < 16; c++) {
            uint32_t off = (uint32_t)n * 256 + (uint32_t)((c ^ (n & 7)) << 4);
            *(uint4*)(smem + F_BUV + off) = *(const uint4*)(src + c * 8);
        }
    }
    {
        int rloc0 = wid * 16 + (lane >> 2);
        int rloc1 = rloc0 + 8;
        int rx0 = rloc0 & 7, rx1 = rloc1 & 7;
#pragma unroll
        for (int nt = 0; nt < 16; nt++) {
            int c = nt * 8 + ((lane & 3) << 1);
            float bx = b2[c], by = b2[c + 1];
            float v0x = fmaxf(acc[nt][0] + bx, 0.f), v0y = fmaxf(acc[nt][1] + by, 0.f);
            float v1x = fmaxf(acc[nt][2] + bx, 0.f), v1y = fmaxf(acc[nt][3] + by, 0.f);
            uint32_t base0 = (uint32_t)rloc0 * 256 + (uint32_t)((((c >> 3) ^ rx0)) << 4) + (uint32_t)(c & 7) * 2;
            *(uint32_t*)(smem + F_A2 + base0) = pack2h(v0x, v0y);
            uint32_t base1 = (uint32_t)rloc1 * 256 + (uint32_t)((((c >> 3) ^ rx1)) << 4) + (uint32_t)(c & 7) * 2;
            *(uint32_t*)(smem + F_A2 + base1) = pack2h(v1x, v1y);
        }
    }
    __syncthreads();

    uint32_t Ah[32];
    {
        int rowA = wid * 16 + (lane & 15);
        uint32_t rbase = (uint32_t)rowA * 256;
        int rx = rowA & 7;
        int csel = lane >> 4;
#pragma unroll
        for (int ks = 0; ks < 8; ks++) {
            int chunk = ks * 2 + csel;
            ldm_x4(&Ah[ks * 4], sb + F_A2 + rbase + (uint32_t)((chunk ^ rx) << 4));
        }
    }
    int row0 = r0 + wid * 16 + (lane >> 2);
    int row1 = row0 + 8;
#pragma unroll
    for (int nt = 0; nt < 32; nt++) {
        uint32_t B[16];
        {
            int nrow = nt * 8 + (lane & 7);
            uint32_t rbase = (uint32_t)nrow * 256;
            int rx = nrow & 7;
            int csel = lane >> 3;
#pragma unroll
            for (int kp = 0; kp < 4; kp++) {
                int chunk = kp * 4 + csel;
                ldm_x4(&B[kp * 4], sb + F_BUV + rbase + (uint32_t)((chunk ^ rx) << 4));
            }
        }
        float accE[4] = {0, 0, 0, 0}, accO[4] = {0, 0, 0, 0};
#pragma unroll
        for (int ks = 0; ks < 8; ks++)
            mma_f16((ks & 1) ? accO : accE, &Ah[ks * 4], &B[ks * 2]);
        int col = nt * 8 + ((lane & 3) << 1);
        if (row0 < N_NODES) {
            float2 o = {accE[0] + accO[0], accE[1] + accO[1]};
            *(float2*)(g_uv + (size_t)row0 * 256 + col) = o;
        }
        if (row1 < N_NODES) {
            float2 o = {accE[2] + accO[2], accE[3] + accO[3]};
            *(float2*)(g_uv + (size_t)row1 * 256 + col) = o;
        }
    }
}

// =====================================================================================
// k_edge_mma: edge classifier, single-fp16 A x fp16 B; M=256/CTA (512 threads);
// full B (552x128 fp16 = 141KB) in SMEM
// =====================================================================================
#define EM_M     256
#define SM_A     0
#define SM_B     65536
#define SM_EDGE_TOTAL (65536 + 552 * 256)   // 206848

__global__ __launch_bounds__(512, 1)
void k_edge_mma(const int* __restrict__ egt, const float* __restrict__ bc1,
                const float* __restrict__ bc2, float* __restrict__ out) {
    extern __shared__ char smem[];
    uint32_t sb = smem_u32(smem);
    int tid = threadIdx.x, wid = tid >> 5, lane = tid & 31;
    int e0 = blockIdx.x * EM_M;

    // async-load the full B (552 rows x 128 k fp16), overlapped with A prep
    for (int id = tid; id < 552 * 16; id += 512) {
        int n = id >> 4, c = id & 15;
        uint32_t dst = sb + SM_B + (uint32_t)n * 256 + (uint32_t)((c ^ (n & 7)) << 4);
        cp16(dst, g_wc2 + (size_t)n * 128 + c * 8);
    }
    CP_COMMIT();

    // A prep: z = relu(u[s]+v[d]+bc1) -> single fp16 (256 rows, thread = row tid/2, half tid&1)
    {
        int m = tid >> 1, h = tid & 1;
        int er = e0 + m;
        int s = 0, d = 0;
        if (er < EGT) { s = egt[er]; d = egt[EGT + er]; }
        const float* up = g_uv + (size_t)s * 256 + h * 64;
        const float* vp = g_uv + (size_t)d * 256 + 128 + h * 64;
        const float* bp = bc1 + h * 64;
#pragma unroll
        for (int kk = 0; kk < 64; kk += 8) {
            float z[8];
#pragma unroll
            for (int j = 0; j < 8; j += 4) {
                float4 u4 = *(const float4*)(up + kk + j);
                float4 v4 = *(const float4*)(vp + kk + j);
                float4 b4 = *(const float4*)(bp + kk + j);
                z[j + 0] = fmaxf(u4.x + v4.x + b4.x, 0.f);
                z[j + 1] = fmaxf(u4.y + v4.y + b4.y, 0.f);
                z[j + 2] = fmaxf(u4.z + v4.z + b4.z, 0.f);
                z[j + 3] = fmaxf(u4.w + v4.w + b4.w, 0.f);
            }
            uint32_t hw[4];
            pack8h(z, hw);
            int chunk = h * 8 + (kk >> 3);
            uint32_t off = (uint32_t)m * 256 + (uint32_t)((chunk ^ (m & 7)) << 4);
            *(uint4*)(smem + SM_A + off) = make_uint4(hw[0], hw[1], hw[2], hw[3]);
        }
    }
    CP_WAIT0();
    __syncthreads();   // A + B smem visible

    uint32_t Ah[32];
    {
        int rowA = wid * 16 + (lane & 15);    // wid 0..15 -> rows 0..255
        uint32_t rbase = (uint32_t)rowA * 256;
        int rx = rowA & 7;
        int csel = lane >> 4;
#pragma unroll
        for (int ks = 0; ks < 8; ks++) {
            int chunk = ks * 2 + csel;
            ldm_x4(&Ah[ks * 4], sb + SM_A + rbase + (uint32_t)((chunk ^ rx) << 4));
        }
    }

    int r0g = e0 + wid * 16 + (lane >> 2);
    bool v0 = r0g < EGT, v1 = (r0g + 8) < EGT;
    float* orow0 = out + (size_t)r0g * 552;
    float* orow1 = orow0 + 8 * 552;

    for (int jt = 0; jt < 69; jt++) {
        uint32_t B[16];
        {
            int nrow = jt * 8 + (lane & 7);
            uint32_t rbase = sb + SM_B + (uint32_t)nrow * 256;
            int rx = nrow & 7;
            int csel = lane >> 3;
#pragma unroll
            for (int kp = 0; kp < 4; kp++) {
                int chunk = kp * 4 + csel;
                ldm_x4(&B[kp * 4], rbase + (uint32_t)((chunk ^ rx) << 4));
            }
        }
        float accE[4] = {0, 0, 0, 0}, accO[4] = {0, 0, 0, 0};
#pragma unroll
        for (int ks = 0; ks < 8; ks++)
            mma_f16((ks & 1) ? accO : accE, &Ah[ks * 4], &B[ks * 2]);

        int col = jt * 8 + ((lane & 3) << 1);
        float bx = bc2[col], by = bc2[col + 1];
        if (v0) {
            float2 o0 = {sigf(accE[0] + accO[0] + bx), sigf(accE[1] + accO[1] + by)};
            *(float2*)(orow0 + col) = o0;
        }
        if (v1) {
            float2 o1 = {sigf(accE[2] + accO[2] + bx), sigf(accE[3] + accO[3] + by)};
            *(float2*)(orow1 + col) = o1;
        }
    }
}

// ---------------- launch ----------------
extern "C" void kernel_launch(void* const* d_in, const int* in_sizes, int n_in,
                              void* d_out, int out_size) {
    const float* x    = (const float*)d_in[0];
    const int*   ei   = (const int*)  d_in[1];
    const int*   egt  = (const int*)  d_in[2];
    const int*   ef   = (const int*)  d_in[3];
    const float* embT = (const float*)d_in[4];
    const float* embA = (const float*)d_in[5];
    const float* W1l  = (const float*)d_in[6];
    const float* W1r  = (const float*)d_in[7];
    const float* b1   = (const float*)d_in[8];
    const float* W2l  = (const float*)d_in[9];
    const float* W2r  = (const float*)d_in[10];
    const float* b2   = (const float*)d_in[11];
    const float* Wc1  = (const float*)d_in[12];
    const float* bc1  = (const float*)d_in[13];
    const float* Wc2  = (const float*)d_in[14];
    const float* bc2  = (const float*)d_in[15];
    float* out = (float*)d_out;

    cudaFuncSetAttribute(k_gemm1_mma, cudaFuncAttributeMaxDynamicSharedMemorySize, G1_SMEM);
    cudaFuncSetAttribute(k_gemm2uv_mma, cudaFuncAttributeMaxDynamicSharedMemorySize, F_SMEM);
    cudaFuncSetAttribute(k_edge_mma, cudaFuncAttributeMaxDynamicSharedMemorySize, SM_EDGE_TOTAL);

    k_prep<<<(552 * 128 + 255) / 256, 256>>>(Wc2, W2l, W2r, Wc1, W1l, W1r);
    k_count<<<(E_EDGES + 255) / 256, 256>>>(ei);
    k_scan2<<<2, 1024>>>();
    k_scatter2<<<(E_EDGES + 255) / 256, 256>>>(ei, ef);
    k_h0build<<<(N_NODES + 255) / 256, 256>>>(x, embT, embA);
    k_agg24<<<(N_NODES * 32 + 255) / 256, 256>>>();
    k_gemm1_mma<<<(N_NODES + 127) / 128, 256, G1_SMEM>>>(b1);
    k_agg256<<<(N_NODES * 32 + 255) / 256, 256>>>();
    k_gemm2uv_mma<<<(N_NODES + 127) / 128, 256, F_SMEM>>>(b2);
    k_edge_mma<<<(EGT + EM_M - 1) / EM_M, 512, SM_EDGE_TOTAL>>>(egt, bc1, bc2, out);
}

// round 11
// speedup vs baseline: 1.8815x; 1.1121x over previous
#include <cuda_runtime.h>
#include <cuda_fp16.h>
#include <cstdint>

#define N_NODES 50000
#define E_EDGES 800000
#define EGT     200000
#define NPAD    53248      // 1024 threads * 52 (CH), multiple of 4

// ---------------- scratch (static device globals; no allocation) ----------------
__device__ float g_h0[N_NODES * 24];        // [x(16) | agg_trigger(4) | agg_action(4)]
__device__ int   g_degd[NPAD];
__device__ int   g_degs[NPAD];
__device__ int   g_curd[N_NODES];
__device__ int   g_curs[N_NODES];
__device__ int   g_off[NPAD + 4];           // CSR by dst
__device__ int   g_offs[NPAD + 4];          // CSR by src
__device__ int   g_csrc[E_EDGES];           // per in-edge: src | (action<<20)
__device__ int   g_strig[E_EDGES];          // per out-edge: trigger code
__device__ float g_agg24[N_NODES * 24];
__device__ __half g_h1h[N_NODES * 256];     // h1 fp16 (consumers convert to fp16 anyway)
__device__ __half g_agg256h[N_NODES * 256]; // agg256 fp16
__device__ float g_uv[N_NODES * 256];       // [u(128) | v(128)] per node
__device__ __half g_wc2[552 * 128];         // Wc2^T fp16, [n][k]
__device__ __half g_w2[128 * 512];          // [W2l;W2r]^T fp16, [n][k]
__device__ __half g_wuv[256 * 128];         // [Wc1_top|Wc1_bot]^T fp16, [n][k]
__device__ __half g_w1[256 * 64];           // [W1l;W1r]^T fp16, [n][k] (k padded 48->64)

// ======================= warp-MMA + async helpers (baseline PTX, sm_80+) =======================
__device__ __forceinline__ uint32_t smem_u32(const void* p) {
    uint32_t a;
    asm("{ .reg .u64 t; cvta.to.shared.u64 t, %1; cvt.u32.u64 %0, t; }" : "=r"(a) : "l"(p));
    return a;
}
__device__ __forceinline__ void ldm_x4(uint32_t* r, uint32_t addr) {
    asm volatile("ldmatrix.sync.aligned.m8n8.x4.shared.b16 {%0,%1,%2,%3}, [%4];"
        : "=r"(r[0]), "=r"(r[1]), "=r"(r[2]), "=r"(r[3]) : "r"(addr));
}
__device__ __forceinline__ void mma_f16(float* c, const uint32_t* a, const uint32_t* b) {
    asm volatile(
        "mma.sync.aligned.m16n8k16.row.col.f32.f16.f16.f32 "
        "{%0,%1,%2,%3}, {%4,%5,%6,%7}, {%8,%9}, {%0,%1,%2,%3};"
        : "+f"(c[0]), "+f"(c[1]), "+f"(c[2]), "+f"(c[3])
        : "r"(a[0]), "r"(a[1]), "r"(a[2]), "r"(a[3]), "r"(b[0]), "r"(b[1]));
}
__device__ __forceinline__ void cp16(uint32_t dst, const void* src) {
    asm volatile("cp.async.cg.shared.global [%0], [%1], 16;" :: "r"(dst), "l"(src));
}
#define CP_COMMIT() asm volatile("cp.async.commit_group;" ::: "memory")
#define CP_WAIT0()  asm volatile("cp.async.wait_group 0;" ::: "memory")
__device__ __forceinline__ float sigf(float x) { return __fdividef(1.f, 1.f + __expf(-x)); }

// pack 8 floats to fp16 (no split)
__device__ __forceinline__ void pack8h(const float* z, uint32_t* hw) {
#pragma unroll
    for (int p = 0; p < 4; p++) {
        __half2 hh = __halves2half2(__float2half(z[2 * p]), __float2half(z[2 * p + 1]));
        hw[p] = *reinterpret_cast<uint32_t*>(&hh);
    }
}
__device__ __forceinline__ uint32_t pack2h(float x, float y) {
    __half2 hh = __halves2half2(__float2half(x), __float2half(y));
    return *reinterpret_cast<uint32_t*>(&hh);
}
__device__ __forceinline__ void add_h2x4(float* acc, uint4 q) {
    const __half2* h = reinterpret_cast<const __half2*>(&q);
#pragma unroll
    for (int p = 0; p < 4; p++) {
        float2 f = __half22float2(h[p]);
        acc[2 * p] += f.x;
        acc[2 * p + 1] += f.y;
    }
}

// ---------------- fused prep: zero counters (incl. padding) + weight transposes (fp16) ----------------
__global__ void k_prep(const float* __restrict__ Wc2, const float* __restrict__ W2l,
                       const float* __restrict__ W2r, const float* __restrict__ Wc1,
                       const float* __restrict__ W1l, const float* __restrict__ W1r) {
    int i = blockIdx.x * blockDim.x + threadIdx.x;
    if (i < NPAD) { g_degd[i] = 0; g_degs[i] = 0; }
    if (i < N_NODES) { g_curd[i] = 0; g_curs[i] = 0; }
    if (i < 552 * 128) {
        int n = i >> 7, k = i & 127;
        g_wc2[i] = __float2half(Wc2[(size_t)k * 552 + n]);
    }
    if (i < 128 * 512) {
        int n = i >> 9, k = i & 511;
        float w = (k < 256) ? W2l[(size_t)k * 128 + n] : W2r[(size_t)(k - 256) * 128 + n];
        g_w2[i] = __float2half(w);
    }
    if (i < 256 * 128) {
        int n = i >> 7, k = i & 127;
        float w = (n < 128) ? Wc1[(size_t)k * 128 + n] : Wc1[(size_t)(128 + k) * 128 + (n - 128)];
        g_wuv[i] = __float2half(w);
    }
    if (i < 256 * 64) {
        int n = i >> 6, k = i & 63;
        float w = 0.f;
        if (k < 24) w = W1l[(size_t)k * 256 + n];
        else if (k < 48) w = W1r[(size_t)(k - 24) * 256 + n];
        g_w1[i] = __float2half(w);
    }
}

// ---------------- degree count (both directions) ----------------
__global__ void k_count(const int* __restrict__ ei) {
    int e = blockIdx.x * blockDim.x + threadIdx.x;
    if (e >= E_EDGES) return;
    atomicAdd(&g_degs[ei[e]], 1);
    atomicAdd(&g_degd[ei[E_EDGES + e]], 1);
}

// ---------------- dual scan: blockIdx.x = 0 (dst-CSR) / 1 (src-CSR), int4 vectorized ----------------
__global__ void k_scan2() {
    int which = blockIdx.x;
    const int* deg = which ? g_degs : g_degd;
    int* off = which ? g_offs : g_off;
    const int CH = 52;
    int tid = threadIdx.x, lane = tid & 31, wid = tid >> 5;
    int beg = tid * CH;
    int sum = 0;
#pragma unroll
    for (int i = 0; i < CH; i += 4) {
        int4 v = *(const int4*)(deg + beg + i);
        sum += v.x + v.y + v.z + v.w;
    }
    int v = sum;
#pragma unroll
    for (int o = 1; o < 32; o <<= 1) {
        int t = __shfl_up_sync(0xFFFFFFFFu, v, o);
        if (lane >= o) v += t;
    }
    __shared__ int wsum[32];
    if (lane == 31) wsum[wid] = v;
    __syncthreads();
    if (wid == 0) {
        int w = wsum[lane];
#pragma unroll
        for (int o = 1; o < 32; o <<= 1) {
            int t = __shfl_up_sync(0xFFFFFFFFu, w, o);
            if (lane >= o) w += t;
        }
        wsum[lane] = w;
    }
    __syncthreads();
    int base = v - sum + (wid ? wsum[wid - 1] : 0);
#pragma unroll
    for (int i = 0; i < CH; i += 4) {
        int4 d = *(const int4*)(deg + beg + i);
        int4 o;
        o.x = base;
        o.y = o.x + d.x;
        o.z = o.y + d.y;
        o.w = o.z + d.z;
        base = o.w + d.w;
        *(int4*)(off + beg + i) = o;
    }
}

// ---------------- scatter both CSRs (action packed into csrc high bits) ----------------
__global__ void k_scatter2(const int* __restrict__ ei, const int* __restrict__ ef) {
    int e = blockIdx.x * blockDim.x + threadIdx.x;
    if (e >= E_EDGES) return;
    int s = ei[e], d = ei[E_EDGES + e];
    int t = ef[2 * e], a = ef[2 * e + 1];
    int posd = g_off[d] + atomicAdd(&g_curd[d], 1);
    g_csrc[posd] = s | (a << 20);
    int poss = g_offs[s] + atomicAdd(&g_curs[s], 1);
    g_strig[poss] = t;
}

// ---------------- h0 build: x copy + trigger/action gather-reduce (no atomics) ----------------
__global__ void k_h0build(const float* __restrict__ x,
                          const float* __restrict__ embT, const float* __restrict__ embA) {
    int n = blockIdx.x * blockDim.x + threadIdx.x;
    if (n >= N_NODES) return;
    float* h0 = g_h0 + (size_t)n * 24;
    const float4* xp = (const float4*)(x + (size_t)n * 16);
#pragma unroll
    for (int j = 0; j < 4; j++) ((float4*)h0)[j] = xp[j];
    float4 trig = make_float4(0, 0, 0, 0);
    int b0 = g_offs[n], e0 = g_offs[n + 1];
    for (int e = b0; e < e0; e++) {
        int t = g_strig[e];
        float4 v = *(const float4*)(embT + (size_t)t * 4);
        trig.x += v.x; trig.y += v.y; trig.z += v.z; trig.w += v.w;
    }
    float4 act = make_float4(0, 0, 0, 0);
    int b1 = g_off[n], e1 = g_off[n + 1];
    for (int e = b1; e < e1; e++) {
        int a = g_csrc[e] >> 20;
        float4 v = *(const float4*)(embA + (size_t)a * 4);
        act.x += v.x; act.y += v.y; act.z += v.z; act.w += v.w;
    }
    ((float4*)h0)[4] = trig;
    ((float4*)h0)[5] = act;
}

// ---------------- layer-1 aggregation in 24-dim space (warp per node, 2-way unroll) ----------------
__global__ void k_agg24() {
    int w = (blockIdx.x * blockDim.x + threadIdx.x) >> 5;
    int lane = threadIdx.x & 31;
    if (w >= N_NODES) return;
    int beg = g_off[w], end = g_off[w + 1];
    if (lane < 24) {
        float acc0 = 0.f, acc1 = 0.f;
        int e = beg;
        for (; e + 1 < end; e += 2) {
            int s0 = g_csrc[e] & 0xFFFFF;
            int s1 = g_csrc[e + 1] & 0xFFFFF;
            acc0 += g_h0[s0 * 24 + lane];
            acc1 += g_h0[s1 * 24 + lane];
        }
        if (e < end) acc0 += g_h0[(g_csrc[e] & 0xFFFFF) * 24 + lane];
        float inv = 1.f / fmaxf((float)(end - beg), 1.f);
        g_agg24[w * 24 + lane] = (acc0 + acc1) * inv;
    }
}

// =====================================================================================
// k_gemm1_mma: h1 = relu([agg24|h0] @ [W1l;W1r] + b1), single-fp16 A x fp16 B -> fp16 h1
// =====================================================================================
#define G1_SA   0
#define G1_SB   16384
#define G1_SMEM 49152

__global__ __launch_bounds__(256, 1)
void k_gemm1_mma(const float* __restrict__ b1) {
    extern __shared__ char smem[];
    uint32_t sb = smem_u32(smem);
    int tid = threadIdx.x, wid = tid >> 5, lane = tid & 31;
    int r0 = blockIdx.x * 128;

    {
        int m = tid >> 1, h = tid & 1;
        int node = min(r0 + m, N_NODES - 1);
        const float* a24 = g_agg24 + (size_t)node * 24;
        const float* h0p = g_h0 + (size_t)node * 24;
#pragma unroll
        for (int kk = 0; kk < 32; kk += 8) {
            float z[8];
#pragma unroll
            for (int j = 0; j < 8; j++) {
                int k = h * 32 + kk + j;
                z[j] = (k < 24) ? a24[k] : ((k < 48) ? h0p[k - 24] : 0.f);
            }
            uint32_t hw[4];
            pack8h(z, hw);
            int c = h * 4 + (kk >> 3);
            uint32_t off = (uint32_t)m * 128 + (uint32_t)((c ^ (m & 7)) << 4);
            *(uint4*)(smem + G1_SA + off) = make_uint4(hw[0], hw[1], hw[2], hw[3]);
        }
    }
    {
        int n = tid;
        const __half* src = g_w1 + (size_t)n * 64;
#pragma unroll
        for (int c = 0; c < 8; c++) {
            uint32_t off = (uint32_t)n * 128 + (uint32_t)((c ^ (n & 7)) << 4);
            *(uint4*)(smem + G1_SB + off) = *(const uint4*)(src + c * 8);
        }
    }
    __syncthreads();

    uint32_t Ah[16];
    {
        int rowA = wid * 16 + (lane & 15);
        uint32_t rbase = (uint32_t)rowA * 128;
        int rx = rowA & 7;
        int csel = lane >> 4;
#pragma unroll
        for (int ks = 0; ks < 4; ks++) {
            int c = ks * 2 + csel;
            ldm_x4(&Ah[ks * 4], sb + G1_SA + rbase + (uint32_t)((c ^ rx) << 4));
        }
    }

    int row0 = r0 + wid * 16 + (lane >> 2);
    int row1 = row0 + 8;
#pragma unroll
    for (int nt = 0; nt < 32; nt++) {
        uint32_t B[8];
        {
            int nrow = nt * 8 + (lane & 7);
            uint32_t rbase = (uint32_t)nrow * 128;
            int rx = nrow & 7;
            int csel = lane >> 3;
#pragma unroll
            for (int kp = 0; kp < 2; kp++) {
                int c = kp * 4 + csel;
                ldm_x4(&B[kp * 4], sb + G1_SB + rbase + (uint32_t)((c ^ rx) << 4));
            }
        }
        float accE[4] = {0, 0, 0, 0}, accO[4] = {0, 0, 0, 0};
#pragma unroll
        for (int ks = 0; ks < 4; ks++)
            mma_f16((ks & 1) ? accO : accE, &Ah[ks * 4], &B[ks * 2]);
        int col = nt * 8 + ((lane & 3) << 1);
        float bx = b1[col], by = b1[col + 1];
        if (row0 < N_NODES)
            *(uint32_t*)(g_h1h + (size_t)row0 * 256 + col) =
                pack2h(fmaxf(accE[0] + accO[0] + bx, 0.f), fmaxf(accE[1] + accO[1] + by, 0.f));
        if (row1 < N_NODES)
            *(uint32_t*)(g_h1h + (size_t)row1 * 256 + col) =
                pack2h(fmaxf(accE[2] + accO[2] + bx, 0.f), fmaxf(accE[3] + accO[3] + by, 0.f));
    }
}

// ---------------- layer-2 aggregation: fp16 gather (1 uint4/lane/edge), fp32 accumulate ----------------
__global__ void k_agg256() {
    int w = (blockIdx.x * blockDim.x + threadIdx.x) >> 5;
    int lane = threadIdx.x & 31;
    if (w >= N_NODES) return;
    int beg = g_off[w], end = g_off[w + 1];
    float a[8] = {0, 0, 0, 0, 0, 0, 0, 0};
    float b[8] = {0, 0, 0, 0, 0, 0, 0, 0};
    int e = beg;
    for (; e + 1 < end; e += 2) {
        int s0 = g_csrc[e] & 0xFFFFF;
        int s1 = g_csrc[e + 1] & 0xFFFFF;
        uint4 q0 = *(const uint4*)(g_h1h + (size_t)s0 * 256 + lane * 8);
        uint4 q1 = *(const uint4*)(g_h1h + (size_t)s1 * 256 + lane * 8);
        add_h2x4(a, q0);
        add_h2x4(b, q1);
    }
    if (e < end) {
        int s0 = g_csrc[e] & 0xFFFFF;
        uint4 q0 = *(const uint4*)(g_h1h + (size_t)s0 * 256 + lane * 8);
        add_h2x4(a, q0);
    }
    float inv = 1.f / fmaxf((float)(end - beg), 1.f);
#pragma unroll
    for (int j = 0; j < 8; j++) a[j] = (a[j] + b[j]) * inv;
    uint32_t hw[4];
    pack8h(a, hw);
    *(uint4*)(g_agg256h + (size_t)w * 256 + lane * 8) = make_uint4(hw[0], hw[1], hw[2], hw[3]);
}

// =====================================================================================
// k_gemm2uv_mma: FUSED  h2 = relu([agg256|h1]@[W2l;W2r]+b2);  uv = h2 @ Wuv
// A inputs already fp16 in global -> straight swizzled copies.
// =====================================================================================
#define F_SA     0
#define F_SB     32768
#define F_A2     0
#define F_BUV    32768
#define F_SMEM   98304

__global__ __launch_bounds__(256, 1)
void k_gemm2uv_mma(const float* __restrict__ b2) {
    extern __shared__ char smem[];
    uint32_t sb = smem_u32(smem);
    int tid = threadIdx.x, wid = tid >> 5, lane = tid & 31;
    int r0 = blockIdx.x * 128;

    float acc[16][4];
#pragma unroll
    for (int nt = 0; nt < 16; nt++)
#pragma unroll
        for (int j = 0; j < 4; j++) acc[nt][j] = 0.f;

    for (int kc = 0; kc < 4; kc++) {
        if (kc) __syncthreads();
        {
            int m = tid >> 1, h = tid & 1;
            int node = min(r0 + m, N_NODES - 1);
            const __half* src = ((kc < 2) ? (g_agg256h + (size_t)node * 256 + kc * 128)
                                          : (g_h1h + (size_t)node * 256 + (kc - 2) * 128)) + h * 64;
#pragma unroll
            for (int c = 0; c < 8; c++) {
                int chunk = h * 8 + c;
                uint32_t off = (uint32_t)m * 256 + (uint32_t)((chunk ^ (m & 7)) << 4);
                *(uint4*)(smem + F_SA + off) = *(const uint4*)(src + c * 8);
            }
        }
        {
            int n = tid >> 1, h = tid & 1;
            const __half* src = g_w2 + (size_t)n * 512 + kc * 128 + h * 64;
#pragma unroll
            for (int c = 0; c < 8; c++) {
                int chunk = h * 8 + c;
                uint32_t off = (uint32_t)n * 256 + (uint32_t)((chunk ^ (n & 7)) << 4);
                *(uint4*)(smem + F_SB + off) = *(const uint4*)(src + c * 8);
            }
        }
        __syncthreads();

        uint32_t Ah[32];
        {
            int rowA = wid * 16 + (lane & 15);
            uint32_t rbase = (uint32_t)rowA * 256;
            int rx = rowA & 7;
            int csel = lane >> 4;
#pragma unroll
            for (int ks = 0; ks < 8; ks++) {
                int chunk = ks * 2 + csel;
                ldm_x4(&Ah[ks * 4], sb + F_SA + rbase + (uint32_t)((chunk ^ rx) << 4));
            }
        }
#pragma unroll
        for (int nt = 0; nt < 16; nt++) {
            uint32_t B[16];
            {
                int nrow = nt * 8 + (lane & 7);
                uint32_t rbase = (uint32_t)nrow * 256;
                int rx = nrow & 7;
                int csel = lane >> 3;
#pragma unroll
                for (int kp = 0; kp < 4; kp++) {
                    int chunk = kp * 4 + csel;
                    ldm_x4(&B[kp * 4], sb + F_SB + rbase + (uint32_t)((chunk ^ rx) << 4));
                }
            }
            float accE[4] = {0, 0, 0, 0}, accO[4] = {0, 0, 0, 0};
#pragma unroll
            for (int ks = 0; ks < 8; ks++)
                mma_f16((ks & 1) ? accO : accE, &Ah[ks * 4], &B[ks * 2]);
#pragma unroll
            for (int j = 0; j < 4; j++) acc[nt][j] += accE[j] + accO[j];
        }
    }
    __syncthreads();

    // ---------------- phase 2: h2 -> A2 smem (single fp16), Buv load, GEMM -> g_uv ----------------
    {
        int n = tid;
        const __half* src = g_wuv + (size_t)n * 128;
#pragma unroll
        for (int c = 0; c < 16; c++) {
            uint32_t off = (uint32_t)n * 256 + (uint32_t)((c ^ (n & 7)) << 4);
            *(uint4*)(smem + F_BUV + off) = *(const uint4*)(src + c * 8);
        }
    }
    {
        int rloc0 = wid * 16 + (lane >> 2);
        int rloc1 = rloc0 + 8;
        int rx0 = rloc0 & 7, rx1 = rloc1 & 7;
#pragma unroll
        for (int nt = 0; nt < 16; nt++) {
            int c = nt * 8 + ((lane & 3) << 1);
            float bx = b2[c], by = b2[c + 1];
            float v0x = fmaxf(acc[nt][0] + bx, 0.f), v0y = fmaxf(acc[nt][1] + by, 0.f);
            float v1x = fmaxf(acc[nt][2] + bx, 0.f), v1y = fmaxf(acc[nt][3] + by, 0.f);
            uint32_t base0 = (uint32_t)rloc0 * 256 + (uint32_t)((((c >> 3) ^ rx0)) << 4) + (uint32_t)(c & 7) * 2;
            *(uint32_t*)(smem + F_A2 + base0) = pack2h(v0x, v0y);
            uint32_t base1 = (uint32_t)rloc1 * 256 + (uint32_t)((((c >> 3) ^ rx1)) << 4) + (uint32_t)(c & 7) * 2;
            *(uint32_t*)(smem + F_A2 + base1) = pack2h(v1x, v1y);
        }
    }
    __syncthreads();

    uint32_t Ah[32];
    {
        int rowA = wid * 16 + (lane & 15);
        uint32_t rbase = (uint32_t)rowA * 256;
        int rx = rowA & 7;
        int csel = lane >> 4;
#pragma unroll
        for (int ks = 0; ks < 8; ks++) {
            int chunk = ks * 2 + csel;
            ldm_x4(&Ah[ks * 4], sb + F_A2 + rbase + (uint32_t)((chunk ^ rx) << 4));
        }
    }
    int row0 = r0 + wid * 16 + (lane >> 2);
    int row1 = row0 + 8;
#pragma unroll
    for (int nt = 0; nt < 32; nt++) {
        uint32_t B[16];
        {
            int nrow = nt * 8 + (lane & 7);
            uint32_t rbase = (uint32_t)nrow * 256;
            int rx = nrow & 7;
            int csel = lane >> 3;
#pragma unroll
            for (int kp = 0; kp < 4; kp++) {
                int chunk = kp * 4 + csel;
                ldm_x4(&B[kp * 4], sb + F_BUV + rbase + (uint32_t)((chunk ^ rx) << 4));
            }
        }
        float accE[4] = {0, 0, 0, 0}, accO[4] = {0, 0, 0, 0};
#pragma unroll
        for (int ks = 0; ks < 8; ks++)
            mma_f16((ks & 1) ? accO : accE, &Ah[ks * 4], &B[ks * 2]);
        int col = nt * 8 + ((lane & 3) << 1);
        if (row0 < N_NODES) {
            float2 o = {accE[0] + accO[0], accE[1] + accO[1]};
            *(float2*)(g_uv + (size_t)row0 * 256 + col) = o;
        }
        if (row1 < N_NODES) {
            float2 o = {accE[2] + accO[2], accE[3] + accO[3]};
            *(float2*)(g_uv + (size_t)row1 * 256 + col) = o;
        }
    }
}

// =====================================================================================
// k_edge_mma: edge classifier, single-fp16 A x fp16 B; M=256/CTA with 256 threads;
// warp owns 32 rows (2 m-tiles) sharing each B fragment. Full B (141KB) in SMEM.
// =====================================================================================
#define EM_M     256
#define SM_A     0
#define SM_B     65536
#define SM_EDGE_TOTAL (65536 + 552 * 256)   // 206848

__global__ __launch_bounds__(256, 1)
void k_edge_mma(const int* __restrict__ egt, const float* __restrict__ bc1,
                const float* __restrict__ bc2, float* __restrict__ out) {
    extern __shared__ char smem[];
    uint32_t sb = smem_u32(smem);
    int tid = threadIdx.x, wid = tid >> 5, lane = tid & 31;
    int e0 = blockIdx.x * EM_M;

    // async-load the full B (552 rows x 128 k fp16), overlapped with A prep
    for (int id = tid; id < 552 * 16; id += 256) {
        int n = id >> 4, c = id & 15;
        uint32_t dst = sb + SM_B + (uint32_t)n * 256 + (uint32_t)((c ^ (n & 7)) << 4);
        cp16(dst, g_wc2 + (size_t)n * 128 + c * 8);
    }
    CP_COMMIT();

    // A prep: z = relu(u[s]+v[d]+bc1) -> single fp16 (256 rows, 2 passes of 128)
    {
        int h = tid & 1;
        const float* bp = bc1 + h * 64;
        for (int m = tid >> 1; m < EM_M; m += 128) {
            int er = e0 + m;
            int s = 0, d = 0;
            if (er < EGT) { s = egt[er]; d = egt[EGT + er]; }
            const float* up = g_uv + (size_t)s * 256 + h * 64;
            const float* vp = g_uv + (size_t)d * 256 + 128 + h * 64;
#pragma unroll
            for (int kk = 0; kk < 64; kk += 8) {
                float z[8];
#pragma unroll
                for (int j = 0; j < 8; j += 4) {
                    float4 u4 = *(const float4*)(up + kk + j);
                    float4 v4 = *(const float4*)(vp + kk + j);
                    float4 b4 = *(const float4*)(bp + kk + j);
                    z[j + 0] = fmaxf(u4.x + v4.x + b4.x, 0.f);
                    z[j + 1] = fmaxf(u4.y + v4.y + b4.y, 0.f);
                    z[j + 2] = fmaxf(u4.z + v4.z + b4.z, 0.f);
                    z[j + 3] = fmaxf(u4.w + v4.w + b4.w, 0.f);
                }
                uint32_t hw[4];
                pack8h(z, hw);
                int chunk = h * 8 + (kk >> 3);
                uint32_t off = (uint32_t)m * 256 + (uint32_t)((chunk ^ (m & 7)) << 4);
                *(uint4*)(smem + SM_A + off) = make_uint4(hw[0], hw[1], hw[2], hw[3]);
            }
        }
    }
    CP_WAIT0();
    __syncthreads();   // A + B smem visible

    // A fragments: warp owns rows [wid*32, wid*32+32) = 2 m-tiles
    uint32_t Ah[2][32];
#pragma unroll
    for (int t = 0; t < 2; t++) {
        int rowA = wid * 32 + t * 16 + (lane & 15);
        uint32_t rbase = (uint32_t)rowA * 256;
        int rx = rowA & 7;
        int csel = lane >> 4;
#pragma unroll
        for (int ks = 0; ks < 8; ks++) {
            int chunk = ks * 2 + csel;
            ldm_x4(&Ah[t][ks * 4], sb + SM_A + rbase + (uint32_t)((chunk ^ rx) << 4));
        }
    }

    int rbase0 = e0 + wid * 32 + (lane >> 2);
    float* op[4];
    bool vv[4];
#pragma unroll
    for (int t = 0; t < 2; t++) {
        int ra = rbase0 + t * 16, rb = ra + 8;
        vv[2 * t] = ra < EGT;
        vv[2 * t + 1] = rb < EGT;
        op[2 * t] = out + (size_t)ra * 552;
        op[2 * t + 1] = out + (size_t)rb * 552;
    }

    for (int jt = 0; jt < 69; jt++) {
        uint32_t B[16];
        {
            int nrow = jt * 8 + (lane & 7);
            uint32_t rbase = sb + SM_B + (uint32_t)nrow * 256;
            int rx = nrow & 7;
            int csel = lane >> 3;
#pragma unroll
            for (int kp = 0; kp < 4; kp++) {
                int chunk = kp * 4 + csel;
                ldm_x4(&B[kp * 4], rbase + (uint32_t)((chunk ^ rx) << 4));
            }
        }
        int col = jt * 8 + ((lane & 3) << 1);
        float bx = bc2[col], by = bc2[col + 1];
#pragma unroll
        for (int t = 0; t < 2; t++) {
            float accE[4] = {0, 0, 0, 0}, accO[4] = {0, 0, 0, 0};
#pragma unroll
            for (int ks = 0; ks < 8; ks++)
                mma_f16((ks & 1) ? accO : accE, &Ah[t][ks * 4], &B[ks * 2]);
            if (vv[2 * t]) {
                float2 o0 = {sigf(accE[0] + accO[0] + bx), sigf(accE[1] + accO[1] + by)};
                *(float2*)(op[2 * t] + col) = o0;
            }
            if (vv[2 * t + 1]) {
                float2 o1 = {sigf(accE[2] + accO[2] + bx), sigf(accE[3] + accO[3] + by)};
                *(float2*)(op[2 * t + 1] + col) = o1;
            }
        }
    }
}

// ---------------- launch ----------------
extern "C" void kernel_launch(void* const* d_in, const int* in_sizes, int n_in,
                              void* d_out, int out_size) {
    const float* x    = (const float*)d_in[0];
    const int*   ei   = (const int*)  d_in[1];
    const int*   egt  = (const int*)  d_in[2];
    const int*   ef   = (const int*)  d_in[3];
    const float* embT = (const float*)d_in[4];
    const float* embA = (const float*)d_in[5];
    const float* W1l  = (const float*)d_in[6];
    const float* W1r  = (const float*)d_in[7];
    const float* b1   = (const float*)d_in[8];
    const float* W2l  = (const float*)d_in[9];
    const float* W2r  = (const float*)d_in[10];
    const float* b2   = (const float*)d_in[11];
    const float* Wc1  = (const float*)d_in[12];
    const float* bc1  = (const float*)d_in[13];
    const float* Wc2  = (const float*)d_in[14];
    const float* bc2  = (const float*)d_in[15];
    float* out = (float*)d_out;

    cudaFuncSetAttribute(k_gemm1_mma, cudaFuncAttributeMaxDynamicSharedMemorySize, G1_SMEM);
    cudaFuncSetAttribute(k_gemm2uv_mma, cudaFuncAttributeMaxDynamicSharedMemorySize, F_SMEM);
    cudaFuncSetAttribute(k_edge_mma, cudaFuncAttributeMaxDynamicSharedMemorySize, SM_EDGE_TOTAL);

    k_prep<<<(552 * 128 + 255) / 256, 256>>>(Wc2, W2l, W2r, Wc1, W1l, W1r);
    k_count<<<(E_EDGES + 255) / 256, 256>>>(ei);
    k_scan2<<<2, 1024>>>();
    k_scatter2<<<(E_EDGES + 255) / 256, 256>>>(ei, ef);
    k_h0build<<<(N_NODES + 255) / 256, 256>>>(x, embT, embA);
    k_agg24<<<(N_NODES * 32 + 255) / 256, 256>>>();
    k_gemm1_mma<<<(N_NODES + 127) / 128, 256, G1_SMEM>>>(b1);
    k_agg256<<<(N_NODES * 32 + 255) / 256, 256>>>();
    k_gemm2uv_mma<<<(N_NODES + 127) / 128, 256, F_SMEM>>>(b2);
    k_edge_mma<<<(EGT + EM_M - 1) / EM_M, 256, SM_EDGE_TOTAL>>>(egt, bc1, bc2, out);
}

// round 12
// speedup vs baseline: 2.0788x; 1.1049x over previous
#include <cuda_runtime.h>
#include <cuda_fp16.h>
#include <cstdint>

#define N_NODES 50000
#define E_EDGES 800000
#define EGT     200000
#define NPAD    53248      // 1024 threads * 52 (CH), multiple of 4

// ---------------- scratch (static device globals; no allocation) ----------------
__device__ float g_h0[N_NODES * 24];        // [x(16) | agg_trigger(4) | agg_action(4)]
__device__ int   g_degd[NPAD];
__device__ int   g_degs[NPAD];
__device__ int   g_curd[N_NODES];
__device__ int   g_curs[N_NODES];
__device__ int   g_off[NPAD + 4];           // CSR by dst
__device__ int   g_offs[NPAD + 4];          // CSR by src
__device__ int   g_csrc[E_EDGES];           // per in-edge: src | (action<<20)
__device__ int   g_strig[E_EDGES];          // per out-edge: trigger code
__device__ float g_agg24[N_NODES * 24];
__device__ __half g_h1h[N_NODES * 256];     // h1 fp16
__device__ __half g_agg256h[N_NODES * 256]; // agg256 fp16
__device__ __half g_uvh[N_NODES * 256];     // [u(128) | v(128)] per node, fp16
__device__ __half g_wc2[552 * 128];         // Wc2^T fp16, [n][k]
__device__ __half g_w2[128 * 512];          // [W2l;W2r]^T fp16, [n][k]
__device__ __half g_wuv[256 * 128];         // [Wc1_top|Wc1_bot]^T fp16, [n][k]
__device__ __half g_w1[256 * 64];           // [W1l;W1r]^T fp16, [n][k] (k padded 48->64)

// ======================= warp-MMA + async helpers (baseline PTX, sm_80+) =======================
__device__ __forceinline__ uint32_t smem_u32(const void* p) {
    uint32_t a;
    asm("{ .reg .u64 t; cvta.to.shared.u64 t, %1; cvt.u32.u64 %0, t; }" : "=r"(a) : "l"(p));
    return a;
}
__device__ __forceinline__ void ldm_x4(uint32_t* r, uint32_t addr) {
    asm volatile("ldmatrix.sync.aligned.m8n8.x4.shared.b16 {%0,%1,%2,%3}, [%4];"
        : "=r"(r[0]), "=r"(r[1]), "=r"(r[2]), "=r"(r[3]) : "r"(addr));
}
__device__ __forceinline__ void mma_f16(float* c, const uint32_t* a, const uint32_t* b) {
    asm volatile(
        "mma.sync.aligned.m16n8k16.row.col.f32.f16.f16.f32 "
        "{%0,%1,%2,%3}, {%4,%5,%6,%7}, {%8,%9}, {%0,%1,%2,%3};"
        : "+f"(c[0]), "+f"(c[1]), "+f"(c[2]), "+f"(c[3])
        : "r"(a[0]), "r"(a[1]), "r"(a[2]), "r"(a[3]), "r"(b[0]), "r"(b[1]));
}
__device__ __forceinline__ void cp16(uint32_t dst, const void* src) {
    asm volatile("cp.async.cg.shared.global [%0], [%1], 16;" :: "r"(dst), "l"(src));
}
#define CP_COMMIT() asm volatile("cp.async.commit_group;" ::: "memory")
#define CP_WAIT0()  asm volatile("cp.async.wait_group 0;" ::: "memory")
__device__ __forceinline__ float sigf(float x) { return __fdividef(1.f, 1.f + __expf(-x)); }

// pack 8 floats to fp16 (no split)
__device__ __forceinline__ void pack8h(const float* z, uint32_t* hw) {
#pragma unroll
    for (int p = 0; p < 4; p++) {
        __half2 hh = __halves2half2(__float2half(z[2 * p]), __float2half(z[2 * p + 1]));
        hw[p] = *reinterpret_cast<uint32_t*>(&hh);
    }
}
__device__ __forceinline__ uint32_t pack2h(float x, float y) {
    __half2 hh = __halves2half2(__float2half(x), __float2half(y));
    return *reinterpret_cast<uint32_t*>(&hh);
}
__device__ __forceinline__ void add_h2x4(float* acc, uint4 q) {
    const __half2* h = reinterpret_cast<const __half2*>(&q);
#pragma unroll
    for (int p = 0; p < 4; p++) {
        float2 f = __half22float2(h[p]);
        acc[2 * p] += f.x;
        acc[2 * p + 1] += f.y;
    }
}
__device__ __forceinline__ void unpack8h(uint4 q, float* f) {
    const __half2* h = reinterpret_cast<const __half2*>(&q);
#pragma unroll
    for (int p = 0; p < 4; p++) {
        float2 v = __half22float2(h[p]);
        f[2 * p] = v.x;
        f[2 * p + 1] = v.y;
    }
}

// ---------------- fused prep: zero counters (incl. padding) + weight transposes (fp16) ----------------
__global__ void k_prep(const float* __restrict__ Wc2, const float* __restrict__ W2l,
                       const float* __restrict__ W2r, const float* __restrict__ Wc1,
                       const float* __restrict__ W1l, const float* __restrict__ W1r) {
    int i = blockIdx.x * blockDim.x + threadIdx.x;
    if (i < NPAD) { g_degd[i] = 0; g_degs[i] = 0; }
    if (i < N_NODES) { g_curd[i] = 0; g_curs[i] = 0; }
    if (i < 552 * 128) {
        int n = i >> 7, k = i & 127;
        g_wc2[i] = __float2half(Wc2[(size_t)k * 552 + n]);
    }
    if (i < 128 * 512) {
        int n = i >> 9, k = i & 511;
        float w = (k < 256) ? W2l[(size_t)k * 128 + n] : W2r[(size_t)(k - 256) * 128 + n];
        g_w2[i] = __float2half(w);
    }
    if (i < 256 * 128) {
        int n = i >> 7, k = i & 127;
        float w = (n < 128) ? Wc1[(size_t)k * 128 + n] : Wc1[(size_t)(128 + k) * 128 + (n - 128)];
        g_wuv[i] = __float2half(w);
    }
    if (i < 256 * 64) {
        int n = i >> 6, k = i & 63;
        float w = 0.f;
        if (k < 24) w = W1l[(size_t)k * 256 + n];
        else if (k < 48) w = W1r[(size_t)(k - 24) * 256 + n];
        g_w1[i] = __float2half(w);
    }
}

// ---------------- degree count (both directions) ----------------
__global__ void k_count(const int* __restrict__ ei) {
    int e = blockIdx.x * blockDim.x + threadIdx.x;
    if (e >= E_EDGES) return;
    atomicAdd(&g_degs[ei[e]], 1);
    atomicAdd(&g_degd[ei[E_EDGES + e]], 1);
}

// ---------------- dual scan: blockIdx.x = 0 (dst-CSR) / 1 (src-CSR), int4 vectorized ----------------
__global__ void k_scan2() {
    int which = blockIdx.x;
    const int* deg = which ? g_degs : g_degd;
    int* off = which ? g_offs : g_off;
    const int CH = 52;
    int tid = threadIdx.x, lane = tid & 31, wid = tid >> 5;
    int beg = tid * CH;
    int sum = 0;
#pragma unroll
    for (int i = 0; i < CH; i += 4) {
        int4 v = *(const int4*)(deg + beg + i);
        sum += v.x + v.y + v.z + v.w;
    }
    int v = sum;
#pragma unroll
    for (int o = 1; o < 32; o <<= 1) {
        int t = __shfl_up_sync(0xFFFFFFFFu, v, o);
        if (lane >= o) v += t;
    }
    __shared__ int wsum[32];
    if (lane == 31) wsum[wid] = v;
    __syncthreads();
    if (wid == 0) {
        int w = wsum[lane];
#pragma unroll
        for (int o = 1; o < 32; o <<= 1) {
            int t = __shfl_up_sync(0xFFFFFFFFu, w, o);
            if (lane >= o) w += t;
        }
        wsum[lane] = w;
    }
    __syncthreads();
    int base = v - sum + (wid ? wsum[wid - 1] : 0);
#pragma unroll
    for (int i = 0; i < CH; i += 4) {
        int4 d = *(const int4*)(deg + beg + i);
        int4 o;
        o.x = base;
        o.y = o.x + d.x;
        o.z = o.y + d.y;
        o.w = o.z + d.z;
        base = o.w + d.w;
        *(int4*)(off + beg + i) = o;
    }
}

// ---------------- scatter both CSRs (action packed into csrc high bits) ----------------
__global__ void k_scatter2(const int* __restrict__ ei, const int* __restrict__ ef) {
    int e = blockIdx.x * blockDim.x + threadIdx.x;
    if (e >= E_EDGES) return;
    int s = ei[e], d = ei[E_EDGES + e];
    int t = ef[2 * e], a = ef[2 * e + 1];
    int posd = g_off[d] + atomicAdd(&g_curd[d], 1);
    g_csrc[posd] = s | (a << 20);
    int poss = g_offs[s] + atomicAdd(&g_curs[s], 1);
    g_strig[poss] = t;
}

// ---------------- h0 build: x copy + trigger/action gather-reduce (no atomics) ----------------
__global__ void k_h0build(const float* __restrict__ x,
                          const float* __restrict__ embT, const float* __restrict__ embA) {
    int n = blockIdx.x * blockDim.x + threadIdx.x;
    if (n >= N_NODES) return;
    float* h0 = g_h0 + (size_t)n * 24;
    const float4* xp = (const float4*)(x + (size_t)n * 16);
#pragma unroll
    for (int j = 0; j < 4; j++) ((float4*)h0)[j] = xp[j];
    float4 trig = make_float4(0, 0, 0, 0);
    int b0 = g_offs[n], e0 = g_offs[n + 1];
    for (int e = b0; e < e0; e++) {
        int t = g_strig[e];
        float4 v = *(const float4*)(embT + (size_t)t * 4);
        trig.x += v.x; trig.y += v.y; trig.z += v.z; trig.w += v.w;
    }
    float4 act = make_float4(0, 0, 0, 0);
    int b1 = g_off[n], e1 = g_off[n + 1];
    for (int e = b1; e < e1; e++) {
        int a = g_csrc[e] >> 20;
        float4 v = *(const float4*)(embA + (size_t)a * 4);
        act.x += v.x; act.y += v.y; act.z += v.z; act.w += v.w;
    }
    ((float4*)h0)[4] = trig;
    ((float4*)h0)[5] = act;
}

// ---------------- layer-1 aggregation in 24-dim space (warp per node, 2-way unroll) ----------------
__global__ void k_agg24() {
    int w = (blockIdx.x * blockDim.x + threadIdx.x) >> 5;
    int lane = threadIdx.x & 31;
    if (w >= N_NODES) return;
    int beg = g_off[w], end = g_off[w + 1];
    if (lane < 24) {
        float acc0 = 0.f, acc1 = 0.f;
        int e = beg;
        for (; e + 1 < end; e += 2) {
            int s0 = g_csrc[e] & 0xFFFFF;
            int s1 = g_csrc[e + 1] & 0xFFFFF;
            acc0 += g_h0[s0 * 24 + lane];
            acc1 += g_h0[s1 * 24 + lane];
        }
        if (e < end) acc0 += g_h0[(g_csrc[e] & 0xFFFFF) * 24 + lane];
        float inv = 1.f / fmaxf((float)(end - beg), 1.f);
        g_agg24[w * 24 + lane] = (acc0 + acc1) * inv;
    }
}

// =====================================================================================
// k_gemm1_mma: h1 = relu([agg24|h0] @ [W1l;W1r] + b1), single-fp16 A x fp16 B -> fp16 h1
// =====================================================================================
#define G1_SA   0
#define G1_SB   16384
#define G1_SMEM 49152

__global__ __launch_bounds__(256, 1)
void k_gemm1_mma(const float* __restrict__ b1) {
    extern __shared__ char smem[];
    uint32_t sb = smem_u32(smem);
    int tid = threadIdx.x, wid = tid >> 5, lane = tid & 31;
    int r0 = blockIdx.x * 128;

    {
        int m = tid >> 1, h = tid & 1;
        int node = min(r0 + m, N_NODES - 1);
        const float* a24 = g_agg24 + (size_t)node * 24;
        const float* h0p = g_h0 + (size_t)node * 24;
#pragma unroll
        for (int kk = 0; kk < 32; kk += 8) {
            float z[8];
#pragma unroll
            for (int j = 0; j < 8; j++) {
                int k = h * 32 + kk + j;
                z[j] = (k < 24) ? a24[k] : ((k < 48) ? h0p[k - 24] : 0.f);
            }
            uint32_t hw[4];
            pack8h(z, hw);
            int c = h * 4 + (kk >> 3);
            uint32_t off = (uint32_t)m * 128 + (uint32_t)((c ^ (m & 7)) << 4);
            *(uint4*)(smem + G1_SA + off) = make_uint4(hw[0], hw[1], hw[2], hw[3]);
        }
    }
    {
        int n = tid;
        const __half* src = g_w1 + (size_t)n * 64;
#pragma unroll
        for (int c = 0; c < 8; c++) {
            uint32_t off = (uint32_t)n * 128 + (uint32_t)((c ^ (n & 7)) << 4);
            *(uint4*)(smem + G1_SB + off) = *(const uint4*)(src + c * 8);
        }
    }
    __syncthreads();

    uint32_t Ah[16];
    {
        int rowA = wid * 16 + (lane & 15);
        uint32_t rbase = (uint32_t)rowA * 128;
        int rx = rowA & 7;
        int csel = lane >> 4;
#pragma unroll
        for (int ks = 0; ks < 4; ks++) {
            int c = ks * 2 + csel;
            ldm_x4(&Ah[ks * 4], sb + G1_SA + rbase + (uint32_t)((c ^ rx) << 4));
        }
    }

    int row0 = r0 + wid * 16 + (lane >> 2);
    int row1 = row0 + 8;
#pragma unroll
    for (int nt = 0; nt < 32; nt++) {
        uint32_t B[8];
        {
            int nrow = nt * 8 + (lane & 7);
            uint32_t rbase = (uint32_t)nrow * 128;
            int rx = nrow & 7;
            int csel = lane >> 3;
#pragma unroll
            for (int kp = 0; kp < 2; kp++) {
                int c = kp * 4 + csel;
                ldm_x4(&B[kp * 4], sb + G1_SB + rbase + (uint32_t)((c ^ rx) << 4));
            }
        }
        float accE[4] = {0, 0, 0, 0}, accO[4] = {0, 0, 0, 0};
#pragma unroll
        for (int ks = 0; ks < 4; ks++)
            mma_f16((ks & 1) ? accO : accE, &Ah[ks * 4], &B[ks * 2]);
        int col = nt * 8 + ((lane & 3) << 1);
        float bx = b1[col], by = b1[col + 1];
        if (row0 < N_NODES)
            *(uint32_t*)(g_h1h + (size_t)row0 * 256 + col) =
                pack2h(fmaxf(accE[0] + accO[0] + bx, 0.f), fmaxf(accE[1] + accO[1] + by, 0.f));
        if (row1 < N_NODES)
            *(uint32_t*)(g_h1h + (size_t)row1 * 256 + col) =
                pack2h(fmaxf(accE[2] + accO[2] + bx, 0.f), fmaxf(accE[3] + accO[3] + by, 0.f));
    }
}

// ---------------- layer-2 aggregation: fp16 gather (1 uint4/lane/edge), fp32 accumulate ----------------
__global__ void k_agg256() {
    int w = (blockIdx.x * blockDim.x + threadIdx.x) >> 5;
    int lane = threadIdx.x & 31;
    if (w >= N_NODES) return;
    int beg = g_off[w], end = g_off[w + 1];
    float a[8] = {0, 0, 0, 0, 0, 0, 0, 0};
    float b[8] = {0, 0, 0, 0, 0, 0, 0, 0};
    int e = beg;
    for (; e + 1 < end; e += 2) {
        int s0 = g_csrc[e] & 0xFFFFF;
        int s1 = g_csrc[e + 1] & 0xFFFFF;
        uint4 q0 = *(const uint4*)(g_h1h + (size_t)s0 * 256 + lane * 8);
        uint4 q1 = *(const uint4*)(g_h1h + (size_t)s1 * 256 + lane * 8);
        add_h2x4(a, q0);
        add_h2x4(b, q1);
    }
    if (e < end) {
        int s0 = g_csrc[e] & 0xFFFFF;
        uint4 q0 = *(const uint4*)(g_h1h + (size_t)s0 * 256 + lane * 8);
        add_h2x4(a, q0);
    }
    float inv = 1.f / fmaxf((float)(end - beg), 1.f);
#pragma unroll
    for (int j = 0; j < 8; j++) a[j] = (a[j] + b[j]) * inv;
    uint32_t hw[4];
    pack8h(a, hw);
    *(uint4*)(g_agg256h + (size_t)w * 256 + lane * 8) = make_uint4(hw[0], hw[1], hw[2], hw[3]);
}

// =====================================================================================
// k_gemm2uv_mma: FUSED  h2 = relu([agg256|h1]@[W2l;W2r]+b2);  uv = h2 @ Wuv -> fp16 uv
// =====================================================================================
#define F_SA     0
#define F_SB     32768
#define F_A2     0
#define F_BUV    32768
#define F_SMEM   98304

__global__ __launch_bounds__(256, 1)
void k_gemm2uv_mma(const float* __restrict__ b2) {
    extern __shared__ char smem[];
    uint32_t sb = smem_u32(smem);
    int tid = threadIdx.x, wid = tid >> 5, lane = tid & 31;
    int r0 = blockIdx.x * 128;

    float acc[16][4];
#pragma unroll
    for (int nt = 0; nt < 16; nt++)
#pragma unroll
        for (int j = 0; j < 4; j++) acc[nt][j] = 0.f;

    for (int kc = 0; kc < 4; kc++) {
        if (kc) __syncthreads();
        {
            int m = tid >> 1, h = tid & 1;
            int node = min(r0 + m, N_NODES - 1);
            const __half* src = ((kc < 2) ? (g_agg256h + (size_t)node * 256 + kc * 128)
                                          : (g_h1h + (size_t)node * 256 + (kc - 2) * 128)) + h * 64;
#pragma unroll
            for (int c = 0; c < 8; c++) {
                int chunk = h * 8 + c;
                uint32_t off = (uint32_t)m * 256 + (uint32_t)((chunk ^ (m & 7)) << 4);
                *(uint4*)(smem + F_SA + off) = *(const uint4*)(src + c * 8);
            }
        }
        {
            int n = tid >> 1, h = tid & 1;
            const __half* src = g_w2 + (size_t)n * 512 + kc * 128 + h * 64;
#pragma unroll
            for (int c = 0; c < 8; c++) {
                int chunk = h * 8 + c;
                uint32_t off = (uint32_t)n * 256 + (uint32_t)((chunk ^ (n & 7)) << 4);
                *(uint4*)(smem + F_SB + off) = *(const uint4*)(src + c * 8);
            }
        }
        __syncthreads();

        uint32_t Ah[32];
        {
            int rowA = wid * 16 + (lane & 15);
            uint32_t rbase = (uint32_t)rowA * 256;
            int rx = rowA & 7;
            int csel = lane >> 4;
#pragma unroll
            for (int ks = 0; ks < 8; ks++) {
                int chunk = ks * 2 + csel;
                ldm_x4(&Ah[ks * 4], sb + F_SA + rbase + (uint32_t)((chunk ^ rx) << 4));
            }
        }
#pragma unroll
        for (int nt = 0; nt < 16; nt++) {
            uint32_t B[16];
            {
                int nrow = nt * 8 + (lane & 7);
                uint32_t rbase = (uint32_t)nrow * 256;
                int rx = nrow & 7;
                int csel = lane >> 3;
#pragma unroll
                for (int kp = 0; kp < 4; kp++) {
                    int chunk = kp * 4 + csel;
                    ldm_x4(&B[kp * 4], sb + F_SB + rbase + (uint32_t)((chunk ^ rx) << 4));
                }
            }
            float accE[4] = {0, 0, 0, 0}, accO[4] = {0, 0, 0, 0};
#pragma unroll
            for (int ks = 0; ks < 8; ks++)
                mma_f16((ks & 1) ? accO : accE, &Ah[ks * 4], &B[ks * 2]);
#pragma unroll
            for (int j = 0; j < 4; j++) acc[nt][j] += accE[j] + accO[j];
        }
    }
    __syncthreads();

    // ---------------- phase 2: h2 -> A2 smem (single fp16), Buv load, GEMM -> g_uvh ----------------
    {
        int n = tid;
        const __half* src = g_wuv + (size_t)n * 128;
#pragma unroll
        for (int c = 0; c < 16; c++) {
            uint32_t off = (uint32_t)n * 256 + (uint32_t)((c ^ (n & 7)) << 4);
            *(uint4*)(smem + F_BUV + off) = *(const uint4*)(src + c * 8);
        }
    }
    {
        int rloc0 = wid * 16 + (lane >> 2);
        int rloc1 = rloc0 + 8;
        int rx0 = rloc0 & 7, rx1 = rloc1 & 7;
#pragma unroll
        for (int nt = 0; nt < 16; nt++) {
            int c = nt * 8 + ((lane & 3) << 1);
            float bx = b2[c], by = b2[c + 1];
            float v0x = fmaxf(acc[nt][0] + bx, 0.f), v0y = fmaxf(acc[nt][1] + by, 0.f);
            float v1x = fmaxf(acc[nt][2] + bx, 0.f), v1y = fmaxf(acc[nt][3] + by, 0.f);
            uint32_t base0 = (uint32_t)rloc0 * 256 + (uint32_t)((((c >> 3) ^ rx0)) << 4) + (uint32_t)(c & 7) * 2;
            *(uint32_t*)(smem + F_A2 + base0) = pack2h(v0x, v0y);
            uint32_t base1 = (uint32_t)rloc1 * 256 + (uint32_t)((((c >> 3) ^ rx1)) << 4) + (uint32_t)(c & 7) * 2;
            *(uint32_t*)(smem + F_A2 + base1) = pack2h(v1x, v1y);
        }
    }
    __syncthreads();

    uint32_t Ah[32];
    {
        int rowA = wid * 16 + (lane & 15);
        uint32_t rbase = (uint32_t)rowA * 256;
        int rx = rowA & 7;
        int csel = lane >> 4;
#pragma unroll
        for (int ks = 0; ks < 8; ks++) {
            int chunk = ks * 2 + csel;
            ldm_x4(&Ah[ks * 4], sb + F_A2 + rbase + (uint32_t)((chunk ^ rx) << 4));
        }
    }
    int row0 = r0 + wid * 16 + (lane >> 2);
    int row1 = row0 + 8;
#pragma unroll
    for (int nt = 0; nt < 32; nt++) {
        uint32_t B[16];
        {
            int nrow = nt * 8 + (lane & 7);
            uint32_t rbase = (uint32_t)nrow * 256;
            int rx = nrow & 7;
            int csel = lane >> 3;
#pragma unroll
            for (int kp = 0; kp < 4; kp++) {
                int chunk = kp * 4 + csel;
                ldm_x4(&B[kp * 4], sb + F_BUV + rbase + (uint32_t)((chunk ^ rx) << 4));
            }
        }
        float accE[4] = {0, 0, 0, 0}, accO[4] = {0, 0, 0, 0};
#pragma unroll
        for (int ks = 0; ks < 8; ks++)
            mma_f16((ks & 1) ? accO : accE, &Ah[ks * 4], &B[ks * 2]);
        int col = nt * 8 + ((lane & 3) << 1);
        if (row0 < N_NODES)
            *(uint32_t*)(g_uvh + (size_t)row0 * 256 + col) = pack2h(accE[0] + accO[0], accE[1] + accO[1]);
        if (row1 < N_NODES)
            *(uint32_t*)(g_uvh + (size_t)row1 * 256 + col) = pack2h(accE[2] + accO[2], accE[3] + accO[3]);
    }
}

// =====================================================================================
// k_edge_mma: edge classifier, single-fp16 A x fp16 B; M=256/CTA with 256 threads;
// warp owns 32 rows (2 m-tiles) sharing each B fragment. Full B (141KB) in SMEM.
// uv read as fp16 (halved gather traffic).
// =====================================================================================
#define EM_M     256
#define SM_A     0
#define SM_B     65536
#define SM_EDGE_TOTAL (65536 + 552 * 256)   // 206848

__global__ __launch_bounds__(256, 1)
void k_edge_mma(const int* __restrict__ egt, const float* __restrict__ bc1,
                const float* __restrict__ bc2, float* __restrict__ out) {
    extern __shared__ char smem[];
    uint32_t sb = smem_u32(smem);
    int tid = threadIdx.x, wid = tid >> 5, lane = tid & 31;
    int e0 = blockIdx.x * EM_M;

    // async-load the full B (552 rows x 128 k fp16), overlapped with A prep
    for (int id = tid; id < 552 * 16; id += 256) {
        int n = id >> 4, c = id & 15;
        uint32_t dst = sb + SM_B + (uint32_t)n * 256 + (uint32_t)((c ^ (n & 7)) << 4);
        cp16(dst, g_wc2 + (size_t)n * 128 + c * 8);
    }
    CP_COMMIT();

    // A prep: z = relu(u[s]+v[d]+bc1) -> fp16 (256 rows, 2 passes of 128); uv fp16 loads
    {
        int h = tid & 1;
        const float* bp = bc1 + h * 64;
        for (int m = tid >> 1; m < EM_M; m += 128) {
            int er = e0 + m;
            int s = 0, d = 0;
            if (er < EGT) { s = egt[er]; d = egt[EGT + er]; }
            const __half* up = g_uvh + (size_t)s * 256 + h * 64;
            const __half* vp = g_uvh + (size_t)d * 256 + 128 + h * 64;
#pragma unroll
            for (int kk = 0; kk < 64; kk += 8) {
                uint4 qu = *(const uint4*)(up + kk);
                uint4 qv = *(const uint4*)(vp + kk);
                float fu[8], fv[8], z[8];
                unpack8h(qu, fu);
                unpack8h(qv, fv);
#pragma unroll
                for (int j = 0; j < 8; j++)
                    z[j] = fmaxf(fu[j] + fv[j] + bp[kk + j], 0.f);
                uint32_t hw[4];
                pack8h(z, hw);
                int chunk = h * 8 + (kk >> 3);
                uint32_t off = (uint32_t)m * 256 + (uint32_t)((chunk ^ (m & 7)) << 4);
                *(uint4*)(smem + SM_A + off) = make_uint4(hw[0], hw[1], hw[2], hw[3]);
            }
        }
    }
    CP_WAIT0();
    __syncthreads();   // A + B smem visible

    // A fragments: warp owns rows [wid*32, wid*32+32) = 2 m-tiles
    uint32_t Ah[2][32];
#pragma unroll
    for (int t = 0; t < 2; t++) {
        int rowA = wid * 32 + t * 16 + (lane & 15);
        uint32_t rbase = (uint32_t)rowA * 256;
        int rx = rowA & 7;
        int csel = lane >> 4;
#pragma unroll
        for (int ks = 0; ks < 8; ks++) {
            int chunk = ks * 2 + csel;
            ldm_x4(&Ah[t][ks * 4], sb + SM_A + rbase + (uint32_t)((chunk ^ rx) << 4));
        }
    }

    int rbase0 = e0 + wid * 32 + (lane >> 2);
    float* op[4];
    bool vv[4];
#pragma unroll
    for (int t = 0; t < 2; t++) {
        int ra = rbase0 + t * 16, rb = ra + 8;
        vv[2 * t] = ra < EGT;
        vv[2 * t + 1] = rb < EGT;
        op[2 * t] = out + (size_t)ra * 552;
        op[2 * t + 1] = out + (size_t)rb * 552;
    }

    for (int jt = 0; jt < 69; jt++) {
        uint32_t B[16];
        {
            int nrow = jt * 8 + (lane & 7);
            uint32_t rbase = sb + SM_B + (uint32_t)nrow * 256;
            int rx = nrow & 7;
            int csel = lane >> 3;
#pragma unroll
            for (int kp = 0; kp < 4; kp++) {
                int chunk = kp * 4 + csel;
                ldm_x4(&B[kp * 4], rbase + (uint32_t)((chunk ^ rx) << 4));
            }
        }
        int col = jt * 8 + ((lane & 3) << 1);
        float bx = bc2[col], by = bc2[col + 1];
#pragma unroll
        for (int t = 0; t < 2; t++) {
            float accE[4] = {0, 0, 0, 0}, accO[4] = {0, 0, 0, 0};
#pragma unroll
            for (int ks = 0; ks < 8; ks++)
                mma_f16((ks & 1) ? accO : accE, &Ah[t][ks * 4], &B[ks * 2]);
            if (vv[2 * t]) {
                float2 o0 = {sigf(accE[0] + accO[0] + bx), sigf(accE[1] + accO[1] + by)};
                *(float2*)(op[2 * t] + col) = o0;
            }
            if (vv[2 * t + 1]) {
                float2 o1 = {sigf(accE[2] + accO[2] + bx), sigf(accE[3] + accO[3] + by)};
                *(float2*)(op[2 * t + 1] + col) = o1;
            }
        }
    }
}

// ---------------- launch ----------------
extern "C" void kernel_launch(void* const* d_in, const int* in_sizes, int n_in,
                              void* d_out, int out_size) {
    const float* x    = (const float*)d_in[0];
    const int*   ei   = (const int*)  d_in[1];
    const int*   egt  = (const int*)  d_in[2];
    const int*   ef   = (const int*)  d_in[3];
    const float* embT = (const float*)d_in[4];
    const float* embA = (const float*)d_in[5];
    const float* W1l  = (const float*)d_in[6];
    const float* W1r  = (const float*)d_in[7];
    const float* b1   = (const float*)d_in[8];
    const float* W2l  = (const float*)d_in[9];
    const float* W2r  = (const float*)d_in[10];
    const float* b2   = (const float*)d_in[11];
    const float* Wc1  = (const float*)d_in[12];
    const float* bc1  = (const float*)d_in[13];
    const float* Wc2  = (const float*)d_in[14];
    const float* bc2  = (const float*)d_in[15];
    float* out = (float*)d_out;

    cudaFuncSetAttribute(k_gemm1_mma, cudaFuncAttributeMaxDynamicSharedMemorySize, G1_SMEM);
    cudaFuncSetAttribute(k_gemm2uv_mma, cudaFuncAttributeMaxDynamicSharedMemorySize, F_SMEM);
    cudaFuncSetAttribute(k_edge_mma, cudaFuncAttributeMaxDynamicSharedMemorySize, SM_EDGE_TOTAL);

    k_prep<<<(552 * 128 + 255) / 256, 256>>>(Wc2, W2l, W2r, Wc1, W1l, W1r);
    k_count<<<(E_EDGES + 255) / 256, 256>>>(ei);
    k_scan2<<<2, 1024>>>();
    k_scatter2<<<(E_EDGES + 255) / 256, 256>>>(ei, ef);
    k_h0build<<<(N_NODES + 255) / 256, 256>>>(x, embT, embA);
    k_agg24<<<(N_NODES * 32 + 255) / 256, 256>>>();
    k_gemm1_mma<<<(N_NODES + 127) / 128, 256, G1_SMEM>>>(b1);
    k_agg256<<<(N_NODES * 32 + 255) / 256, 256>>>();
    k_gemm2uv_mma<<<(N_NODES + 127) / 128, 256, F_SMEM>>>(b2);
    k_edge_mma<<<(EGT + EM_M - 1) / EM_M, 256, SM_EDGE_TOTAL>>>(egt, bc1, bc2, out);
}

// round 13
// speedup vs baseline: 2.1407x; 1.0298x over previous
#include <cuda_runtime.h>
#include <cuda_fp16.h>
#include <cstdint>

#define N_NODES 50000
#define E_EDGES 800000
#define EGT     200000
#define NPAD    53248      // 1024 threads * 52 (CH), multiple of 4

// ---------------- scratch (static device globals; no allocation) ----------------
__device__ float g_h0[N_NODES * 24];        // [x(16) | agg_trigger(4) | agg_action(4)]
__device__ int   g_degd[NPAD];
__device__ int   g_degs[NPAD];
__device__ int   g_curd[N_NODES];
__device__ int   g_curs[N_NODES];
__device__ int   g_off[NPAD + 4];           // CSR by dst
__device__ int   g_offs[NPAD + 4];          // CSR by src
__device__ int   g_csrc[E_EDGES];           // per in-edge: src | (action<<20)
__device__ int   g_strig[E_EDGES];          // per out-edge: trigger code
__device__ float g_agg24[N_NODES * 24];
__device__ __half g_h1h[N_NODES * 256];     // h1 fp16
__device__ __half g_agg256h[N_NODES * 256]; // agg256 fp16
__device__ __half g_uvh[N_NODES * 256];     // [u(128) | v(128)] per node, fp16
__device__ __half g_wc2[552 * 128];         // Wc2^T fp16, [n][k]
__device__ __half g_w2[128 * 512];          // [W2l;W2r]^T fp16, [n][k]
__device__ __half g_wuv[256 * 128];         // [Wc1_top|Wc1_bot]^T fp16, [n][k]
__device__ __half g_w1[256 * 64];           // [W1l;W1r]^T fp16, [n][k] (k padded 48->64)

// ======================= warp-MMA + async helpers (baseline PTX, sm_80+) =======================
__device__ __forceinline__ uint32_t smem_u32(const void* p) {
    uint32_t a;
    asm("{ .reg .u64 t; cvta.to.shared.u64 t, %1; cvt.u32.u64 %0, t; }" : "=r"(a) : "l"(p));
    return a;
}
__device__ __forceinline__ void ldm_x4(uint32_t* r, uint32_t addr) {
    asm volatile("ldmatrix.sync.aligned.m8n8.x4.shared.b16 {%0,%1,%2,%3}, [%4];"
        : "=r"(r[0]), "=r"(r[1]), "=r"(r[2]), "=r"(r[3]) : "r"(addr));
}
__device__ __forceinline__ void mma_f16(float* c, const uint32_t* a, const uint32_t* b) {
    asm volatile(
        "mma.sync.aligned.m16n8k16.row.col.f32.f16.f16.f32 "
        "{%0,%1,%2,%3}, {%4,%5,%6,%7}, {%8,%9}, {%0,%1,%2,%3};"
        : "+f"(c[0]), "+f"(c[1]), "+f"(c[2]), "+f"(c[3])
        : "r"(a[0]), "r"(a[1]), "r"(a[2]), "r"(a[3]), "r"(b[0]), "r"(b[1]));
}
__device__ __forceinline__ void cp16(uint32_t dst, const void* src) {
    asm volatile("cp.async.cg.shared.global [%0], [%1], 16;" :: "r"(dst), "l"(src));
}
#define CP_COMMIT() asm volatile("cp.async.commit_group;" ::: "memory")
#define CP_WAIT0()  asm volatile("cp.async.wait_group 0;" ::: "memory")
__device__ __forceinline__ float sigf(float x) { return __fdividef(1.f, 1.f + __expf(-x)); }
__device__ __forceinline__ void st_cs2(float* p, float x, float y) {
    asm volatile("st.global.cs.v2.f32 [%0], {%1, %2};" :: "l"(p), "f"(x), "f"(y) : "memory");
}

// pack 8 floats to fp16 (no split)
__device__ __forceinline__ void pack8h(const float* z, uint32_t* hw) {
#pragma unroll
    for (int p = 0; p < 4; p++) {
        __half2 hh = __halves2half2(__float2half(z[2 * p]), __float2half(z[2 * p + 1]));
        hw[p] = *reinterpret_cast<uint32_t*>(&hh);
    }
}
__device__ __forceinline__ uint32_t pack2h(float x, float y) {
    __half2 hh = __halves2half2(__float2half(x), __float2half(y));
    return *reinterpret_cast<uint32_t*>(&hh);
}
__device__ __forceinline__ void add_h2x4(float* acc, uint4 q) {
    const __half2* h = reinterpret_cast<const __half2*>(&q);
#pragma unroll
    for (int p = 0; p < 4; p++) {
        float2 f = __half22float2(h[p]);
        acc[2 * p] += f.x;
        acc[2 * p + 1] += f.y;
    }
}
__device__ __forceinline__ void unpack8h(uint4 q, float* f) {
    const __half2* h = reinterpret_cast<const __half2*>(&q);
#pragma unroll
    for (int p = 0; p < 4; p++) {
        float2 v = __half22float2(h[p]);
        f[2 * p] = v.x;
        f[2 * p + 1] = v.y;
    }
}

// ---------------- fused prep: counters + weight transposes + degree count ----------------
__global__ void k_prep(const float* __restrict__ Wc2, const float* __restrict__ W2l,
                       const float* __restrict__ W2r, const float* __restrict__ Wc1,
                       const float* __restrict__ W1l, const float* __restrict__ W1r,
                       const int* __restrict__ ei) {
    int i = blockIdx.x * blockDim.x + threadIdx.x;
    if (i < NPAD) { g_degd[i] = 0; g_degs[i] = 0; }
    if (i < N_NODES) { g_curd[i] = 0; g_curs[i] = 0; }
    if (i < 552 * 128) {
        int n = i >> 7, k = i & 127;
        g_wc2[i] = __float2half(Wc2[(size_t)k * 552 + n]);
    }
    if (i < 128 * 512) {
        int n = i >> 9, k = i & 511;
        float w = (k < 256) ? W2l[(size_t)k * 128 + n] : W2r[(size_t)(k - 256) * 128 + n];
        g_w2[i] = __float2half(w);
    }
    if (i < 256 * 128) {
        int n = i >> 7, k = i & 127;
        float w = (n < 128) ? Wc1[(size_t)k * 128 + n] : Wc1[(size_t)(128 + k) * 128 + (n - 128)];
        g_wuv[i] = __float2half(w);
    }
    if (i < 256 * 64) {
        int n = i >> 6, k = i & 63;
        float w = 0.f;
        if (k < 24) w = W1l[(size_t)k * 256 + n];
        else if (k < 48) w = W1r[(size_t)(k - 24) * 256 + n];
        g_w1[i] = __float2half(w);
    }
}

// ---------------- degree count (needs zeroed counters from k_prep) ----------------
__global__ void k_count(const int* __restrict__ ei) {
    int e = blockIdx.x * blockDim.x + threadIdx.x;
    if (e >= E_EDGES) return;
    atomicAdd(&g_degs[ei[e]], 1);
    atomicAdd(&g_degd[ei[E_EDGES + e]], 1);
}

// ---------------- dual scan: blockIdx.x = 0 (dst-CSR) / 1 (src-CSR), int4 vectorized ----------------
__global__ void k_scan2() {
    int which = blockIdx.x;
    const int* deg = which ? g_degs : g_degd;
    int* off = which ? g_offs : g_off;
    const int CH = 52;
    int tid = threadIdx.x, lane = tid & 31, wid = tid >> 5;
    int beg = tid * CH;
    int sum = 0;
#pragma unroll
    for (int i = 0; i < CH; i += 4) {
        int4 v = *(const int4*)(deg + beg + i);
        sum += v.x + v.y + v.z + v.w;
    }
    int v = sum;
#pragma unroll
    for (int o = 1; o < 32; o <<= 1) {
        int t = __shfl_up_sync(0xFFFFFFFFu, v, o);
        if (lane >= o) v += t;
    }
    __shared__ int wsum[32];
    if (lane == 31) wsum[wid] = v;
    __syncthreads();
    if (wid == 0) {
        int w = wsum[lane];
#pragma unroll
        for (int o = 1; o < 32; o <<= 1) {
            int t = __shfl_up_sync(0xFFFFFFFFu, w, o);
            if (lane >= o) w += t;
        }
        wsum[lane] = w;
    }
    __syncthreads();
    int base = v - sum + (wid ? wsum[wid - 1] : 0);
#pragma unroll
    for (int i = 0; i < CH; i += 4) {
        int4 d = *(const int4*)(deg + beg + i);
        int4 o;
        o.x = base;
        o.y = o.x + d.x;
        o.z = o.y + d.y;
        o.w = o.z + d.z;
        base = o.w + d.w;
        *(int4*)(off + beg + i) = o;
    }
}

// ---------------- scatter both CSRs (action packed into csrc high bits) ----------------
__global__ void k_scatter2(const int* __restrict__ ei, const int* __restrict__ ef) {
    int e = blockIdx.x * blockDim.x + threadIdx.x;
    if (e >= E_EDGES) return;
    int s = ei[e], d = ei[E_EDGES + e];
    int t = ef[2 * e], a = ef[2 * e + 1];
    int posd = g_off[d] + atomicAdd(&g_curd[d], 1);
    g_csrc[posd] = s | (a << 20);
    int poss = g_offs[s] + atomicAdd(&g_curs[s], 1);
    g_strig[poss] = t;
}

// ---------------- h0 build: x copy + trigger/action gather-reduce (no atomics) ----------------
__global__ void k_h0build(const float* __restrict__ x,
                          const float* __restrict__ embT, const float* __restrict__ embA) {
    int n = blockIdx.x * blockDim.x + threadIdx.x;
    if (n >= N_NODES) return;
    float* h0 = g_h0 + (size_t)n * 24;
    const float4* xp = (const float4*)(x + (size_t)n * 16);
#pragma unroll
    for (int j = 0; j < 4; j++) ((float4*)h0)[j] = xp[j];
    float4 trig = make_float4(0, 0, 0, 0);
    int b0 = g_offs[n], e0 = g_offs[n + 1];
    for (int e = b0; e < e0; e++) {
        int t = g_strig[e];
        float4 v = *(const float4*)(embT + (size_t)t * 4);
        trig.x += v.x; trig.y += v.y; trig.z += v.z; trig.w += v.w;
    }
    float4 act = make_float4(0, 0, 0, 0);
    int b1 = g_off[n], e1 = g_off[n + 1];
    for (int e = b1; e < e1; e++) {
        int a = g_csrc[e] >> 20;
        float4 v = *(const float4*)(embA + (size_t)a * 4);
        act.x += v.x; act.y += v.y; act.z += v.z; act.w += v.w;
    }
    ((float4*)h0)[4] = trig;
    ((float4*)h0)[5] = act;
}

// ---------------- layer-1 aggregation in 24-dim space (warp per node, 2-way unroll) ----------------
__global__ void k_agg24() {
    int w = (blockIdx.x * blockDim.x + threadIdx.x) >> 5;
    int lane = threadIdx.x & 31;
    if (w >= N_NODES) return;
    int beg = g_off[w], end = g_off[w + 1];
    if (lane < 24) {
        float acc0 = 0.f, acc1 = 0.f;
        int e = beg;
        for (; e + 1 < end; e += 2) {
            int s0 = g_csrc[e] & 0xFFFFF;
            int s1 = g_csrc[e + 1] & 0xFFFFF;
            acc0 += g_h0[s0 * 24 + lane];
            acc1 += g_h0[s1 * 24 + lane];
        }
        if (e < end) acc0 += g_h0[(g_csrc[e] & 0xFFFFF) * 24 + lane];
        float inv = 1.f / fmaxf((float)(end - beg), 1.f);
        g_agg24[w * 24 + lane] = (acc0 + acc1) * inv;
    }
}

// =====================================================================================
// k_gemm1_mma: h1 = relu([agg24|h0] @ [W1l;W1r] + b1), single-fp16 A x fp16 B -> fp16 h1
// =====================================================================================
#define G1_SA   0
#define G1_SB   16384
#define G1_SMEM 49152

__global__ __launch_bounds__(256, 1)
void k_gemm1_mma(const float* __restrict__ b1) {
    extern __shared__ char smem[];
    uint32_t sb = smem_u32(smem);
    int tid = threadIdx.x, wid = tid >> 5, lane = tid & 31;
    int r0 = blockIdx.x * 128;

    {
        int m = tid >> 1, h = tid & 1;
        int node = min(r0 + m, N_NODES - 1);
        const float* a24 = g_agg24 + (size_t)node * 24;
        const float* h0p = g_h0 + (size_t)node * 24;
#pragma unroll
        for (int kk = 0; kk < 32; kk += 8) {
            float z[8];
#pragma unroll
            for (int j = 0; j < 8; j++) {
                int k = h * 32 + kk + j;
                z[j] = (k < 24) ? a24[k] : ((k < 48) ? h0p[k - 24] : 0.f);
            }
            uint32_t hw[4];
            pack8h(z, hw);
            int c = h * 4 + (kk >> 3);
            uint32_t off = (uint32_t)m * 128 + (uint32_t)((c ^ (m & 7)) << 4);
            *(uint4*)(smem + G1_SA + off) = make_uint4(hw[0], hw[1], hw[2], hw[3]);
        }
    }
    {
        int n = tid;
        const __half* src = g_w1 + (size_t)n * 64;
#pragma unroll
        for (int c = 0; c < 8; c++) {
            uint32_t off = (uint32_t)n * 128 + (uint32_t)((c ^ (n & 7)) << 4);
            *(uint4*)(smem + G1_SB + off) = *(const uint4*)(src + c * 8);
        }
    }
    __syncthreads();

    uint32_t Ah[16];
    {
        int rowA = wid * 16 + (lane & 15);
        uint32_t rbase = (uint32_t)rowA * 128;
        int rx = rowA & 7;
        int csel = lane >> 4;
#pragma unroll
        for (int ks = 0; ks < 4; ks++) {
            int c = ks * 2 + csel;
            ldm_x4(&Ah[ks * 4], sb + G1_SA + rbase + (uint32_t)((c ^ rx) << 4));
        }
    }

    int row0 = r0 + wid * 16 + (lane >> 2);
    int row1 = row0 + 8;
#pragma unroll
    for (int nt = 0; nt < 32; nt++) {
        uint32_t B[8];
        {
            int nrow = nt * 8 + (lane & 7);
            uint32_t rbase = (uint32_t)nrow * 128;
            int rx = nrow & 7;
            int csel = lane >> 3;
#pragma unroll
            for (int kp = 0; kp < 2; kp++) {
                int c = kp * 4 + csel;
                ldm_x4(&B[kp * 4], sb + G1_SB + rbase + (uint32_t)((c ^ rx) << 4));
            }
        }
        float accE[4] = {0, 0, 0, 0}, accO[4] = {0, 0, 0, 0};
#pragma unroll
        for (int ks = 0; ks < 4; ks++)
            mma_f16((ks & 1) ? accO : accE, &Ah[ks * 4], &B[ks * 2]);
        int col = nt * 8 + ((lane & 3) << 1);
        float bx = b1[col], by = b1[col + 1];
        if (row0 < N_NODES)
            *(uint32_t*)(g_h1h + (size_t)row0 * 256 + col) =
                pack2h(fmaxf(accE[0] + accO[0] + bx, 0.f), fmaxf(accE[1] + accO[1] + by, 0.f));
        if (row1 < N_NODES)
            *(uint32_t*)(g_h1h + (size_t)row1 * 256 + col) =
                pack2h(fmaxf(accE[2] + accO[2] + bx, 0.f), fmaxf(accE[3] + accO[3] + by, 0.f));
    }
}

// ---------------- layer-2 aggregation: fp16 gather (1 uint4/lane/edge), fp32 accumulate ----------------
__global__ void k_agg256() {
    int w = (blockIdx.x * blockDim.x + threadIdx.x) >> 5;
    int lane = threadIdx.x & 31;
    if (w >= N_NODES) return;
    int beg = g_off[w], end = g_off[w + 1];
    float a[8] = {0, 0, 0, 0, 0, 0, 0, 0};
    float b[8] = {0, 0, 0, 0, 0, 0, 0, 0};
    int e = beg;
    for (; e + 1 < end; e += 2) {
        int s0 = g_csrc[e] & 0xFFFFF;
        int s1 = g_csrc[e + 1] & 0xFFFFF;
        uint4 q0 = *(const uint4*)(g_h1h + (size_t)s0 * 256 + lane * 8);
        uint4 q1 = *(const uint4*)(g_h1h + (size_t)s1 * 256 + lane * 8);
        add_h2x4(a, q0);
        add_h2x4(b, q1);
    }
    if (e < end) {
        int s0 = g_csrc[e] & 0xFFFFF;
        uint4 q0 = *(const uint4*)(g_h1h + (size_t)s0 * 256 + lane * 8);
        add_h2x4(a, q0);
    }
    float inv = 1.f / fmaxf((float)(end - beg), 1.f);
#pragma unroll
    for (int j = 0; j < 8; j++) a[j] = (a[j] + b[j]) * inv;
    uint32_t hw[4];
    pack8h(a, hw);
    *(uint4*)(g_agg256h + (size_t)w * 256 + lane * 8) = make_uint4(hw[0], hw[1], hw[2], hw[3]);
}

// =====================================================================================
// k_gemm2uv_mma: FUSED  h2 = relu([agg256|h1]@[W2l;W2r]+b2);  uv = h2 @ Wuv -> fp16 uv
// =====================================================================================
#define F_SA     0
#define F_SB     32768
#define F_A2     0
#define F_BUV    32768
#define F_SMEM   98304

__global__ __launch_bounds__(256, 1)
void k_gemm2uv_mma(const float* __restrict__ b2) {
    extern __shared__ char smem[];
    uint32_t sb = smem_u32(smem);
    int tid = threadIdx.x, wid = tid >> 5, lane = tid & 31;
    int r0 = blockIdx.x * 128;

    float acc[16][4];
#pragma unroll
    for (int nt = 0; nt < 16; nt++)
#pragma unroll
        for (int j = 0; j < 4; j++) acc[nt][j] = 0.f;

    for (int kc = 0; kc < 4; kc++) {
        if (kc) __syncthreads();
        {
            int m = tid >> 1, h = tid & 1;
            int node = min(r0 + m, N_NODES - 1);
            const __half* src = ((kc < 2) ? (g_agg256h + (size_t)node * 256 + kc * 128)
                                          : (g_h1h + (size_t)node * 256 + (kc - 2) * 128)) + h * 64;
#pragma unroll
            for (int c = 0; c < 8; c++) {
                int chunk = h * 8 + c;
                uint32_t off = (uint32_t)m * 256 + (uint32_t)((chunk ^ (m & 7)) << 4);
                *(uint4*)(smem + F_SA + off) = *(const uint4*)(src + c * 8);
            }
        }
        {
            int n = tid >> 1, h = tid & 1;
            const __half* src = g_w2 + (size_t)n * 512 + kc * 128 + h * 64;
#pragma unroll
            for (int c = 0; c < 8; c++) {
                int chunk = h * 8 + c;
                uint32_t off = (uint32_t)n * 256 + (uint32_t)((chunk ^ (n & 7)) << 4);
                *(uint4*)(smem + F_SB + off) = *(const uint4*)(src + c * 8);
            }
        }
        __syncthreads();

        uint32_t Ah[32];
        {
            int rowA = wid * 16 + (lane & 15);
            uint32_t rbase = (uint32_t)rowA * 256;
            int rx = rowA & 7;
            int csel = lane >> 4;
#pragma unroll
            for (int ks = 0; ks < 8; ks++) {
                int chunk = ks * 2 + csel;
                ldm_x4(&Ah[ks * 4], sb + F_SA + rbase + (uint32_t)((chunk ^ rx) << 4));
            }
        }
#pragma unroll
        for (int nt = 0; nt < 16; nt++) {
            uint32_t B[16];
            {
                int nrow = nt * 8 + (lane & 7);
                uint32_t rbase = (uint32_t)nrow * 256;
                int rx = nrow & 7;
                int csel = lane >> 3;
#pragma unroll
                for (int kp = 0; kp < 4; kp++) {
                    int chunk = kp * 4 + csel;
                    ldm_x4(&B[kp * 4], sb + F_SB + rbase + (uint32_t)((chunk ^ rx) << 4));
                }
            }
            float accE[4] = {0, 0, 0, 0}, accO[4] = {0, 0, 0, 0};
#pragma unroll
            for (int ks = 0; ks < 8; ks++)
                mma_f16((ks & 1) ? accO : accE, &Ah[ks * 4], &B[ks * 2]);
#pragma unroll
            for (int j = 0; j < 4; j++) acc[nt][j] += accE[j] + accO[j];
        }
    }
    __syncthreads();

    // ---------------- phase 2: h2 -> A2 smem (single fp16), Buv load, GEMM -> g_uvh ----------------
    {
        int n = tid;
        const __half* src = g_wuv + (size_t)n * 128;
#pragma unroll
        for (int c = 0; c < 16; c++) {
            uint32_t off = (uint32_t)n * 256 + (uint32_t)((c ^ (n & 7)) << 4);
            *(uint4*)(smem + F_BUV + off) = *(const uint4*)(src + c * 8);
        }
    }
    {
        int rloc0 = wid * 16 + (lane >> 2);
        int rloc1 = rloc0 + 8;
        int rx0 = rloc0 & 7, rx1 = rloc1 & 7;
#pragma unroll
        for (int nt = 0; nt < 16; nt++) {
            int c = nt * 8 + ((lane & 3) << 1);
            float bx = b2[c], by = b2[c + 1];
            float v0x = fmaxf(acc[nt][0] + bx, 0.f), v0y = fmaxf(acc[nt][1] + by, 0.f);
            float v1x = fmaxf(acc[nt][2] + bx, 0.f), v1y = fmaxf(acc[nt][3] + by, 0.f);
            uint32_t base0 = (uint32_t)rloc0 * 256 + (uint32_t)((((c >> 3) ^ rx0)) << 4) + (uint32_t)(c & 7) * 2;
            *(uint32_t*)(smem + F_A2 + base0) = pack2h(v0x, v0y);
            uint32_t base1 = (uint32_t)rloc1 * 256 + (uint32_t)((((c >> 3) ^ rx1)) << 4) + (uint32_t)(c & 7) * 2;
            *(uint32_t*)(smem + F_A2 + base1) = pack2h(v1x, v1y);
        }
    }
    __syncthreads();

    uint32_t Ah[32];
    {
        int rowA = wid * 16 + (lane & 15);
        uint32_t rbase = (uint32_t)rowA * 256;
        int rx = rowA & 7;
        int csel = lane >> 4;
#pragma unroll
        for (int ks = 0; ks < 8; ks++) {
            int chunk = ks * 2 + csel;
            ldm_x4(&Ah[ks * 4], sb + F_A2 + rbase + (uint32_t)((chunk ^ rx) << 4));
        }
    }
    int row0 = r0 + wid * 16 + (lane >> 2);
    int row1 = row0 + 8;
#pragma unroll
    for (int nt = 0; nt < 32; nt++) {
        uint32_t B[16];
        {
            int nrow = nt * 8 + (lane & 7);
            uint32_t rbase = (uint32_t)nrow * 256;
            int rx = nrow & 7;
            int csel = lane >> 3;
#pragma unroll
            for (int kp = 0; kp < 4; kp++) {
                int chunk = kp * 4 + csel;
                ldm_x4(&B[kp * 4], sb + F_BUV + rbase + (uint32_t)((chunk ^ rx) << 4));
            }
        }
        float accE[4] = {0, 0, 0, 0}, accO[4] = {0, 0, 0, 0};
#pragma unroll
        for (int ks = 0; ks < 8; ks++)
            mma_f16((ks & 1) ? accO : accE, &Ah[ks * 4], &B[ks * 2]);
        int col = nt * 8 + ((lane & 3) << 1);
        if (row0 < N_NODES)
            *(uint32_t*)(g_uvh + (size_t)row0 * 256 + col) = pack2h(accE[0] + accO[0], accE[1] + accO[1]);
        if (row1 < N_NODES)
            *(uint32_t*)(g_uvh + (size_t)row1 * 256 + col) = pack2h(accE[2] + accO[2], accE[3] + accO[3]);
    }
}

// =====================================================================================
// k_edge_mma: PERSISTENT edge classifier; B loaded ONCE per SM; single-fp16 A x fp16 B;
// M=256/block, warp owns 32 rows (2 m-tiles); streaming fp32 output stores (st.cs).
// =====================================================================================
#define EM_M     256
#define EM_NBLK  ((EGT + EM_M - 1) / EM_M)   // 782
#define SM_A     0
#define SM_B     65536
#define SM_EDGE_TOTAL (65536 + 552 * 256)    // 206848

__global__ __launch_bounds__(256, 1)
void k_edge_mma(const int* __restrict__ egt, const float* __restrict__ bc1,
                const float* __restrict__ bc2, float* __restrict__ out) {
    extern __shared__ char smem[];
    uint32_t sb = smem_u32(smem);
    int tid = threadIdx.x, wid = tid >> 5, lane = tid & 31;

    // load full B (552 rows x 128 k fp16 = 141KB) ONCE for this CTA's lifetime
    for (int id = tid; id < 552 * 16; id += 256) {
        int n = id >> 4, c = id & 15;
        uint32_t dst = sb + SM_B + (uint32_t)n * 256 + (uint32_t)((c ^ (n & 7)) << 4);
        cp16(dst, g_wc2 + (size_t)n * 128 + c * 8);
    }
    CP_COMMIT();

    int h = tid & 1;
    const float* bp = bc1 + h * 64;
    bool first = true;

    for (int blk = blockIdx.x; blk < EM_NBLK; blk += gridDim.x) {
        int e0 = blk * EM_M;

        if (!first) __syncthreads();   // all warps done reading A smem of previous block
        // A prep: z = relu(u[s]+v[d]+bc1) -> fp16 (256 rows, 2 passes of 128)
        for (int m = tid >> 1; m < EM_M; m += 128) {
            int er = e0 + m;
            int s = 0, d = 0;
            if (er < EGT) { s = egt[er]; d = egt[EGT + er]; }
            const __half* up = g_uvh + (size_t)s * 256 + h * 64;
            const __half* vp = g_uvh + (size_t)d * 256 + 128 + h * 64;
#pragma unroll
            for (int kk = 0; kk < 64; kk += 8) {
                uint4 qu = *(const uint4*)(up + kk);
                uint4 qv = *(const uint4*)(vp + kk);
                float fu[8], fv[8], z[8];
                unpack8h(qu, fu);
                unpack8h(qv, fv);
#pragma unroll
                for (int j = 0; j < 8; j++)
                    z[j] = fmaxf(fu[j] + fv[j] + bp[kk + j], 0.f);
                uint32_t hw[4];
                pack8h(z, hw);
                int chunk = h * 8 + (kk >> 3);
                uint32_t off = (uint32_t)m * 256 + (uint32_t)((chunk ^ (m & 7)) << 4);
                *(uint4*)(smem + SM_A + off) = make_uint4(hw[0], hw[1], hw[2], hw[3]);
            }
        }
        if (first) { CP_WAIT0(); first = false; }
        __syncthreads();   // A (+B on first iter) visible

        // A fragments: warp owns rows [wid*32, wid*32+32) = 2 m-tiles
        uint32_t Ah[2][32];
#pragma unroll
        for (int t = 0; t < 2; t++) {
            int rowA = wid * 32 + t * 16 + (lane & 15);
            uint32_t rbase = (uint32_t)rowA * 256;
            int rx = rowA & 7;
            int csel = lane >> 4;
#pragma unroll
            for (int ks = 0; ks < 8; ks++) {
                int chunk = ks * 2 + csel;
                ldm_x4(&Ah[t][ks * 4], sb + SM_A + rbase + (uint32_t)((chunk ^ rx) << 4));
            }
        }

        int rbase0 = e0 + wid * 32 + (lane >> 2);
        float* op[4];
        bool vv[4];
#pragma unroll
        for (int t = 0; t < 2; t++) {
            int ra = rbase0 + t * 16, rb = ra + 8;
            vv[2 * t] = ra < EGT;
            vv[2 * t + 1] = rb < EGT;
            op[2 * t] = out + (size_t)ra * 552;
            op[2 * t + 1] = out + (size_t)rb * 552;
        }

        for (int jt = 0; jt < 69; jt++) {
            uint32_t B[16];
            {
                int nrow = jt * 8 + (lane & 7);
                uint32_t rbase = sb + SM_B + (uint32_t)nrow * 256;
                int rx = nrow & 7;
                int csel = lane >> 3;
#pragma unroll
                for (int kp = 0; kp < 4; kp++) {
                    int chunk = kp * 4 + csel;
                    ldm_x4(&B[kp * 4], rbase + (uint32_t)((chunk ^ rx) << 4));
                }
            }
            int col = jt * 8 + ((lane & 3) << 1);
            float bx = bc2[col], by = bc2[col + 1];
#pragma unroll
            for (int t = 0; t < 2; t++) {
                float accE[4] = {0, 0, 0, 0}, accO[4] = {0, 0, 0, 0};
#pragma unroll
                for (int ks = 0; ks < 8; ks++)
                    mma_f16((ks & 1) ? accO : accE, &Ah[t][ks * 4], &B[ks * 2]);
                if (vv[2 * t])
                    st_cs2(op[2 * t] + col, sigf(accE[0] + accO[0] + bx), sigf(accE[1] + accO[1] + by));
                if (vv[2 * t + 1])
                    st_cs2(op[2 * t + 1] + col, sigf(accE[2] + accO[2] + bx), sigf(accE[3] + accO[3] + by));
            }
        }
    }
}

// ---------------- launch ----------------
extern "C" void kernel_launch(void* const* d_in, const int* in_sizes, int n_in,
                              void* d_out, int out_size) {
    const float* x    = (const float*)d_in[0];
    const int*   ei   = (const int*)  d_in[1];
    const int*   egt  = (const int*)  d_in[2];
    const int*   ef   = (const int*)  d_in[3];
    const float* embT = (const float*)d_in[4];
    const float* embA = (const float*)d_in[5];
    const float* W1l  = (const float*)d_in[6];
    const float* W1r  = (const float*)d_in[7];
    const float* b1   = (const float*)d_in[8];
    const float* W2l  = (const float*)d_in[9];
    const float* W2r  = (const float*)d_in[10];
    const float* b2   = (const float*)d_in[11];
    const float* Wc1  = (const float*)d_in[12];
    const float* bc1  = (const float*)d_in[13];
    const float* Wc2  = (const float*)d_in[14];
    const float* bc2  = (const float*)d_in[15];
    float* out = (float*)d_out;

    cudaFuncSetAttribute(k_gemm1_mma, cudaFuncAttributeMaxDynamicSharedMemorySize, G1_SMEM);
    cudaFuncSetAttribute(k_gemm2uv_mma, cudaFuncAttributeMaxDynamicSharedMemorySize, F_SMEM);
    cudaFuncSetAttribute(k_edge_mma, cudaFuncAttributeMaxDynamicSharedMemorySize, SM_EDGE_TOTAL);

    k_prep<<<(552 * 128 + 255) / 256, 256>>>(Wc2, W2l, W2r, Wc1, W1l, W1r, ei);
    k_count<<<(E_EDGES + 255) / 256, 256>>>(ei);
    k_scan2<<<2, 1024>>>();
    k_scatter2<<<(E_EDGES + 255) / 256, 256>>>(ei, ef);
    k_h0build<<<(N_NODES + 255) / 256, 256>>>(x, embT, embA);
    k_agg24<<<(N_NODES * 32 + 255) / 256, 256>>>();
    k_gemm1_mma<<<(N_NODES + 127) / 128, 256, G1_SMEM>>>(b1);
    k_agg256<<<(N_NODES * 32 + 255) / 256, 256>>>();
    k_gemm2uv_mma<<<(N_NODES + 127) / 128, 256, F_SMEM>>>(b2);
    k_edge_mma<<<148, 256, SM_EDGE_TOTAL>>>(egt, bc1, bc2, out);
}

// round 14
// speedup vs baseline: 2.3277x; 1.0873x over previous
#include <cuda_runtime.h>
#include <cuda_fp16.h>
#include <cstdint>

#define N_NODES 50000
#define E_EDGES 800000
#define EGT     200000
#define NPAD    53248      // 1024 threads * 52 (CH), multiple of 4

// ---------------- scratch (static device globals; no allocation) ----------------
__device__ float g_h0[N_NODES * 24];        // [x(16) | agg_trigger(4) | agg_action(4)]
__device__ int   g_degd[NPAD];
__device__ int   g_degs[NPAD];
__device__ int   g_curd[N_NODES];
__device__ int   g_curs[N_NODES];
__device__ int   g_off[NPAD + 4];           // CSR by dst
__device__ int   g_offs[NPAD + 4];          // CSR by src
__device__ int   g_csrc[E_EDGES];           // per in-edge: src | (action<<20)
__device__ int   g_strig[E_EDGES];          // per out-edge: trigger code
__device__ float g_agg24[N_NODES * 24];
__device__ __half g_h1h[N_NODES * 256];     // h1 fp16
__device__ __half g_agg256h[N_NODES * 256]; // agg256 fp16
__device__ __half g_uvh[N_NODES * 256];     // [u(128) | v(128)] per node, fp16
__device__ __half g_wc2[552 * 128];         // Wc2^T fp16, [n][k]
__device__ __half g_w2[128 * 512];          // [W2l;W2r]^T fp16, [n][k]
__device__ __half g_wuv[256 * 128];         // [Wc1_top|Wc1_bot]^T fp16, [n][k]
__device__ __half g_w1[256 * 64];           // [W1l;W1r]^T fp16, [n][k] (k padded 48->64)

// ======================= warp-MMA + async helpers (baseline PTX, sm_80+) =======================
__device__ __forceinline__ uint32_t smem_u32(const void* p) {
    uint32_t a;
    asm("{ .reg .u64 t; cvta.to.shared.u64 t, %1; cvt.u32.u64 %0, t; }" : "=r"(a) : "l"(p));
    return a;
}
__device__ __forceinline__ void ldm_x4(uint32_t* r, uint32_t addr) {
    asm volatile("ldmatrix.sync.aligned.m8n8.x4.shared.b16 {%0,%1,%2,%3}, [%4];"
        : "=r"(r[0]), "=r"(r[1]), "=r"(r[2]), "=r"(r[3]) : "r"(addr));
}
__device__ __forceinline__ void mma_f16(float* c, const uint32_t* a, const uint32_t* b) {
    asm volatile(
        "mma.sync.aligned.m16n8k16.row.col.f32.f16.f16.f32 "
        "{%0,%1,%2,%3}, {%4,%5,%6,%7}, {%8,%9}, {%0,%1,%2,%3};"
        : "+f"(c[0]), "+f"(c[1]), "+f"(c[2]), "+f"(c[3])
        : "r"(a[0]), "r"(a[1]), "r"(a[2]), "r"(a[3]), "r"(b[0]), "r"(b[1]));
}
__device__ __forceinline__ void cp16(uint32_t dst, const void* src) {
    asm volatile("cp.async.cg.shared.global [%0], [%1], 16;" :: "r"(dst), "l"(src));
}
#define CP_COMMIT() asm volatile("cp.async.commit_group;" ::: "memory")
#define CP_WAIT0()  asm volatile("cp.async.wait_group 0;" ::: "memory")
// sigmoid(x) = 0.5*tanh(x/2) + 0.5 — single MUFU.TANH (sm_75+)
__device__ __forceinline__ float sigf(float x) {
    float t;
    asm("tanh.approx.f32 %0, %1;" : "=f"(t) : "f"(x * 0.5f));
    return fmaf(t, 0.5f, 0.5f);
}
__device__ __forceinline__ void st_cs2(float* p, float x, float y) {
    asm volatile("st.global.cs.v2.f32 [%0], {%1, %2};" :: "l"(p), "f"(x), "f"(y) : "memory");
}

// pack 8 floats to fp16 (no split)
__device__ __forceinline__ void pack8h(const float* z, uint32_t* hw) {
#pragma unroll
    for (int p = 0; p < 4; p++) {
        __half2 hh = __halves2half2(__float2half(z[2 * p]), __float2half(z[2 * p + 1]));
        hw[p] = *reinterpret_cast<uint32_t*>(&hh);
    }
}
__device__ __forceinline__ uint32_t pack2h(float x, float y) {
    __half2 hh = __halves2half2(__float2half(x), __float2half(y));
    return *reinterpret_cast<uint32_t*>(&hh);
}
__device__ __forceinline__ void add_h2x4(float* acc, uint4 q) {
    const __half2* h = reinterpret_cast<const __half2*>(&q);
#pragma unroll
    for (int p = 0; p < 4; p++) {
        float2 f = __half22float2(h[p]);
        acc[2 * p] += f.x;
        acc[2 * p + 1] += f.y;
    }
}
__device__ __forceinline__ void unpack8h(uint4 q, float* f) {
    const __half2* h = reinterpret_cast<const __half2*>(&q);
#pragma unroll
    for (int p = 0; p < 4; p++) {
        float2 v = __half22float2(h[p]);
        f[2 * p] = v.x;
        f[2 * p + 1] = v.y;
    }
}

// ---------------- fused prep: counters + weight transposes (fp16) ----------------
__global__ void k_prep(const float* __restrict__ Wc2, const float* __restrict__ W2l,
                       const float* __restrict__ W2r, const float* __restrict__ Wc1,
                       const float* __restrict__ W1l, const float* __restrict__ W1r) {
    int i = blockIdx.x * blockDim.x + threadIdx.x;
    if (i < NPAD) { g_degd[i] = 0; g_degs[i] = 0; }
    if (i < N_NODES) { g_curd[i] = 0; g_curs[i] = 0; }
    if (i < 552 * 128) {
        int n = i >> 7, k = i & 127;
        g_wc2[i] = __float2half(Wc2[(size_t)k * 552 + n]);
    }
    if (i < 128 * 512) {
        int n = i >> 9, k = i & 511;
        float w = (k < 256) ? W2l[(size_t)k * 128 + n] : W2r[(size_t)(k - 256) * 128 + n];
        g_w2[i] = __float2half(w);
    }
    if (i < 256 * 128) {
        int n = i >> 7, k = i & 127;
        float w = (n < 128) ? Wc1[(size_t)k * 128 + n] : Wc1[(size_t)(128 + k) * 128 + (n - 128)];
        g_wuv[i] = __float2half(w);
    }
    if (i < 256 * 64) {
        int n = i >> 6, k = i & 63;
        float w = 0.f;
        if (k < 24) w = W1l[(size_t)k * 256 + n];
        else if (k < 48) w = W1r[(size_t)(k - 24) * 256 + n];
        g_w1[i] = __float2half(w);
    }
}

// ---------------- degree count (needs zeroed counters from k_prep) ----------------
__global__ void k_count(const int* __restrict__ ei) {
    int e = blockIdx.x * blockDim.x + threadIdx.x;
    if (e >= E_EDGES) return;
    atomicAdd(&g_degs[ei[e]], 1);
    atomicAdd(&g_degd[ei[E_EDGES + e]], 1);
}

// ---------------- dual scan: blockIdx.x = 0 (dst-CSR) / 1 (src-CSR), int4 vectorized ----------------
__global__ void k_scan2() {
    int which = blockIdx.x;
    const int* deg = which ? g_degs : g_degd;
    int* off = which ? g_offs : g_off;
    const int CH = 52;
    int tid = threadIdx.x, lane = tid & 31, wid = tid >> 5;
    int beg = tid * CH;
    int sum = 0;
#pragma unroll
    for (int i = 0; i < CH; i += 4) {
        int4 v = *(const int4*)(deg + beg + i);
        sum += v.x + v.y + v.z + v.w;
    }
    int v = sum;
#pragma unroll
    for (int o = 1; o < 32; o <<= 1) {
        int t = __shfl_up_sync(0xFFFFFFFFu, v, o);
        if (lane >= o) v += t;
    }
    __shared__ int wsum[32];
    if (lane == 31) wsum[wid] = v;
    __syncthreads();
    if (wid == 0) {
        int w = wsum[lane];
#pragma unroll
        for (int o = 1; o < 32; o <<= 1) {
            int t = __shfl_up_sync(0xFFFFFFFFu, w, o);
            if (lane >= o) w += t;
        }
        wsum[lane] = w;
    }
    __syncthreads();
    int base = v - sum + (wid ? wsum[wid - 1] : 0);
#pragma unroll
    for (int i = 0; i < CH; i += 4) {
        int4 d = *(const int4*)(deg + beg + i);
        int4 o;
        o.x = base;
        o.y = o.x + d.x;
        o.z = o.y + d.y;
        o.w = o.z + d.z;
        base = o.w + d.w;
        *(int4*)(off + beg + i) = o;
    }
}

// ---------------- scatter both CSRs (action packed into csrc high bits) ----------------
__global__ void k_scatter2(const int* __restrict__ ei, const int* __restrict__ ef) {
    int e = blockIdx.x * blockDim.x + threadIdx.x;
    if (e >= E_EDGES) return;
    int s = ei[e], d = ei[E_EDGES + e];
    int t = ef[2 * e], a = ef[2 * e + 1];
    int posd = g_off[d] + atomicAdd(&g_curd[d], 1);
    g_csrc[posd] = s | (a << 20);
    int poss = g_offs[s] + atomicAdd(&g_curs[s], 1);
    g_strig[poss] = t;
}

// ---------------- h0 build: x copy + trigger/action gather-reduce (no atomics) ----------------
__global__ void k_h0build(const float* __restrict__ x,
                          const float* __restrict__ embT, const float* __restrict__ embA) {
    int n = blockIdx.x * blockDim.x + threadIdx.x;
    if (n >= N_NODES) return;
    float* h0 = g_h0 + (size_t)n * 24;
    const float4* xp = (const float4*)(x + (size_t)n * 16);
#pragma unroll
    for (int j = 0; j < 4; j++) ((float4*)h0)[j] = xp[j];
    float4 trig = make_float4(0, 0, 0, 0);
    int b0 = g_offs[n], e0 = g_offs[n + 1];
    for (int e = b0; e < e0; e++) {
        int t = g_strig[e];
        float4 v = *(const float4*)(embT + (size_t)t * 4);
        trig.x += v.x; trig.y += v.y; trig.z += v.z; trig.w += v.w;
    }
    float4 act = make_float4(0, 0, 0, 0);
    int b1 = g_off[n], e1 = g_off[n + 1];
    for (int e = b1; e < e1; e++) {
        int a = g_csrc[e] >> 20;
        float4 v = *(const float4*)(embA + (size_t)a * 4);
        act.x += v.x; act.y += v.y; act.z += v.z; act.w += v.w;
    }
    ((float4*)h0)[4] = trig;
    ((float4*)h0)[5] = act;
}

// ---------------- layer-1 aggregation in 24-dim space (warp per node, 2-way unroll) ----------------
__global__ void k_agg24() {
    int w = (blockIdx.x * blockDim.x + threadIdx.x) >> 5;
    int lane = threadIdx.x & 31;
    if (w >= N_NODES) return;
    int beg = g_off[w], end = g_off[w + 1];
    if (lane < 24) {
        float acc0 = 0.f, acc1 = 0.f;
        int e = beg;
        for (; e + 1 < end; e += 2) {
            int s0 = g_csrc[e] & 0xFFFFF;
            int s1 = g_csrc[e + 1] & 0xFFFFF;
            acc0 += g_h0[s0 * 24 + lane];
            acc1 += g_h0[s1 * 24 + lane];
        }
        if (e < end) acc0 += g_h0[(g_csrc[e] & 0xFFFFF) * 24 + lane];
        float inv = 1.f / fmaxf((float)(end - beg), 1.f);
        g_agg24[w * 24 + lane] = (acc0 + acc1) * inv;
    }
}

// =====================================================================================
// k_gemm1_mma: h1 = relu([agg24|h0] @ [W1l;W1r] + b1), single-fp16 A x fp16 B -> fp16 h1
// =====================================================================================
#define G1_SA   0
#define G1_SB   16384
#define G1_SMEM 49152

__global__ __launch_bounds__(256, 1)
void k_gemm1_mma(const float* __restrict__ b1) {
    extern __shared__ char smem[];
    uint32_t sb = smem_u32(smem);
    int tid = threadIdx.x, wid = tid >> 5, lane = tid & 31;
    int r0 = blockIdx.x * 128;

    {
        int m = tid >> 1, h = tid & 1;
        int node = min(r0 + m, N_NODES - 1);
        const float* a24 = g_agg24 + (size_t)node * 24;
        const float* h0p = g_h0 + (size_t)node * 24;
#pragma unroll
        for (int kk = 0; kk < 32; kk += 8) {
            float z[8];
#pragma unroll
            for (int j = 0; j < 8; j++) {
                int k = h * 32 + kk + j;
                z[j] = (k < 24) ? a24[k] : ((k < 48) ? h0p[k - 24] : 0.f);
            }
            uint32_t hw[4];
            pack8h(z, hw);
            int c = h * 4 + (kk >> 3);
            uint32_t off = (uint32_t)m * 128 + (uint32_t)((c ^ (m & 7)) << 4);
            *(uint4*)(smem + G1_SA + off) = make_uint4(hw[0], hw[1], hw[2], hw[3]);
        }
    }
    {
        int n = tid;
        const __half* src = g_w1 + (size_t)n * 64;
#pragma unroll
        for (int c = 0; c < 8; c++) {
            uint32_t off = (uint32_t)n * 128 + (uint32_t)((c ^ (n & 7)) << 4);
            *(uint4*)(smem + G1_SB + off) = *(const uint4*)(src + c * 8);
        }
    }
    __syncthreads();

    uint32_t Ah[16];
    {
        int rowA = wid * 16 + (lane & 15);
        uint32_t rbase = (uint32_t)rowA * 128;
        int rx = rowA & 7;
        int csel = lane >> 4;
#pragma unroll
        for (int ks = 0; ks < 4; ks++) {
            int c = ks * 2 + csel;
            ldm_x4(&Ah[ks * 4], sb + G1_SA + rbase + (uint32_t)((c ^ rx) << 4));
        }
    }

    int row0 = r0 + wid * 16 + (lane >> 2);
    int row1 = row0 + 8;
#pragma unroll
    for (int nt = 0; nt < 32; nt++) {
        uint32_t B[8];
        {
            int nrow = nt * 8 + (lane & 7);
            uint32_t rbase = (uint32_t)nrow * 128;
            int rx = nrow & 7;
            int csel = lane >> 3;
#pragma unroll
            for (int kp = 0; kp < 2; kp++) {
                int c = kp * 4 + csel;
                ldm_x4(&B[kp * 4], sb + G1_SB + rbase + (uint32_t)((c ^ rx) << 4));
            }
        }
        float accE[4] = {0, 0, 0, 0}, accO[4] = {0, 0, 0, 0};
#pragma unroll
        for (int ks = 0; ks < 4; ks++)
            mma_f16((ks & 1) ? accO : accE, &Ah[ks * 4], &B[ks * 2]);
        int col = nt * 8 + ((lane & 3) << 1);
        float bx = b1[col], by = b1[col + 1];
        if (row0 < N_NODES)
            *(uint32_t*)(g_h1h + (size_t)row0 * 256 + col) =
                pack2h(fmaxf(accE[0] + accO[0] + bx, 0.f), fmaxf(accE[1] + accO[1] + by, 0.f));
        if (row1 < N_NODES)
            *(uint32_t*)(g_h1h + (size_t)row1 * 256 + col) =
                pack2h(fmaxf(accE[2] + accO[2] + bx, 0.f), fmaxf(accE[3] + accO[3] + by, 0.f));
    }
}

// ---------------- layer-2 aggregation: fp16 gather (1 uint4/lane/edge), fp32 accumulate ----------------
__global__ void k_agg256() {
    int w = (blockIdx.x * blockDim.x + threadIdx.x) >> 5;
    int lane = threadIdx.x & 31;
    if (w >= N_NODES) return;
    int beg = g_off[w], end = g_off[w + 1];
    float a[8] = {0, 0, 0, 0, 0, 0, 0, 0};
    float b[8] = {0, 0, 0, 0, 0, 0, 0, 0};
    int e = beg;
    for (; e + 1 < end; e += 2) {
        int s0 = g_csrc[e] & 0xFFFFF;
        int s1 = g_csrc[e + 1] & 0xFFFFF;
        uint4 q0 = *(const uint4*)(g_h1h + (size_t)s0 * 256 + lane * 8);
        uint4 q1 = *(const uint4*)(g_h1h + (size_t)s1 * 256 + lane * 8);
        add_h2x4(a, q0);
        add_h2x4(b, q1);
    }
    if (e < end) {
        int s0 = g_csrc[e] & 0xFFFFF;
        uint4 q0 = *(const uint4*)(g_h1h + (size_t)s0 * 256 + lane * 8);
        add_h2x4(a, q0);
    }
    float inv = 1.f / fmaxf((float)(end - beg), 1.f);
#pragma unroll
    for (int j = 0; j < 8; j++) a[j] = (a[j] + b[j]) * inv;
    uint32_t hw[4];
    pack8h(a, hw);
    *(uint4*)(g_agg256h + (size_t)w * 256 + lane * 8) = make_uint4(hw[0], hw[1], hw[2], hw[3]);
}

// =====================================================================================
// k_gemm2uv_mma: FUSED  h2 = relu([agg256|h1]@[W2l;W2r]+b2);  uv = h2 @ Wuv -> fp16 uv
// B k-chunks loaded via cp.async, overlapped with A pack.
// =====================================================================================
#define F_SA     0
#define F_SB     32768
#define F_A2     0
#define F_BUV    32768
#define F_SMEM   98304

__global__ __launch_bounds__(256, 1)
void k_gemm2uv_mma(const float* __restrict__ b2) {
    extern __shared__ char smem[];
    uint32_t sb = smem_u32(smem);
    int tid = threadIdx.x, wid = tid >> 5, lane = tid & 31;
    int r0 = blockIdx.x * 128;

    float acc[16][4];
#pragma unroll
    for (int nt = 0; nt < 16; nt++)
#pragma unroll
        for (int j = 0; j < 4; j++) acc[nt][j] = 0.f;

    for (int kc = 0; kc < 4; kc++) {
        if (kc) __syncthreads();
        // B chunk via cp.async (overlaps with A pack below)
        {
            int n = tid >> 1, h = tid & 1;
            const __half* src = g_w2 + (size_t)n * 512 + kc * 128 + h * 64;
#pragma unroll
            for (int c = 0; c < 8; c++) {
                int chunk = h * 8 + c;
                uint32_t off = (uint32_t)n * 256 + (uint32_t)((chunk ^ (n & 7)) << 4);
                cp16(sb + F_SB + off, src + c * 8);
            }
            CP_COMMIT();
        }
        // A chunk (fp16 global -> swizzled smem)
        {
            int m = tid >> 1, h = tid & 1;
            int node = min(r0 + m, N_NODES - 1);
            const __half* src = ((kc < 2) ? (g_agg256h + (size_t)node * 256 + kc * 128)
                                          : (g_h1h + (size_t)node * 256 + (kc - 2) * 128)) + h * 64;
#pragma unroll
            for (int c = 0; c < 8; c++) {
                int chunk = h * 8 + c;
                uint32_t off = (uint32_t)m * 256 + (uint32_t)((chunk ^ (m & 7)) << 4);
                *(uint4*)(smem + F_SA + off) = *(const uint4*)(src + c * 8);
            }
        }
        CP_WAIT0();
        __syncthreads();

        uint32_t Ah[32];
        {
            int rowA = wid * 16 + (lane & 15);
            uint32_t rbase = (uint32_t)rowA * 256;
            int rx = rowA & 7;
            int csel = lane >> 4;
#pragma unroll
            for (int ks = 0; ks < 8; ks++) {
                int chunk = ks * 2 + csel;
                ldm_x4(&Ah[ks * 4], sb + F_SA + rbase + (uint32_t)((chunk ^ rx) << 4));
            }
        }
#pragma unroll
        for (int nt = 0; nt < 16; nt++) {
            uint32_t B[16];
            {
                int nrow = nt * 8 + (lane & 7);
                uint32_t rbase = (uint32_t)nrow * 256;
                int rx = nrow & 7;
                int csel = lane >> 3;
#pragma unroll
                for (int kp = 0; kp < 4; kp++) {
                    int chunk = kp * 4 + csel;
                    ldm_x4(&B[kp * 4], sb + F_SB + rbase + (uint32_t)((chunk ^ rx) << 4));
                }
            }
            float accE[4] = {0, 0, 0, 0}, accO[4] = {0, 0, 0, 0};
#pragma unroll
            for (int ks = 0; ks < 8; ks++)
                mma_f16((ks & 1) ? accO : accE, &Ah[ks * 4], &B[ks * 2]);
#pragma unroll
            for (int j = 0; j < 4; j++) acc[nt][j] += accE[j] + accO[j];
        }
    }
    __syncthreads();

    // ---------------- phase 2: h2 -> A2 smem (single fp16), Buv load, GEMM -> g_uvh ----------------
    {
        int n = tid;
        const __half* src = g_wuv + (size_t)n * 128;
#pragma unroll
        for (int c = 0; c < 16; c++) {
            uint32_t off = (uint32_t)n * 256 + (uint32_t)((c ^ (n & 7)) << 4);
            cp16(sb + F_BUV + off, src + c * 8);
        }
        CP_COMMIT();
    }
    {
        int rloc0 = wid * 16 + (lane >> 2);
        int rloc1 = rloc0 + 8;
        int rx0 = rloc0 & 7, rx1 = rloc1 & 7;
#pragma unroll
        for (int nt = 0; nt < 16; nt++) {
            int c = nt * 8 + ((lane & 3) << 1);
            float bx = b2[c], by = b2[c + 1];
            float v0x = fmaxf(acc[nt][0] + bx, 0.f), v0y = fmaxf(acc[nt][1] + by, 0.f);
            float v1x = fmaxf(acc[nt][2] + bx, 0.f), v1y = fmaxf(acc[nt][3] + by, 0.f);
            uint32_t base0 = (uint32_t)rloc0 * 256 + (uint32_t)((((c >> 3) ^ rx0)) << 4) + (uint32_t)(c & 7) * 2;
            *(uint32_t*)(smem + F_A2 + base0) = pack2h(v0x, v0y);
            uint32_t base1 = (uint32_t)rloc1 * 256 + (uint32_t)((((c >> 3) ^ rx1)) << 4) + (uint32_t)(c & 7) * 2;
            *(uint32_t*)(smem + F_A2 + base1) = pack2h(v1x, v1y);
        }
    }
    CP_WAIT0();
    __syncthreads();

    uint32_t Ah[32];
    {
        int rowA = wid * 16 + (lane & 15);
        uint32_t rbase = (uint32_t)rowA * 256;
        int rx = rowA & 7;
        int csel = lane >> 4;
#pragma unroll
        for (int ks = 0; ks < 8; ks++) {
            int chunk = ks * 2 + csel;
            ldm_x4(&Ah[ks * 4], sb + F_A2 + rbase + (uint32_t)((chunk ^ rx) << 4));
        }
    }
    int row0 = r0 + wid * 16 + (lane >> 2);
    int row1 = row0 + 8;
#pragma unroll
    for (int nt = 0; nt < 32; nt++) {
        uint32_t B[16];
        {
            int nrow = nt * 8 + (lane & 7);
            uint32_t rbase = (uint32_t)nrow * 256;
            int rx = nrow & 7;
            int csel = lane >> 3;
#pragma unroll
            for (int kp = 0; kp < 4; kp++) {
                int chunk = kp * 4 + csel;
                ldm_x4(&B[kp * 4], sb + F_BUV + rbase + (uint32_t)((chunk ^ rx) << 4));
            }
        }
        float accE[4] = {0, 0, 0, 0}, accO[4] = {0, 0, 0, 0};
#pragma unroll
        for (int ks = 0; ks < 8; ks++)
            mma_f16((ks & 1) ? accO : accE, &Ah[ks * 4], &B[ks * 2]);
        int col = nt * 8 + ((lane & 3) << 1);
        if (row0 < N_NODES)
            *(uint32_t*)(g_uvh + (size_t)row0 * 256 + col) = pack2h(accE[0] + accO[0], accE[1] + accO[1]);
        if (row1 < N_NODES)
            *(uint32_t*)(g_uvh + (size_t)row1 * 256 + col) = pack2h(accE[2] + accO[2], accE[3] + accO[3]);
    }
}

// =====================================================================================
// k_edge_mma: PERSISTENT edge classifier; B loaded ONCE per SM; single-fp16 A x fp16 B;
// M=256/block, warp owns 32 rows (2 m-tiles); streaming fp32 output stores (st.cs);
// sigmoid via MUFU.TANH.
// =====================================================================================
#define EM_M     256
#define EM_NBLK  ((EGT + EM_M - 1) / EM_M)   // 782
#define SM_A     0
#define SM_B     65536
#define SM_EDGE_TOTAL (65536 + 552 * 256)    // 206848

__global__ __launch_bounds__(256, 1)
void k_edge_mma(const int* __restrict__ egt, const float* __restrict__ bc1,
                const float* __restrict__ bc2, float* __restrict__ out) {
    extern __shared__ char smem[];
    uint32_t sb = smem_u32(smem);
    int tid = threadIdx.x, wid = tid >> 5, lane = tid & 31;

    // load full B (552 rows x 128 k fp16 = 141KB) ONCE for this CTA's lifetime
    for (int id = tid; id < 552 * 16; id += 256) {
        int n = id >> 4, c = id & 15;
        uint32_t dst = sb + SM_B + (uint32_t)n * 256 + (uint32_t)((c ^ (n & 7)) << 4);
        cp16(dst, g_wc2 + (size_t)n * 128 + c * 8);
    }
    CP_COMMIT();

    int h = tid & 1;
    const float* bp = bc1 + h * 64;
    bool first = true;

    for (int blk = blockIdx.x; blk < EM_NBLK; blk += gridDim.x) {
        int e0 = blk * EM_M;

        if (!first) __syncthreads();   // all warps done reading A smem of previous block
        // A prep: z = relu(u[s]+v[d]+bc1) -> fp16 (256 rows, 2 passes of 128)
        for (int m = tid >> 1; m < EM_M; m += 128) {
            int er = e0 + m;
            int s = 0, d = 0;
            if (er < EGT) { s = egt[er]; d = egt[EGT + er]; }
            const __half* up = g_uvh + (size_t)s * 256 + h * 64;
            const __half* vp = g_uvh + (size_t)d * 256 + 128 + h * 64;
#pragma unroll
            for (int kk = 0; kk < 64; kk += 8) {
                uint4 qu = *(const uint4*)(up + kk);
                uint4 qv = *(const uint4*)(vp + kk);
                float fu[8], fv[8], z[8];
                unpack8h(qu, fu);
                unpack8h(qv, fv);
#pragma unroll
                for (int j = 0; j < 8; j++)
                    z[j] = fmaxf(fu[j] + fv[j] + bp[kk + j], 0.f);
                uint32_t hw[4];
                pack8h(z, hw);
                int chunk = h * 8 + (kk >> 3);
                uint32_t off = (uint32_t)m * 256 + (uint32_t)((chunk ^ (m & 7)) << 4);
                *(uint4*)(smem + SM_A + off) = make_uint4(hw[0], hw[1], hw[2], hw[3]);
            }
        }
        if (first) { CP_WAIT0(); first = false; }
        __syncthreads();   // A (+B on first iter) visible

        // A fragments: warp owns rows [wid*32, wid*32+32) = 2 m-tiles
        uint32_t Ah[2][32];
#pragma unroll
        for (int t = 0; t < 2; t++) {
            int rowA = wid * 32 + t * 16 + (lane & 15);
            uint32_t rbase = (uint32_t)rowA * 256;
            int rx = rowA & 7;
            int csel = lane >> 4;
#pragma unroll
            for (int ks = 0; ks < 8; ks++) {
                int chunk = ks * 2 + csel;
                ldm_x4(&Ah[t][ks * 4], sb + SM_A + rbase + (uint32_t)((chunk ^ rx) << 4));
            }
        }

        int rbase0 = e0 + wid * 32 + (lane >> 2);
        float* op[4];
        bool vv[4];
#pragma unroll
        for (int t = 0; t < 2; t++) {
            int ra = rbase0 + t * 16, rb = ra + 8;
            vv[2 * t] = ra < EGT;
            vv[2 * t + 1] = rb < EGT;
            op[2 * t] = out + (size_t)ra * 552;
            op[2 * t + 1] = out + (size_t)rb * 552;
        }

        for (int jt = 0; jt < 69; jt++) {
            uint32_t B[16];
            {
                int nrow = jt * 8 + (lane & 7);
                uint32_t rbase = sb + SM_B + (uint32_t)nrow * 256;
                int rx = nrow & 7;
                int csel = lane >> 3;
#pragma unroll
                for (int kp = 0; kp < 4; kp++) {
                    int chunk = kp * 4 + csel;
                    ldm_x4(&B[kp * 4], rbase + (uint32_t)((chunk ^ rx) << 4));
                }
            }
            int col = jt * 8 + ((lane & 3) << 1);
            float bx = bc2[col], by = bc2[col + 1];
#pragma unroll
            for (int t = 0; t < 2; t++) {
                float accE[4] = {0, 0, 0, 0}, accO[4] = {0, 0, 0, 0};
#pragma unroll
                for (int ks = 0; ks < 8; ks++)
                    mma_f16((ks & 1) ? accO : accE, &Ah[t][ks * 4], &B[ks * 2]);
                if (vv[2 * t])
                    st_cs2(op[2 * t] + col, sigf(accE[0] + accO[0] + bx), sigf(accE[1] + accO[1] + by));
                if (vv[2 * t + 1])
                    st_cs2(op[2 * t + 1] + col, sigf(accE[2] + accO[2] + bx), sigf(accE[3] + accO[3] + by));
            }
        }
    }
}

// ---------------- launch ----------------
extern "C" void kernel_launch(void* const* d_in, const int* in_sizes, int n_in,
                              void* d_out, int out_size) {
    const float* x    = (const float*)d_in[0];
    const int*   ei   = (const int*)  d_in[1];
    const int*   egt  = (const int*)  d_in[2];
    const int*   ef   = (const int*)  d_in[3];
    const float* embT = (const float*)d_in[4];
    const float* embA = (const float*)d_in[5];
    const float* W1l  = (const float*)d_in[6];
    const float* W1r  = (const float*)d_in[7];
    const float* b1   = (const float*)d_in[8];
    const float* W2l  = (const float*)d_in[9];
    const float* W2r  = (const float*)d_in[10];
    const float* b2   = (const float*)d_in[11];
    const float* Wc1  = (const float*)d_in[12];
    const float* bc1  = (const float*)d_in[13];
    const float* Wc2  = (const float*)d_in[14];
    const float* bc2  = (const float*)d_in[15];
    float* out = (float*)d_out;

    cudaFuncSetAttribute(k_gemm1_mma, cudaFuncAttributeMaxDynamicSharedMemorySize, G1_SMEM);
    cudaFuncSetAttribute(k_gemm2uv_mma, cudaFuncAttributeMaxDynamicSharedMemorySize, F_SMEM);
    cudaFuncSetAttribute(k_edge_mma, cudaFuncAttributeMaxDynamicSharedMemorySize, SM_EDGE_TOTAL);

    k_prep<<<(552 * 128 + 255) / 256, 256>>>(Wc2, W2l, W2r, Wc1, W1l, W1r);
    k_count<<<(E_EDGES + 255) / 256, 256>>>(ei);
    k_scan2<<<2, 1024>>>();
    k_scatter2<<<(E_EDGES + 255) / 256, 256>>>(ei, ef);
    k_h0build<<<(N_NODES + 255) / 256, 256>>>(x, embT, embA);
    k_agg24<<<(N_NODES * 32 + 255) / 256, 256>>>();
    k_gemm1_mma<<<(N_NODES + 127) / 128, 256, G1_SMEM>>>(b1);
    k_agg256<<<(N_NODES * 32 + 255) / 256, 256>>>();
    k_gemm2uv_mma<<<(N_NODES + 127) / 128, 256, F_SMEM>>>(b2);
    k_edge_mma<<<148, 256, SM_EDGE_TOTAL>>>(egt, bc1, bc2, out);
}